// round 5
// baseline (speedup 1.0000x reference)
#include <cuda_runtime.h>
#include <cuda_bf16.h>
#include <stdint.h>
#include <math.h>

// B=8, M=1024, H=512, K=8 heads, D=64, SPAN=1024, MK=2048
#define DINLINE __device__ __forceinline__

// ---------------- scratch ----------------------------------------------------
__device__ __nv_bfloat16 g_Qh[64 * 1024 * 64];
__device__ __nv_bfloat16 g_Ql[64 * 1024 * 64];
__device__ __nv_bfloat16 g_Kh[64 * 2048 * 64];
__device__ __nv_bfloat16 g_Kl[64 * 2048 * 64];
__device__ __nv_bfloat16 g_Vh[64 * 2048 * 64];
__device__ __nv_bfloat16 g_Vl[64 * 2048 * 64];
__device__ float g_C[8 * 1024 * 512];

// ---------------- helpers ----------------------------------------------------
DINLINE void mma_bf16(float c[4], uint32_t a0, uint32_t a1, uint32_t a2,
                      uint32_t a3, uint32_t b0, uint32_t b1) {
    asm volatile(
        "mma.sync.aligned.m16n8k16.row.col.f32.bf16.bf16.f32 "
        "{%0,%1,%2,%3}, {%4,%5,%6,%7}, {%8,%9}, {%0,%1,%2,%3};\n"
        : "+f"(c[0]), "+f"(c[1]), "+f"(c[2]), "+f"(c[3])
        : "r"(a0), "r"(a1), "r"(a2), "r"(a3), "r"(b0), "r"(b1));
}

DINLINE uint32_t smem_u32(const void* p) {
    return (uint32_t)__cvta_generic_to_shared(p);
}

DINLINE void ldmx4(uint32_t& r0, uint32_t& r1, uint32_t& r2, uint32_t& r3,
                   uint32_t a) {
    asm volatile(
        "ldmatrix.sync.aligned.m8n8.x4.shared.b16 {%0,%1,%2,%3}, [%4];\n"
        : "=r"(r0), "=r"(r1), "=r"(r2), "=r"(r3)
        : "r"(a));
}

DINLINE void ldmx2(uint32_t& r0, uint32_t& r1, uint32_t a) {
    asm volatile("ldmatrix.sync.aligned.m8n8.x2.shared.b16 {%0,%1}, [%2];\n"
                 : "=r"(r0), "=r"(r1)
                 : "r"(a));
}

DINLINE void stmx4(uint32_t a, uint32_t r0, uint32_t r1, uint32_t r2,
                   uint32_t r3) {
    asm volatile(
        "stmatrix.sync.aligned.m8n8.x4.shared.b16 [%0], {%1,%2,%3,%4};\n" ::
            "r"(a),
        "r"(r0), "r"(r1), "r"(r2), "r"(r3));
}

DINLINE void split_bf(float x, __nv_bfloat16& h, __nv_bfloat16& l) {
    h = __float2bfloat16_rn(x);
    l = __float2bfloat16_rn(x - __bfloat162float(h));
}

DINLINE void st_bf2(__nv_bfloat16* p, __nv_bfloat16 a, __nv_bfloat16 b) {
    __nv_bfloat162 t;
    t.x = a;
    t.y = b;
    *(__nv_bfloat162*)p = t;
}

DINLINE uint32_t pack_bf2(__nv_bfloat16 a, __nv_bfloat16 b) {
    __nv_bfloat162 t;
    t.x = a;
    t.y = b;
    return *(uint32_t*)&t;
}

// ---------------- bf16x3 GEMM (512 thr, 4x4 warps): C[R,512]=A[R,512]@W ------
template <int EPI>
__global__ void __launch_bounds__(512, 1) gemm_tc2(
    const float* __restrict__ A, const float* __restrict__ W,
    float* __restrict__ outF, __nv_bfloat16* __restrict__ outH,
    __nv_bfloat16* __restrict__ outL, int T) {
    constexpr int AS = 40;  // bf16 row stride (80B -> 20-bank step, ldm-safe)
    __shared__ __nv_bfloat16 Ah[128 * AS], Al[128 * AS];
    __shared__ __nv_bfloat16 Bh[128 * AS], Bl[128 * AS];

    const int tid = threadIdx.x;
    const int lane = tid & 31, wid = tid >> 5;
    const int wm = wid >> 2, wn = wid & 3;  // 4 x 4 warps
    const int row0 = blockIdx.x * 128, col0 = blockIdx.y * 128;
    const int g = lane >> 2, t2 = (lane & 3) * 2;

    float acc[2][4][4] = {};

    const uint32_t aAh =
        smem_u32(&Ah[(wm * 32 + (lane & 15)) * AS + ((lane >> 4) << 3)]);
    const uint32_t aAl =
        smem_u32(&Al[(wm * 32 + (lane & 15)) * AS + ((lane >> 4) << 3)]);
    const uint32_t aBh = smem_u32(
        &Bh[(wn * 32 + (lane & 7)) * AS + (((lane >> 3) & 1) << 3)]);
    const uint32_t aBl = smem_u32(
        &Bl[(wn * 32 + (lane & 7)) * AS + (((lane >> 3) & 1) << 3)]);

    for (int kk = 0; kk < 512; kk += 32) {
        __syncthreads();  // prior MMAs done before overwrite
        // A tile 128x32 fp32 -> split
#pragma unroll
        for (int it = 0; it < 2; it++) {
            int idx = tid + it * 512;
            int r = idx >> 3, kq = (idx & 7) * 4;
            float4 v = *(const float4*)&A[(size_t)(row0 + r) * 512 + kk + kq];
            __nv_bfloat16 h0, l0, h1, l1, h2, l2, h3, l3;
            split_bf(v.x, h0, l0);
            split_bf(v.y, h1, l1);
            split_bf(v.z, h2, l2);
            split_bf(v.w, h3, l3);
            st_bf2(&Ah[r * AS + kq], h0, h1);
            st_bf2(&Ah[r * AS + kq + 2], h2, h3);
            st_bf2(&Al[r * AS + kq], l0, l1);
            st_bf2(&Al[r * AS + kq + 2], l2, l3);
        }
        // B tile 32x128 fp32 -> split, transposed [n][k]
#pragma unroll
        for (int it = 0; it < 2; it++) {
            int idx = tid + it * 512;
            int k = idx >> 5, c4 = (idx & 31) * 4;
            float4 v = *(const float4*)&W[(size_t)(kk + k) * 512 + col0 + c4];
            __nv_bfloat16 h, l;
            split_bf(v.x, h, l); Bh[(c4 + 0) * AS + k] = h; Bl[(c4 + 0) * AS + k] = l;
            split_bf(v.y, h, l); Bh[(c4 + 1) * AS + k] = h; Bl[(c4 + 1) * AS + k] = l;
            split_bf(v.z, h, l); Bh[(c4 + 2) * AS + k] = h; Bl[(c4 + 2) * AS + k] = l;
            split_bf(v.w, h, l); Bh[(c4 + 3) * AS + k] = h; Bl[(c4 + 3) * AS + k] = l;
        }
        __syncthreads();

#pragma unroll
        for (int ks = 0; ks < 32; ks += 16) {
            uint32_t a[2][4], l[2][4];
#pragma unroll
            for (int mf = 0; mf < 2; mf++) {
                ldmx4(a[mf][0], a[mf][1], a[mf][2], a[mf][3],
                      aAh + mf * (16 * AS * 2) + ks * 2);
                ldmx4(l[mf][0], l[mf][1], l[mf][2], l[mf][3],
                      aAl + mf * (16 * AS * 2) + ks * 2);
            }
#pragma unroll
            for (int nf = 0; nf < 4; nf++) {
                uint32_t b0, b1, c0, c1;
                ldmx2(b0, b1, aBh + nf * (8 * AS * 2) + ks * 2);
                ldmx2(c0, c1, aBl + nf * (8 * AS * 2) + ks * 2);
#pragma unroll
                for (int mf = 0; mf < 2; mf++) {
                    mma_bf16(acc[mf][nf], a[mf][0], a[mf][1], a[mf][2],
                             a[mf][3], b0, b1);
                    mma_bf16(acc[mf][nf], a[mf][0], a[mf][1], a[mf][2],
                             a[mf][3], c0, c1);
                    mma_bf16(acc[mf][nf], l[mf][0], l[mf][1], l[mf][2],
                             l[mf][3], b0, b1);
                }
            }
        }
    }

    // epilogue
#pragma unroll
    for (int mf = 0; mf < 2; mf++) {
#pragma unroll
        for (int nf = 0; nf < 4; nf++) {
            int rr = row0 + wm * 32 + mf * 16 + g;
            int cc = col0 + wn * 32 + nf * 8 + t2;
            if (EPI == 0) {
                *(float2*)&outF[(size_t)rr * 512 + cc] =
                    make_float2(acc[mf][nf][0], acc[mf][nf][1]);
                *(float2*)&outF[(size_t)(rr + 8) * 512 + cc] =
                    make_float2(acc[mf][nf][2], acc[mf][nf][3]);
            } else {
                int head = cc >> 6, d = cc & 63;
#pragma unroll
                for (int rh = 0; rh < 2; rh++) {
                    int grow = rr + rh * 8;
                    int b = grow / T, t = grow - b * T;
                    size_t idx = (((size_t)(b * 8 + head) * T + t) << 6) + d;
                    __nv_bfloat16 h0, l0, h1, l1;
                    split_bf(acc[mf][nf][rh * 2 + 0], h0, l0);
                    split_bf(acc[mf][nf][rh * 2 + 1], h1, l1);
                    st_bf2(&outH[idx], h0, h1);
                    st_bf2(&outL[idx], l0, l1);
                }
            }
        }
    }
}

// ---------------- fused banded attention v3 (512 thr, ldmatrix/stmatrix) -----
__global__ void __launch_bounds__(512, 1) attn_tc3(
    const __nv_bfloat16* __restrict__ Qh, const __nv_bfloat16* __restrict__ Ql,
    const __nv_bfloat16* __restrict__ Kh_, const __nv_bfloat16* __restrict__ Kl_,
    const __nv_bfloat16* __restrict__ Vh_, const __nv_bfloat16* __restrict__ Vl_,
    const float* __restrict__ Eg, float* __restrict__ Cg) {
    constexpr int QS = 72, KS = 72, ES = 72, VS = 200, PS = 200, QES = 130;
    extern __shared__ char smraw[];
    __nv_bfloat16* Qsh = (__nv_bfloat16*)smraw;  // [64][QS]
    __nv_bfloat16* Qsl = Qsh + 64 * QS;
    __nv_bfloat16* Ksh = Qsl + 64 * QS;          // [192][KS]
    __nv_bfloat16* Ksl = Ksh + 192 * KS;
    __nv_bfloat16* Esh = Ksl + 192 * KS;         // [s=128][ES] hi only
    __nv_bfloat16* Vsh = Esh + 128 * ES;         // [d=64][VS]
    __nv_bfloat16* Vsl = Vsh + 64 * VS;
    __nv_bfloat16* Psh = Vsl + 64 * VS;          // [m=64][PS]
    __nv_bfloat16* Psl = Psh + 64 * PS;
    float* QEs = (float*)(Psl + 64 * PS);        // [64][QES]
    float* redmax = QEs + 64 * QES;              // [4][64]
    float* redsum = redmax + 256;                // [4][64]
    float* mrow = redsum + 256;                  // [64]
    float* lrow = mrow + 64;                     // [64]

    const int tid = threadIdx.x, lane = tid & 31, wid = tid >> 5;
    const int wm = wid >> 2, wn = wid & 3;  // 4 x 4 warps
    const int g = lane >> 2, t2 = (lane & 3) * 2;
    const int R0 = wm * 16;
    const int n = blockIdx.y, m0 = blockIdx.x * 64;
    const float SCl2 = 0.125f * 1.4426950408889634f;  // 1/sqrt(64)*log2(e)

    // Q tile (once)
    {
        const uint4* sh = (const uint4*)(Qh + (((size_t)n * 1024 + m0) << 6));
        const uint4* sl = (const uint4*)(Ql + (((size_t)n * 1024 + m0) << 6));
        int m = tid >> 3, j = tid & 7;
        ((uint4*)(Qsh + m * QS))[j] = sh[tid];
        ((uint4*)(Qsl + m * QS))[j] = sl[tid];
    }
    if (tid < 64) {
        mrow[tid] = -1e30f;
        lrow[tid] = 0.f;
    }

    // ldmatrix / stmatrix byte addresses
    const int a16 = lane & 15, a8 = lane & 7;
    const int hi4 = (lane >> 4) << 3, hi3 = ((lane >> 3) & 1) << 3;
    const uint32_t aQh = smem_u32(&Qsh[(R0 + a16) * QS + hi4]);
    const uint32_t aQl = smem_u32(&Qsl[(R0 + a16) * QS + hi4]);
    const uint32_t aKh = smem_u32(&Ksh[(wn * 48 + a8) * KS + hi3]);
    const uint32_t aKl = smem_u32(&Ksl[(wn * 48 + a8) * KS + hi3]);
    const uint32_t aE = smem_u32(&Esh[(wn * 32 + a8) * ES + hi3]);
    const uint32_t aVh = smem_u32(&Vsh[(wn * 16 + a8) * VS + hi3]);
    const uint32_t aVl = smem_u32(&Vsl[(wn * 16 + a8) * VS + hi3]);
    const uint32_t aPstH = smem_u32(&Psh[(R0 + a16) * PS + wn * 48 + hi4]);
    const uint32_t aPstL = smem_u32(&Psl[(R0 + a16) * PS + wn * 48 + hi4]);
    const uint32_t aPldH = smem_u32(&Psh[(R0 + a16) * PS + hi4]);
    const uint32_t aPldL = smem_u32(&Psl[(R0 + a16) * PS + hi4]);

    float o[2][4] = {};

    for (int c = 0; c < 8; c++) {
        const int s0 = c * 128;
        const size_t kbase = ((size_t)n * 2048 + m0 + s0) << 6;
        __syncthreads();  // prior chunk's reads complete

        // K chunk 192x64 hi/lo
        {
            const uint4* sh = (const uint4*)(Kh_ + kbase);
            const uint4* sl = (const uint4*)(Kl_ + kbase);
#pragma unroll
            for (int it = 0; it < 3; it++) {
                int f = tid + it * 512;
                int kr = f >> 3, j = f & 7;
                ((uint4*)(Ksh + kr * KS))[j] = sh[f];
                ((uint4*)(Ksl + kr * KS))[j] = sl[f];
            }
        }
        // V chunk transposed [d][key]
        {
            int d2 = tid & 31, kp = tid >> 5;
#pragma unroll
            for (int it = 0; it < 6; it++) {
                int key = (kp + it * 16) * 2;
                uint32_t va = *(const uint32_t*)(Vh_ + kbase + (size_t)key * 64 + d2 * 2);
                uint32_t vb = *(const uint32_t*)(Vh_ + kbase + (size_t)(key + 1) * 64 + d2 * 2);
                __nv_bfloat162 x2 = *(__nv_bfloat162*)&va;
                __nv_bfloat162 y2 = *(__nv_bfloat162*)&vb;
                st_bf2(&Vsh[(2 * d2) * VS + key], x2.x, y2.x);
                st_bf2(&Vsh[(2 * d2 + 1) * VS + key], x2.y, y2.y);
                uint32_t wa = *(const uint32_t*)(Vl_ + kbase + (size_t)key * 64 + d2 * 2);
                uint32_t wb = *(const uint32_t*)(Vl_ + kbase + (size_t)(key + 1) * 64 + d2 * 2);
                __nv_bfloat162 z2 = *(__nv_bfloat162*)&wa;
                __nv_bfloat162 w2 = *(__nv_bfloat162*)&wb;
                st_bf2(&Vsl[(2 * d2) * VS + key], z2.x, w2.x);
                st_bf2(&Vsl[(2 * d2 + 1) * VS + key], z2.y, w2.y);
            }
        }
        // E chunk: Esh[s][d] = E[d][s0+s], hi only
#pragma unroll
        for (int it = 0; it < 8; it++) {
            int idx = tid + it * 512;
            int s2 = (idx & 63) * 2, d = idx >> 6;
            float2 e2 = *(const float2*)&Eg[(size_t)d * 1024 + s0 + s2];
            Esh[s2 * ES + d] = __float2bfloat16_rn(e2.x);
            Esh[(s2 + 1) * ES + d] = __float2bfloat16_rn(e2.y);
        }
        __syncthreads();

        // ---- QK (64x192 bf16x3) + QE (64x128 1-pass) ----
        float sAcc[6][4] = {};
        float qeAcc[4][4] = {};
#pragma unroll
        for (int ks = 0; ks < 64; ks += 16) {
            uint32_t a0, a1, a2, a3, l0, l1, l2, l3;
            ldmx4(a0, a1, a2, a3, aQh + ks * 2);
            ldmx4(l0, l1, l2, l3, aQl + ks * 2);
#pragma unroll
            for (int nf = 0; nf < 6; nf++) {
                uint32_t b0, b1, c0, c1;
                ldmx2(b0, b1, aKh + nf * (8 * KS * 2) + ks * 2);
                ldmx2(c0, c1, aKl + nf * (8 * KS * 2) + ks * 2);
                mma_bf16(sAcc[nf], a0, a1, a2, a3, b0, b1);
                mma_bf16(sAcc[nf], a0, a1, a2, a3, c0, c1);
                mma_bf16(sAcc[nf], l0, l1, l2, l3, b0, b1);
            }
#pragma unroll
            for (int nf = 0; nf < 4; nf++) {
                uint32_t e0, e1;
                ldmx2(e0, e1, aE + nf * (8 * ES * 2) + ks * 2);
                mma_bf16(qeAcc[nf], a0, a1, a2, a3, e0, e1);
            }
        }
        // stage QE fragments (cross-lane diagonal gather needs smem)
#pragma unroll
        for (int nf = 0; nf < 4; nf++) {
            int cc = wn * 32 + nf * 8 + t2;
            *(float2*)&QEs[(R0 + g) * QES + cc] =
                make_float2(qeAcc[nf][0], qeAcc[nf][1]);
            *(float2*)&QEs[(R0 + 8 + g) * QES + cc] =
                make_float2(qeAcc[nf][2], qeAcc[nf][3]);
        }
        __syncthreads();

        // ---- phase 1: masked z = S + QE, per-warp row-max partials ----
        float mx0 = -3e38f, mx1 = -3e38f;
#pragma unroll
        for (int nf = 0; nf < 6; nf++) {
            int cc = wn * 48 + nf * 8 + t2;
#pragma unroll
            for (int e = 0; e < 4; e++) {
                int r = R0 + g + ((e >> 1) << 3);
                int col = cc + (e & 1);
                int diff = col - r;
                float z = -3e38f;
                if ((unsigned)diff < 128u) z = sAcc[nf][e] + QEs[r * QES + diff];
                sAcc[nf][e] = z;
                if (e < 2) mx0 = fmaxf(mx0, z);
                else mx1 = fmaxf(mx1, z);
            }
        }
        mx0 = fmaxf(mx0, __shfl_xor_sync(0xffffffffu, mx0, 1));
        mx0 = fmaxf(mx0, __shfl_xor_sync(0xffffffffu, mx0, 2));
        mx1 = fmaxf(mx1, __shfl_xor_sync(0xffffffffu, mx1, 1));
        mx1 = fmaxf(mx1, __shfl_xor_sync(0xffffffffu, mx1, 2));
        if ((lane & 3) == 0) {
            redmax[wn * 64 + R0 + g] = mx0;
            redmax[wn * 64 + R0 + 8 + g] = mx1;
        }
        __syncthreads();

        // ---- phase 2: exp, P store (stmatrix), sums, O rescale ----
        const int r0i = R0 + g, r1i = R0 + 8 + g;
        float rm0 = fmaxf(fmaxf(redmax[r0i], redmax[64 + r0i]),
                          fmaxf(redmax[128 + r0i], redmax[192 + r0i]));
        float rm1 = fmaxf(fmaxf(redmax[r1i], redmax[64 + r1i]),
                          fmaxf(redmax[128 + r1i], redmax[192 + r1i]));
        float mo0 = mrow[r0i], mo1 = mrow[r1i];
        float mn0 = fmaxf(mo0, rm0 * SCl2), mn1 = fmaxf(mo1, rm1 * SCl2);
        float al0 = exp2f(mo0 - mn0), al1 = exp2f(mo1 - mn1);
        float sum0 = 0.f, sum1 = 0.f;
#pragma unroll
        for (int pair = 0; pair < 3; pair++) {
            uint32_t rh[4], rl[4];
#pragma unroll
            for (int hh = 0; hh < 2; hh++) {
                int nf = pair * 2 + hh;
                float p0 = exp2f(sAcc[nf][0] * SCl2 - mn0);
                float p1 = exp2f(sAcc[nf][1] * SCl2 - mn0);
                float p2 = exp2f(sAcc[nf][2] * SCl2 - mn1);
                float p3 = exp2f(sAcc[nf][3] * SCl2 - mn1);
                sum0 += p0 + p1;
                sum1 += p2 + p3;
                __nv_bfloat16 h0, q0, h1, q1, h2, q2, h3, q3;
                split_bf(p0, h0, q0);
                split_bf(p1, h1, q1);
                split_bf(p2, h2, q2);
                split_bf(p3, h3, q3);
                rh[hh * 2 + 0] = pack_bf2(h0, h1);
                rh[hh * 2 + 1] = pack_bf2(h2, h3);
                rl[hh * 2 + 0] = pack_bf2(q0, q1);
                rl[hh * 2 + 1] = pack_bf2(q2, q3);
            }
            stmx4(aPstH + pair * 32, rh[0], rh[1], rh[2], rh[3]);
            stmx4(aPstL + pair * 32, rl[0], rl[1], rl[2], rl[3]);
        }
        sum0 += __shfl_xor_sync(0xffffffffu, sum0, 1);
        sum0 += __shfl_xor_sync(0xffffffffu, sum0, 2);
        sum1 += __shfl_xor_sync(0xffffffffu, sum1, 1);
        sum1 += __shfl_xor_sync(0xffffffffu, sum1, 2);
        if ((lane & 3) == 0) {
            redsum[wn * 64 + r0i] = sum0;
            redsum[wn * 64 + r1i] = sum1;
        }
#pragma unroll
        for (int nf = 0; nf < 2; nf++) {
            o[nf][0] *= al0;
            o[nf][1] *= al0;
            o[nf][2] *= al1;
            o[nf][3] *= al1;
        }
        __syncthreads();

        // state update (one writer per row)
        if (wn == 0 && (lane & 3) == 0) {
            float sa = redsum[r0i] + redsum[64 + r0i] + redsum[128 + r0i] +
                       redsum[192 + r0i];
            lrow[r0i] = lrow[r0i] * al0 + sa;
            mrow[r0i] = mn0;
            float sb = redsum[r1i] + redsum[64 + r1i] + redsum[128 + r1i] +
                       redsum[192 + r1i];
            lrow[r1i] = lrow[r1i] * al1 + sb;
            mrow[r1i] = mn1;
        }

        // ---- PV: O += P(64x192) @ V^T ----
#pragma unroll
        for (int ks = 0; ks < 192; ks += 16) {
            uint32_t p0, p1, p2, p3, q0, q1, q2, q3;
            ldmx4(p0, p1, p2, p3, aPldH + ks * 2);
            ldmx4(q0, q1, q2, q3, aPldL + ks * 2);
#pragma unroll
            for (int nf = 0; nf < 2; nf++) {
                uint32_t v0, v1, u0, u1;
                ldmx2(v0, v1, aVh + nf * (8 * VS * 2) + ks * 2);
                ldmx2(u0, u1, aVl + nf * (8 * VS * 2) + ks * 2);
                mma_bf16(o[nf], p0, p1, p2, p3, v0, v1);
                mma_bf16(o[nf], p0, p1, p2, p3, u0, u1);
                mma_bf16(o[nf], q0, q1, q2, q3, v0, v1);
            }
        }
    }

    __syncthreads();
    // epilogue: normalize, write context [B,M,H] fp32
    const int b = n >> 3, kh = n & 7;
    float i0 = 1.0f / lrow[R0 + g];
    float i1 = 1.0f / lrow[R0 + 8 + g];
#pragma unroll
    for (int nf = 0; nf < 2; nf++) {
        int cc = kh * 64 + wn * 16 + nf * 8 + t2;
        size_t base = ((size_t)b * 1024 + m0 + R0 + g) * 512 + cc;
        *(float2*)&Cg[base] = make_float2(o[nf][0] * i0, o[nf][1] * i0);
        *(float2*)&Cg[base + 8 * 512] = make_float2(o[nf][2] * i1, o[nf][3] * i1);
    }
}

// ---------------- launcher ----------------------------------------------------
extern "C" void kernel_launch(void* const* d_in, const int* in_sizes, int n_in,
                              void* d_out, int out_size) {
    const float* query = (const float*)d_in[0];
    const float* key = (const float*)d_in[1];
    const float* value = (const float*)d_in[2];
    const float* pos = (const float*)d_in[3];
    const float* Wq = (const float*)d_in[4];
    const float* Wk = (const float*)d_in[5];
    const float* Wv = (const float*)d_in[6];
    const float* Wo = (const float*)d_in[7];
    float* out = (float*)d_out;

    __nv_bfloat16 *qh, *ql, *kh, *kl, *vh, *vl;
    float* cptr;
    cudaGetSymbolAddress((void**)&qh, g_Qh);
    cudaGetSymbolAddress((void**)&ql, g_Ql);
    cudaGetSymbolAddress((void**)&kh, g_Kh);
    cudaGetSymbolAddress((void**)&kl, g_Kl);
    cudaGetSymbolAddress((void**)&vh, g_Vh);
    cudaGetSymbolAddress((void**)&vl, g_Vl);
    cudaGetSymbolAddress((void**)&cptr, g_C);

    gemm_tc2<1><<<dim3(64, 4), 512>>>(query, Wq, nullptr, qh, ql, 1024);
    gemm_tc2<1><<<dim3(128, 4), 512>>>(key, Wk, nullptr, kh, kl, 2048);
    gemm_tc2<1><<<dim3(128, 4), 512>>>(value, Wv, nullptr, vh, vl, 2048);

    // smem: bf16 regions (elems*2B) + fp32 regions
    const int smem_bytes =
        (2 * 64 * 72 + 2 * 192 * 72 + 128 * 72 + 2 * 64 * 200 + 2 * 64 * 200) * 2 +
        (64 * 130 + 256 + 256 + 64 + 64) * 4;  // 230400
    cudaFuncSetAttribute(attn_tc3, cudaFuncAttributeMaxDynamicSharedMemorySize,
                         smem_bytes);
    attn_tc3<<<dim3(16, 64), 512, smem_bytes>>>(qh, ql, kh, kl, vh, vl, pos,
                                                cptr);

    gemm_tc2<0><<<dim3(64, 4), 512>>>(cptr, Wo, out, nullptr, nullptr, 1024);
}

// round 7
// speedup vs baseline: 1.1656x; 1.1656x over previous
#include <cuda_runtime.h>
#include <cuda_bf16.h>
#include <stdint.h>
#include <math.h>

// B=8, M=1024, H=512, K=8 heads, D=64, SPAN=1024, MK=2048
#define DINLINE __device__ __forceinline__

// ---------------- scratch ----------------------------------------------------
__device__ __nv_bfloat16 g_Qh[64 * 1024 * 64];
__device__ __nv_bfloat16 g_Ql[64 * 1024 * 64];
__device__ __nv_bfloat16 g_Kh[64 * 2048 * 64];
__device__ __nv_bfloat16 g_Kl[64 * 2048 * 64];
__device__ __nv_bfloat16 g_Vh[64 * 2048 * 64];
__device__ __nv_bfloat16 g_Vl[64 * 2048 * 64];
__device__ float g_C[8 * 1024 * 512];

// ---------------- helpers ----------------------------------------------------
DINLINE void mma_bf16(float c[4], uint32_t a0, uint32_t a1, uint32_t a2,
                      uint32_t a3, uint32_t b0, uint32_t b1) {
    asm volatile(
        "mma.sync.aligned.m16n8k16.row.col.f32.bf16.bf16.f32 "
        "{%0,%1,%2,%3}, {%4,%5,%6,%7}, {%8,%9}, {%0,%1,%2,%3};\n"
        : "+f"(c[0]), "+f"(c[1]), "+f"(c[2]), "+f"(c[3])
        : "r"(a0), "r"(a1), "r"(a2), "r"(a3), "r"(b0), "r"(b1));
}

DINLINE uint32_t smem_u32(const void* p) {
    return (uint32_t)__cvta_generic_to_shared(p);
}

DINLINE void ldmx4(uint32_t& r0, uint32_t& r1, uint32_t& r2, uint32_t& r3,
                   uint32_t a) {
    asm volatile(
        "ldmatrix.sync.aligned.m8n8.x4.shared.b16 {%0,%1,%2,%3}, [%4];\n"
        : "=r"(r0), "=r"(r1), "=r"(r2), "=r"(r3)
        : "r"(a));
}

DINLINE void ldmx2(uint32_t& r0, uint32_t& r1, uint32_t a) {
    asm volatile("ldmatrix.sync.aligned.m8n8.x2.shared.b16 {%0,%1}, [%2];\n"
                 : "=r"(r0), "=r"(r1)
                 : "r"(a));
}

DINLINE void stmx4(uint32_t a, uint32_t r0, uint32_t r1, uint32_t r2,
                   uint32_t r3) {
    asm volatile(
        "stmatrix.sync.aligned.m8n8.x4.shared.b16 [%0], {%1,%2,%3,%4};\n" ::
            "r"(a),
        "r"(r0), "r"(r1), "r"(r2), "r"(r3));
}

DINLINE void split_bf(float x, __nv_bfloat16& h, __nv_bfloat16& l) {
    h = __float2bfloat16_rn(x);
    l = __float2bfloat16_rn(x - __bfloat162float(h));
}

DINLINE void st_bf2(__nv_bfloat16* p, __nv_bfloat16 a, __nv_bfloat16 b) {
    __nv_bfloat162 t;
    t.x = a;
    t.y = b;
    *(__nv_bfloat162*)p = t;
}

DINLINE uint32_t pack_bf2(__nv_bfloat16 a, __nv_bfloat16 b) {
    __nv_bfloat162 t;
    t.x = a;
    t.y = b;
    return *(uint32_t*)&t;
}

// ---------------- bf16x3 GEMM (round-4 proven version, 256 thr) ---------------
template <int EPI>
__global__ void __launch_bounds__(256, 1) gemm_tc(
    const float* __restrict__ A, const float* __restrict__ W,
    float* __restrict__ outF, __nv_bfloat16* __restrict__ outH,
    __nv_bfloat16* __restrict__ outL, int T) {
    constexpr int AS = 42;
    __shared__ __nv_bfloat16 Ah[128 * AS], Al[128 * AS];
    __shared__ __nv_bfloat16 Bh[128 * AS], Bl[128 * AS];

    const int tid = threadIdx.x;
    const int lane = tid & 31, wid = tid >> 5;
    const int wm = wid >> 2, wn = wid & 3;
    const int row0 = blockIdx.x * 128, col0 = blockIdx.y * 128;
    const int g = lane >> 2, t2 = (lane & 3) * 2;

    float acc[4][4][4] = {};

    for (int kk = 0; kk < 512; kk += 32) {
        {
            int r = tid >> 3, kq = (tid & 7) * 4;
#pragma unroll
            for (int it = 0; it < 4; it++, r += 32) {
                float4 v = *(const float4*)&A[(size_t)(row0 + r) * 512 + kk + kq];
                __nv_bfloat16 h0, l0, h1, l1, h2, l2, h3, l3;
                split_bf(v.x, h0, l0);
                split_bf(v.y, h1, l1);
                split_bf(v.z, h2, l2);
                split_bf(v.w, h3, l3);
                st_bf2(&Ah[r * AS + kq], h0, h1);
                st_bf2(&Ah[r * AS + kq + 2], h2, h3);
                st_bf2(&Al[r * AS + kq], l0, l1);
                st_bf2(&Al[r * AS + kq + 2], l2, l3);
            }
        }
        {
            int k = tid >> 5, c4 = (tid & 31) * 4;
#pragma unroll
            for (int it = 0; it < 4; it++, k += 8) {
                float4 v = *(const float4*)&W[(size_t)(kk + k) * 512 + col0 + c4];
                __nv_bfloat16 h, l;
                split_bf(v.x, h, l); Bh[(c4 + 0) * AS + k] = h; Bl[(c4 + 0) * AS + k] = l;
                split_bf(v.y, h, l); Bh[(c4 + 1) * AS + k] = h; Bl[(c4 + 1) * AS + k] = l;
                split_bf(v.z, h, l); Bh[(c4 + 2) * AS + k] = h; Bl[(c4 + 2) * AS + k] = l;
                split_bf(v.w, h, l); Bh[(c4 + 3) * AS + k] = h; Bl[(c4 + 3) * AS + k] = l;
            }
        }
        __syncthreads();
#pragma unroll
        for (int ks = 0; ks < 32; ks += 16) {
            uint32_t ah[4][4], al[4][4], bh[4][2], bl[4][2];
#pragma unroll
            for (int mf = 0; mf < 4; mf++) {
                int rb = wm * 64 + mf * 16 + g;
                ah[mf][0] = *(uint32_t*)&Ah[rb * AS + ks + t2];
                ah[mf][1] = *(uint32_t*)&Ah[(rb + 8) * AS + ks + t2];
                ah[mf][2] = *(uint32_t*)&Ah[rb * AS + ks + 8 + t2];
                ah[mf][3] = *(uint32_t*)&Ah[(rb + 8) * AS + ks + 8 + t2];
                al[mf][0] = *(uint32_t*)&Al[rb * AS + ks + t2];
                al[mf][1] = *(uint32_t*)&Al[(rb + 8) * AS + ks + t2];
                al[mf][2] = *(uint32_t*)&Al[rb * AS + ks + 8 + t2];
                al[mf][3] = *(uint32_t*)&Al[(rb + 8) * AS + ks + 8 + t2];
            }
#pragma unroll
            for (int nf = 0; nf < 4; nf++) {
                int cb = wn * 32 + nf * 8 + g;
                bh[nf][0] = *(uint32_t*)&Bh[cb * AS + ks + t2];
                bh[nf][1] = *(uint32_t*)&Bh[cb * AS + ks + 8 + t2];
                bl[nf][0] = *(uint32_t*)&Bl[cb * AS + ks + t2];
                bl[nf][1] = *(uint32_t*)&Bl[cb * AS + ks + 8 + t2];
            }
#pragma unroll
            for (int mf = 0; mf < 4; mf++)
#pragma unroll
                for (int nf = 0; nf < 4; nf++) {
                    mma_bf16(acc[mf][nf], ah[mf][0], ah[mf][1], ah[mf][2],
                             ah[mf][3], bh[nf][0], bh[nf][1]);
                    mma_bf16(acc[mf][nf], ah[mf][0], ah[mf][1], ah[mf][2],
                             ah[mf][3], bl[nf][0], bl[nf][1]);
                    mma_bf16(acc[mf][nf], al[mf][0], al[mf][1], al[mf][2],
                             al[mf][3], bh[nf][0], bh[nf][1]);
                }
        }
        __syncthreads();
    }

#pragma unroll
    for (int mf = 0; mf < 4; mf++) {
#pragma unroll
        for (int nf = 0; nf < 4; nf++) {
            int rr = row0 + wm * 64 + mf * 16 + g;
            int cc = col0 + wn * 32 + nf * 8 + t2;
            if (EPI == 0) {
                *(float2*)&outF[(size_t)rr * 512 + cc] =
                    make_float2(acc[mf][nf][0], acc[mf][nf][1]);
                *(float2*)&outF[(size_t)(rr + 8) * 512 + cc] =
                    make_float2(acc[mf][nf][2], acc[mf][nf][3]);
            } else {
                int head = cc >> 6, d = cc & 63;
#pragma unroll
                for (int rh = 0; rh < 2; rh++) {
                    int grow = rr + rh * 8;
                    int b = grow / T, t = grow - b * T;
                    size_t idx = (((size_t)(b * 8 + head) * T + t) << 6) + d;
                    __nv_bfloat16 h0, l0, h1, l1;
                    split_bf(acc[mf][nf][rh * 2 + 0], h0, l0);
                    split_bf(acc[mf][nf][rh * 2 + 1], h1, l1);
                    st_bf2(&outH[idx], h0, h1);
                    st_bf2(&outL[idx], l0, l1);
                }
            }
        }
    }
}

// ---------------- fused banded attention v5 -----------------------------------
// Round-4 layout (256 thr, 2x4 warps) + hoisted Q frags + ldmatrix/stmatrix.
// PV uses full 3-pass bf16x3 (Ph*Vh + Ph*Vl + Pl*Vh) -> round-4 numerics.
__global__ void __launch_bounds__(256, 1) attn_tc5(
    const __nv_bfloat16* __restrict__ Qh, const __nv_bfloat16* __restrict__ Ql,
    const __nv_bfloat16* __restrict__ Kh_, const __nv_bfloat16* __restrict__ Kl_,
    const __nv_bfloat16* __restrict__ Vh_, const __nv_bfloat16* __restrict__ Vl_,
    const float* __restrict__ Eg, float* __restrict__ Cg) {
    constexpr int QS = 72, KS = 72, ES = 72, VS = 200, PS = 200, QES = 130;
    extern __shared__ char smraw[];
    __nv_bfloat16* Qsh = (__nv_bfloat16*)smraw;  // [64][QS]
    __nv_bfloat16* Qsl = Qsh + 64 * QS;
    __nv_bfloat16* Ksh = Qsl + 64 * QS;          // [192][KS]
    __nv_bfloat16* Ksl = Ksh + 192 * KS;
    __nv_bfloat16* Esh = Ksl + 192 * KS;         // [s=128][ES] hi only
    __nv_bfloat16* Vsh = Esh + 128 * ES;         // [d=64][VS]
    __nv_bfloat16* Vsl = Vsh + 64 * VS;
    __nv_bfloat16* Psh = Vsl + 64 * VS;          // [m=64][PS]
    __nv_bfloat16* Psl = Psh + 64 * PS;
    float* QEs = (float*)(Psl + 64 * PS);        // [64][QES]
    float* redmax = QEs + 64 * QES;              // [4][64]
    float* redsum = redmax + 256;                // [4][64]
    float* mrow = redsum + 256;                  // [64]
    float* lrow = mrow + 64;                     // [64]

    const int tid = threadIdx.x, lane = tid & 31, wid = tid >> 5;
    const int wm = wid >> 2, wn = wid & 3;  // 2 x 4 warps
    const int g = lane >> 2, t2 = (lane & 3) * 2;
    const int n = blockIdx.y, m0 = blockIdx.x * 64;
    const float SCl2 = 0.125f * 1.4426950408889634f;

    // stage Q tile
    {
        const uint4* sh = (const uint4*)(Qh + (((size_t)n * 1024 + m0) << 6));
        const uint4* sl = (const uint4*)(Ql + (((size_t)n * 1024 + m0) << 6));
#pragma unroll
        for (int it = 0; it < 2; it++) {
            int f = tid + it * 256;
            int m = f >> 3, j = f & 7;
            ((uint4*)(Qsh + m * QS))[j] = sh[f];
            ((uint4*)(Qsl + m * QS))[j] = sl[f];
        }
    }
    if (tid < 64) {
        mrow[tid] = -1e30f;
        lrow[tid] = 0.f;
    }
    __syncthreads();

    // ldmatrix addresses
    const int a16 = lane & 15, a8 = lane & 7;
    const int hi4 = (lane >> 4) << 3, hi3 = ((lane >> 3) & 1) << 3;
    const uint32_t aQh = smem_u32(&Qsh[(wm * 32 + a16) * QS + hi4]);
    const uint32_t aQl = smem_u32(&Qsl[(wm * 32 + a16) * QS + hi4]);
    const uint32_t aKh = smem_u32(&Ksh[(wn * 48 + a8) * KS + hi3]);
    const uint32_t aKl = smem_u32(&Ksl[(wn * 48 + a8) * KS + hi3]);
    const uint32_t aE = smem_u32(&Esh[(wn * 32 + a8) * ES + hi3]);
    const uint32_t aVh = smem_u32(&Vsh[(wn * 16 + a8) * VS + hi3]);
    const uint32_t aVl = smem_u32(&Vsl[(wn * 16 + a8) * VS + hi3]);
    const uint32_t aPstH = smem_u32(&Psh[(wm * 32 + a16) * PS + wn * 48 + hi4]);
    const uint32_t aPstL = smem_u32(&Psl[(wm * 32 + a16) * PS + wn * 48 + hi4]);
    const uint32_t aPldH = smem_u32(&Psh[(wm * 32 + a16) * PS + hi4]);
    const uint32_t aPldL = smem_u32(&Psl[(wm * 32 + a16) * PS + hi4]);

    // hoist Q fragments (constant across all 8 chunks)
    uint32_t qfh[2][4][4], qfl[2][4][4];
#pragma unroll
    for (int mf = 0; mf < 2; mf++)
#pragma unroll
        for (int ksi = 0; ksi < 4; ksi++) {
            ldmx4(qfh[mf][ksi][0], qfh[mf][ksi][1], qfh[mf][ksi][2],
                  qfh[mf][ksi][3], aQh + mf * (16 * QS * 2) + ksi * 32);
            ldmx4(qfl[mf][ksi][0], qfl[mf][ksi][1], qfl[mf][ksi][2],
                  qfl[mf][ksi][3], aQl + mf * (16 * QS * 2) + ksi * 32);
        }

    float o[2][2][4] = {};

    for (int c = 0; c < 8; c++) {
        const int s0 = c * 128;
        const size_t kbase = ((size_t)n * 2048 + m0 + s0) << 6;
        __syncthreads();  // prior chunk's reads complete before overwrite

        // K chunk 192x64 hi/lo
        {
            const uint4* sh = (const uint4*)(Kh_ + kbase);
            const uint4* sl = (const uint4*)(Kl_ + kbase);
#pragma unroll
            for (int it = 0; it < 6; it++) {
                int f = tid + it * 256;
                int kr = f >> 3, j = f & 7;
                ((uint4*)(Ksh + kr * KS))[j] = sh[f];
                ((uint4*)(Ksl + kr * KS))[j] = sl[f];
            }
        }
        // V chunk transposed [d][key], hi and lo
        {
            int d2 = tid & 31, kp = tid >> 5;
#pragma unroll
            for (int it = 0; it < 12; it++) {
                int key = (kp + it * 8) * 2;
                uint32_t va = *(const uint32_t*)(Vh_ + kbase + (size_t)key * 64 + d2 * 2);
                uint32_t vb = *(const uint32_t*)(Vh_ + kbase + (size_t)(key + 1) * 64 + d2 * 2);
                __nv_bfloat162 x2 = *(__nv_bfloat162*)&va;
                __nv_bfloat162 y2 = *(__nv_bfloat162*)&vb;
                st_bf2(&Vsh[(2 * d2) * VS + key], x2.x, y2.x);
                st_bf2(&Vsh[(2 * d2 + 1) * VS + key], x2.y, y2.y);
                uint32_t wa = *(const uint32_t*)(Vl_ + kbase + (size_t)key * 64 + d2 * 2);
                uint32_t wb = *(const uint32_t*)(Vl_ + kbase + (size_t)(key + 1) * 64 + d2 * 2);
                __nv_bfloat162 z2 = *(__nv_bfloat162*)&wa;
                __nv_bfloat162 w2 = *(__nv_bfloat162*)&wb;
                st_bf2(&Vsl[(2 * d2) * VS + key], z2.x, w2.x);
                st_bf2(&Vsl[(2 * d2 + 1) * VS + key], z2.y, w2.y);
            }
        }
        // E chunk: Esh[s][d] = E[d][s0+s], hi only
#pragma unroll
        for (int it = 0; it < 16; it++) {
            int idx = tid + it * 256;
            int s2 = (idx & 63) * 2, d = idx >> 6;
            float2 e2 = *(const float2*)&Eg[(size_t)d * 1024 + s0 + s2];
            Esh[s2 * ES + d] = __float2bfloat16_rn(e2.x);
            Esh[(s2 + 1) * ES + d] = __float2bfloat16_rn(e2.y);
        }
        __syncthreads();

        // ---- QK (64x192 bf16x3) + QE (64x128 1-pass) ----
        float sAcc[2][6][4] = {};
        float qeAcc[2][4][4] = {};
#pragma unroll
        for (int ksi = 0; ksi < 4; ksi++) {
            const int ksb = ksi * 32;
#pragma unroll
            for (int nf = 0; nf < 6; nf++) {
                uint32_t b0, b1, c0, c1;
                ldmx2(b0, b1, aKh + nf * (8 * KS * 2) + ksb);
                ldmx2(c0, c1, aKl + nf * (8 * KS * 2) + ksb);
#pragma unroll
                for (int mf = 0; mf < 2; mf++) {
                    mma_bf16(sAcc[mf][nf], qfh[mf][ksi][0], qfh[mf][ksi][1],
                             qfh[mf][ksi][2], qfh[mf][ksi][3], b0, b1);
                    mma_bf16(sAcc[mf][nf], qfh[mf][ksi][0], qfh[mf][ksi][1],
                             qfh[mf][ksi][2], qfh[mf][ksi][3], c0, c1);
                    mma_bf16(sAcc[mf][nf], qfl[mf][ksi][0], qfl[mf][ksi][1],
                             qfl[mf][ksi][2], qfl[mf][ksi][3], b0, b1);
                }
            }
#pragma unroll
            for (int nf = 0; nf < 4; nf++) {
                uint32_t e0, e1;
                ldmx2(e0, e1, aE + nf * (8 * ES * 2) + ksb);
#pragma unroll
                for (int mf = 0; mf < 2; mf++)
                    mma_bf16(qeAcc[mf][nf], qfh[mf][ksi][0], qfh[mf][ksi][1],
                             qfh[mf][ksi][2], qfh[mf][ksi][3], e0, e1);
            }
        }
        // stage QE fragments (diagonal gather needs smem)
#pragma unroll
        for (int mf = 0; mf < 2; mf++) {
            int R = wm * 32 + mf * 16 + g;
#pragma unroll
            for (int nf = 0; nf < 4; nf++) {
                int cc = wn * 32 + nf * 8 + t2;
                *(float2*)&QEs[R * QES + cc] =
                    make_float2(qeAcc[mf][nf][0], qeAcc[mf][nf][1]);
                *(float2*)&QEs[(R + 8) * QES + cc] =
                    make_float2(qeAcc[mf][nf][2], qeAcc[mf][nf][3]);
            }
        }
        __syncthreads();

        // ---- phase 1: masked z = S + QE, per-warp row-max partials ----
#pragma unroll
        for (int mf = 0; mf < 2; mf++) {
            int R = wm * 32 + mf * 16 + g;
            float mx0 = -3e38f, mx1 = -3e38f;
#pragma unroll
            for (int nf = 0; nf < 6; nf++) {
                int cc = wn * 48 + nf * 8 + t2;
#pragma unroll
                for (int e = 0; e < 4; e++) {
                    int r = R + ((e >> 1) << 3);
                    int col = cc + (e & 1);
                    int diff = col - r;
                    float z = -3e38f;
                    if ((unsigned)diff < 128u)
                        z = sAcc[mf][nf][e] + QEs[r * QES + diff];
                    sAcc[mf][nf][e] = z;
                    if (e < 2) mx0 = fmaxf(mx0, z);
                    else mx1 = fmaxf(mx1, z);
                }
            }
            mx0 = fmaxf(mx0, __shfl_xor_sync(0xffffffffu, mx0, 1));
            mx0 = fmaxf(mx0, __shfl_xor_sync(0xffffffffu, mx0, 2));
            mx1 = fmaxf(mx1, __shfl_xor_sync(0xffffffffu, mx1, 1));
            mx1 = fmaxf(mx1, __shfl_xor_sync(0xffffffffu, mx1, 2));
            if ((lane & 3) == 0) {
                redmax[wn * 64 + R] = mx0;
                redmax[wn * 64 + R + 8] = mx1;
            }
        }
        __syncthreads();

        // ---- phase 2: exp, P store (stmatrix), sums, O rescale ----
        float mn[2][2], alpha[2][2];
#pragma unroll
        for (int mf = 0; mf < 2; mf++) {
            int R = wm * 32 + mf * 16 + g;
#pragma unroll
            for (int h = 0; h < 2; h++) {
                int r = R + h * 8;
                float rm = fmaxf(fmaxf(redmax[r], redmax[64 + r]),
                                 fmaxf(redmax[128 + r], redmax[192 + r]));
                float mo = mrow[r];
                float m2 = fmaxf(mo, rm * SCl2);
                mn[mf][h] = m2;
                alpha[mf][h] = exp2f(mo - m2);
            }
        }
#pragma unroll
        for (int mf = 0; mf < 2; mf++) {
            int R = wm * 32 + mf * 16 + g;
            float sum0 = 0.f, sum1 = 0.f;
#pragma unroll
            for (int pair = 0; pair < 3; pair++) {
                uint32_t rh[4], rl[4];
#pragma unroll
                for (int hh = 0; hh < 2; hh++) {
                    int nf = pair * 2 + hh;
                    float p0 = exp2f(sAcc[mf][nf][0] * SCl2 - mn[mf][0]);
                    float p1 = exp2f(sAcc[mf][nf][1] * SCl2 - mn[mf][0]);
                    float p2 = exp2f(sAcc[mf][nf][2] * SCl2 - mn[mf][1]);
                    float p3 = exp2f(sAcc[mf][nf][3] * SCl2 - mn[mf][1]);
                    sum0 += p0 + p1;
                    sum1 += p2 + p3;
                    __nv_bfloat16 h0, q0, h1, q1, h2, q2, h3, q3;
                    split_bf(p0, h0, q0);
                    split_bf(p1, h1, q1);
                    split_bf(p2, h2, q2);
                    split_bf(p3, h3, q3);
                    rh[hh * 2 + 0] = pack_bf2(h0, h1);
                    rh[hh * 2 + 1] = pack_bf2(h2, h3);
                    rl[hh * 2 + 0] = pack_bf2(q0, q1);
                    rl[hh * 2 + 1] = pack_bf2(q2, q3);
                }
                stmx4(aPstH + mf * (16 * PS * 2) + pair * 32, rh[0], rh[1],
                      rh[2], rh[3]);
                stmx4(aPstL + mf * (16 * PS * 2) + pair * 32, rl[0], rl[1],
                      rl[2], rl[3]);
            }
            sum0 += __shfl_xor_sync(0xffffffffu, sum0, 1);
            sum0 += __shfl_xor_sync(0xffffffffu, sum0, 2);
            sum1 += __shfl_xor_sync(0xffffffffu, sum1, 1);
            sum1 += __shfl_xor_sync(0xffffffffu, sum1, 2);
            if ((lane & 3) == 0) {
                redsum[wn * 64 + R] = sum0;
                redsum[wn * 64 + R + 8] = sum1;
            }
#pragma unroll
            for (int nf = 0; nf < 2; nf++) {
                o[mf][nf][0] *= alpha[mf][0];
                o[mf][nf][1] *= alpha[mf][0];
                o[mf][nf][2] *= alpha[mf][1];
                o[mf][nf][3] *= alpha[mf][1];
            }
        }
        __syncthreads();

        // state update (one writer per row)
        if (wn == 0 && (lane & 3) == 0) {
#pragma unroll
            for (int mf = 0; mf < 2; mf++) {
                int R = wm * 32 + mf * 16 + g;
#pragma unroll
                for (int h = 0; h < 2; h++) {
                    int r = R + h * 8;
                    float s = redsum[r] + redsum[64 + r] + redsum[128 + r] +
                              redsum[192 + r];
                    lrow[r] = lrow[r] * alpha[mf][h] + s;
                    mrow[r] = mn[mf][h];
                }
            }
        }

        // ---- PV: O += P(64x192) @ V^T (full bf16x3: 3 passes) ----
#pragma unroll
        for (int ks = 0; ks < 192; ks += 16) {
            uint32_t ph[2][4], pl[2][4];
#pragma unroll
            for (int mf = 0; mf < 2; mf++) {
                ldmx4(ph[mf][0], ph[mf][1], ph[mf][2], ph[mf][3],
                      aPldH + mf * (16 * PS * 2) + ks * 2);
                ldmx4(pl[mf][0], pl[mf][1], pl[mf][2], pl[mf][3],
                      aPldL + mf * (16 * PS * 2) + ks * 2);
            }
#pragma unroll
            for (int nf = 0; nf < 2; nf++) {
                uint32_t v0, v1, u0, u1;
                ldmx2(v0, v1, aVh + nf * (8 * VS * 2) + ks * 2);
                ldmx2(u0, u1, aVl + nf * (8 * VS * 2) + ks * 2);
#pragma unroll
                for (int mf = 0; mf < 2; mf++) {
                    mma_bf16(o[mf][nf], ph[mf][0], ph[mf][1], ph[mf][2],
                             ph[mf][3], v0, v1);
                    mma_bf16(o[mf][nf], ph[mf][0], ph[mf][1], ph[mf][2],
                             ph[mf][3], u0, u1);
                    mma_bf16(o[mf][nf], pl[mf][0], pl[mf][1], pl[mf][2],
                             pl[mf][3], v0, v1);
                }
            }
        }
    }

    __syncthreads();
    // epilogue: normalize, write context [B,M,H] fp32
    const int b = n >> 3, kh = n & 7;
#pragma unroll
    for (int mf = 0; mf < 2; mf++) {
        int r = wm * 32 + mf * 16 + g;
        float i0 = 1.0f / lrow[r];
        float i1 = 1.0f / lrow[r + 8];
#pragma unroll
        for (int nf = 0; nf < 2; nf++) {
            int cc = kh * 64 + wn * 16 + nf * 8 + t2;
            size_t base = ((size_t)b * 1024 + m0 + r) * 512 + cc;
            *(float2*)&Cg[base] =
                make_float2(o[mf][nf][0] * i0, o[mf][nf][1] * i0);
            *(float2*)&Cg[base + 8 * 512] =
                make_float2(o[mf][nf][2] * i1, o[mf][nf][3] * i1);
        }
    }
}

// ---------------- launcher ----------------------------------------------------
extern "C" void kernel_launch(void* const* d_in, const int* in_sizes, int n_in,
                              void* d_out, int out_size) {
    const float* query = (const float*)d_in[0];
    const float* key = (const float*)d_in[1];
    const float* value = (const float*)d_in[2];
    const float* pos = (const float*)d_in[3];
    const float* Wq = (const float*)d_in[4];
    const float* Wk = (const float*)d_in[5];
    const float* Wv = (const float*)d_in[6];
    const float* Wo = (const float*)d_in[7];
    float* out = (float*)d_out;

    __nv_bfloat16 *qh, *ql, *kh, *kl, *vh, *vl;
    float* cptr;
    cudaGetSymbolAddress((void**)&qh, g_Qh);
    cudaGetSymbolAddress((void**)&ql, g_Ql);
    cudaGetSymbolAddress((void**)&kh, g_Kh);
    cudaGetSymbolAddress((void**)&kl, g_Kl);
    cudaGetSymbolAddress((void**)&vh, g_Vh);
    cudaGetSymbolAddress((void**)&vl, g_Vl);
    cudaGetSymbolAddress((void**)&cptr, g_C);

    gemm_tc<1><<<dim3(64, 4), 256>>>(query, Wq, nullptr, qh, ql, 1024);
    gemm_tc<1><<<dim3(128, 4), 256>>>(key, Wk, nullptr, kh, kl, 2048);
    gemm_tc<1><<<dim3(128, 4), 256>>>(value, Wv, nullptr, vh, vl, 2048);

    // smem bytes: bf16 regions *2 + fp32 regions *4
    const int smem_bytes =
        (2 * 64 * 72 + 2 * 192 * 72 + 128 * 72 + 2 * 64 * 200 + 2 * 64 * 200) * 2 +
        (64 * 130 + 256 + 256 + 64 + 64) * 4;  // 230400
    cudaFuncSetAttribute(attn_tc5, cudaFuncAttributeMaxDynamicSharedMemorySize,
                         smem_bytes);
    attn_tc5<<<dim3(16, 64), 256, smem_bytes>>>(qh, ql, kh, kl, vh, vl, pos,
                                                cptr);

    gemm_tc<0><<<dim3(64, 4), 256>>>(cptr, Wo, out, nullptr, nullptr, 1024);
}

// round 8
// speedup vs baseline: 1.5325x; 1.3147x over previous
#include <cuda_runtime.h>
#include <cuda_bf16.h>
#include <stdint.h>
#include <math.h>

// B=8, M=1024, H=512, K=8 heads, D=64, SPAN=1024, MK=2048
#define DINLINE __device__ __forceinline__

// ---------------- scratch ----------------------------------------------------
__device__ __align__(16) __nv_bfloat16 g_Qh[64 * 1024 * 64];
__device__ __align__(16) __nv_bfloat16 g_Ql[64 * 1024 * 64];
__device__ __align__(16) __nv_bfloat16 g_Kh[64 * 2048 * 64];
__device__ __align__(16) __nv_bfloat16 g_Kl[64 * 2048 * 64];
__device__ __align__(16) __nv_bfloat16 g_Vh[64 * 2048 * 64];
__device__ __align__(16) __nv_bfloat16 g_Vl[64 * 2048 * 64];
__device__ __align__(16) __nv_bfloat16 g_Xqh[8 * 1024 * 512], g_Xql[8 * 1024 * 512];
__device__ __align__(16) __nv_bfloat16 g_Xkh[8 * 2048 * 512], g_Xkl[8 * 2048 * 512];
__device__ __align__(16) __nv_bfloat16 g_Xvh[8 * 2048 * 512], g_Xvl[8 * 2048 * 512];
__device__ __align__(16) __nv_bfloat16 g_WqTh[512 * 512], g_WqTl[512 * 512];
__device__ __align__(16) __nv_bfloat16 g_WkTh[512 * 512], g_WkTl[512 * 512];
__device__ __align__(16) __nv_bfloat16 g_WvTh[512 * 512], g_WvTl[512 * 512];
__device__ __align__(16) __nv_bfloat16 g_WoTh[512 * 512], g_WoTl[512 * 512];
__device__ __align__(16) __nv_bfloat16 g_Ch[8 * 1024 * 512], g_Cl[8 * 1024 * 512];

// ---------------- helpers ----------------------------------------------------
DINLINE void mma_bf16(float c[4], uint32_t a0, uint32_t a1, uint32_t a2,
                      uint32_t a3, uint32_t b0, uint32_t b1) {
    asm volatile(
        "mma.sync.aligned.m16n8k16.row.col.f32.bf16.bf16.f32 "
        "{%0,%1,%2,%3}, {%4,%5,%6,%7}, {%8,%9}, {%0,%1,%2,%3};\n"
        : "+f"(c[0]), "+f"(c[1]), "+f"(c[2]), "+f"(c[3])
        : "r"(a0), "r"(a1), "r"(a2), "r"(a3), "r"(b0), "r"(b1));
}

DINLINE uint32_t smem_u32(const void* p) {
    return (uint32_t)__cvta_generic_to_shared(p);
}

DINLINE void cp16(uint32_t dst, const void* src) {
    asm volatile("cp.async.cg.shared.global [%0], [%1], 16;\n" ::"r"(dst),
                 "l"(src));
}
DINLINE void cp_commit() { asm volatile("cp.async.commit_group;\n" ::); }
template <int N>
DINLINE void cp_wait() {
    asm volatile("cp.async.wait_group %0;\n" ::"n"(N));
}

DINLINE void split_bf(float x, __nv_bfloat16& h, __nv_bfloat16& l) {
    h = __float2bfloat16_rn(x);
    l = __float2bfloat16_rn(x - __bfloat162float(h));
}

DINLINE void st_bf2(__nv_bfloat16* p, __nv_bfloat16 a, __nv_bfloat16 b) {
    __nv_bfloat162 t;
    t.x = a;
    t.y = b;
    *(__nv_bfloat162*)p = t;
}

// ---------------- split kernels ------------------------------------------------
__global__ void __launch_bounds__(256) split_x(const float* __restrict__ in,
                                               __nv_bfloat16* __restrict__ h,
                                               __nv_bfloat16* __restrict__ l,
                                               int n4) {
    int i = blockIdx.x * blockDim.x + threadIdx.x;
    if (i >= n4) return;
    float4 v = ((const float4*)in)[i];
    __nv_bfloat16 h0, l0, h1, l1, h2, l2, h3, l3;
    split_bf(v.x, h0, l0);
    split_bf(v.y, h1, l1);
    split_bf(v.z, h2, l2);
    split_bf(v.w, h3, l3);
    st_bf2(h + (size_t)i * 4, h0, h1);
    st_bf2(h + (size_t)i * 4 + 2, h2, h3);
    st_bf2(l + (size_t)i * 4, l0, l1);
    st_bf2(l + (size_t)i * 4 + 2, l2, l3);
}

// W[k][n] (512x512) -> T[n][k] split hi/lo
__global__ void __launch_bounds__(256) split_wT(const float* __restrict__ W,
                                                __nv_bfloat16* __restrict__ Th,
                                                __nv_bfloat16* __restrict__ Tl) {
    __shared__ float tile[32][33];
    int tx = threadIdx.x, ty = threadIdx.y;  // (32, 8)
    int n0 = blockIdx.x * 32, k0 = blockIdx.y * 32;
#pragma unroll
    for (int i = 0; i < 4; i++)
        tile[ty + i * 8][tx] = W[(size_t)(k0 + ty + i * 8) * 512 + n0 + tx];
    __syncthreads();
#pragma unroll
    for (int i = 0; i < 4; i++) {
        float v = tile[tx][ty + i * 8];
        __nv_bfloat16 h, l;
        split_bf(v, h, l);
        Th[(size_t)(n0 + ty + i * 8) * 512 + k0 + tx] = h;
        Tl[(size_t)(n0 + ty + i * 8) * 512 + k0 + tx] = l;
    }
}

// ---------------- pre-split bf16x3 GEMM with cp.async double buffer -----------
// C[R,512] = A[R,512] @ W ; A given hi/lo, W given transposed [n][k] hi/lo.
// EPI=0: fp32 out. EPI=1: head-scatter bf16 hi/lo out.
constexpr int AS2 = 40;
constexpr int TSZ = 128 * AS2;

template <int EPI>
__global__ void __launch_bounds__(256, 1) gemm_ps(
    const __nv_bfloat16* __restrict__ Ah_g, const __nv_bfloat16* __restrict__ Al_g,
    const __nv_bfloat16* __restrict__ Th_g, const __nv_bfloat16* __restrict__ Tl_g,
    float* __restrict__ outF, __nv_bfloat16* __restrict__ outH,
    __nv_bfloat16* __restrict__ outL, int T) {
    extern __shared__ __nv_bfloat16 smg[];

    const int tid = threadIdx.x;
    const int lane = tid & 31, wid = tid >> 5;
    const int wm = wid >> 2, wn = wid & 3;  // 2 x 4 warps
    const int row0 = blockIdx.x * 128, col0 = blockIdx.y * 128;
    const int g = lane >> 2, t2 = (lane & 3) * 2;

    const int lr = tid >> 2;        // 0..63
    const int lc = (tid & 3) * 8;   // 0,8,16,24 (bf16 units; 16B chunks)

    float acc[4][4][4] = {};

    // prologue load, buffer 0
    {
        __nv_bfloat16* Ah = smg;
        __nv_bfloat16* Al = Ah + TSZ;
        __nv_bfloat16* Bh = Al + TSZ;
        __nv_bfloat16* Bl = Bh + TSZ;
#pragma unroll
        for (int half = 0; half < 2; half++) {
            int r = lr + half * 64;
            cp16(smem_u32(Ah + r * AS2 + lc), Ah_g + (size_t)(row0 + r) * 512 + lc);
            cp16(smem_u32(Al + r * AS2 + lc), Al_g + (size_t)(row0 + r) * 512 + lc);
            cp16(smem_u32(Bh + r * AS2 + lc), Th_g + (size_t)(col0 + r) * 512 + lc);
            cp16(smem_u32(Bl + r * AS2 + lc), Tl_g + (size_t)(col0 + r) * 512 + lc);
        }
        cp_commit();
    }

    int buf = 0;
    for (int kk = 0; kk < 512; kk += 32) {
        if (kk + 32 < 512) {
            __nv_bfloat16* Ah = smg + (buf ^ 1) * 4 * TSZ;
            __nv_bfloat16* Al = Ah + TSZ;
            __nv_bfloat16* Bh = Al + TSZ;
            __nv_bfloat16* Bl = Bh + TSZ;
            int kn = kk + 32;
#pragma unroll
            for (int half = 0; half < 2; half++) {
                int r = lr + half * 64;
                cp16(smem_u32(Ah + r * AS2 + lc),
                     Ah_g + (size_t)(row0 + r) * 512 + kn + lc);
                cp16(smem_u32(Al + r * AS2 + lc),
                     Al_g + (size_t)(row0 + r) * 512 + kn + lc);
                cp16(smem_u32(Bh + r * AS2 + lc),
                     Th_g + (size_t)(col0 + r) * 512 + kn + lc);
                cp16(smem_u32(Bl + r * AS2 + lc),
                     Tl_g + (size_t)(col0 + r) * 512 + kn + lc);
            }
            cp_commit();
            cp_wait<1>();
        } else {
            cp_wait<0>();
        }
        __syncthreads();

        const __nv_bfloat16* Ah = smg + buf * 4 * TSZ;
        const __nv_bfloat16* Al = Ah + TSZ;
        const __nv_bfloat16* Bh = Al + TSZ;
        const __nv_bfloat16* Bl = Bh + TSZ;
#pragma unroll
        for (int ks = 0; ks < 32; ks += 16) {
            uint32_t ah[4][4], al[4][4], bh[4][2], bl[4][2];
#pragma unroll
            for (int mf = 0; mf < 4; mf++) {
                int rb = wm * 64 + mf * 16 + g;
                ah[mf][0] = *(uint32_t*)&Ah[rb * AS2 + ks + t2];
                ah[mf][1] = *(uint32_t*)&Ah[(rb + 8) * AS2 + ks + t2];
                ah[mf][2] = *(uint32_t*)&Ah[rb * AS2 + ks + 8 + t2];
                ah[mf][3] = *(uint32_t*)&Ah[(rb + 8) * AS2 + ks + 8 + t2];
                al[mf][0] = *(uint32_t*)&Al[rb * AS2 + ks + t2];
                al[mf][1] = *(uint32_t*)&Al[(rb + 8) * AS2 + ks + t2];
                al[mf][2] = *(uint32_t*)&Al[rb * AS2 + ks + 8 + t2];
                al[mf][3] = *(uint32_t*)&Al[(rb + 8) * AS2 + ks + 8 + t2];
            }
#pragma unroll
            for (int nf = 0; nf < 4; nf++) {
                int cb = wn * 32 + nf * 8 + g;
                bh[nf][0] = *(uint32_t*)&Bh[cb * AS2 + ks + t2];
                bh[nf][1] = *(uint32_t*)&Bh[cb * AS2 + ks + 8 + t2];
                bl[nf][0] = *(uint32_t*)&Bl[cb * AS2 + ks + t2];
                bl[nf][1] = *(uint32_t*)&Bl[cb * AS2 + ks + 8 + t2];
            }
#pragma unroll
            for (int mf = 0; mf < 4; mf++)
#pragma unroll
                for (int nf = 0; nf < 4; nf++) {
                    mma_bf16(acc[mf][nf], ah[mf][0], ah[mf][1], ah[mf][2],
                             ah[mf][3], bh[nf][0], bh[nf][1]);
                    mma_bf16(acc[mf][nf], ah[mf][0], ah[mf][1], ah[mf][2],
                             ah[mf][3], bl[nf][0], bl[nf][1]);
                    mma_bf16(acc[mf][nf], al[mf][0], al[mf][1], al[mf][2],
                             al[mf][3], bh[nf][0], bh[nf][1]);
                }
        }
        __syncthreads();
        buf ^= 1;
    }

    // epilogue
#pragma unroll
    for (int mf = 0; mf < 4; mf++) {
#pragma unroll
        for (int nf = 0; nf < 4; nf++) {
            int rr = row0 + wm * 64 + mf * 16 + g;
            int cc = col0 + wn * 32 + nf * 8 + t2;
            if (EPI == 0) {
                *(float2*)&outF[(size_t)rr * 512 + cc] =
                    make_float2(acc[mf][nf][0], acc[mf][nf][1]);
                *(float2*)&outF[(size_t)(rr + 8) * 512 + cc] =
                    make_float2(acc[mf][nf][2], acc[mf][nf][3]);
            } else {
                int head = cc >> 6, d = cc & 63;
#pragma unroll
                for (int rh = 0; rh < 2; rh++) {
                    int grow = rr + rh * 8;
                    int b = grow / T, t = grow - b * T;
                    size_t idx = (((size_t)(b * 8 + head) * T + t) << 6) + d;
                    __nv_bfloat16 h0, l0, h1, l1;
                    split_bf(acc[mf][nf][rh * 2 + 0], h0, l0);
                    split_bf(acc[mf][nf][rh * 2 + 1], h1, l1);
                    st_bf2(&outH[idx], h0, h1);
                    st_bf2(&outL[idx], l0, l1);
                }
            }
        }
    }
}

// ---------------- fused banded attention (round-4 proven version) -------------
// 64 queries/CTA, key-chunk 128 (192 keys loaded), 8 chunks, 256 thr 2x4 warps.
// Changes vs round 4: K loads via cp.async (overlap with V/E staging); epilogue
// writes context pre-split bf16 hi/lo (bit-identical to old fp32->split path).
__global__ void __launch_bounds__(256, 1) attn_tc6(
    const __nv_bfloat16* __restrict__ Qh, const __nv_bfloat16* __restrict__ Ql,
    const __nv_bfloat16* __restrict__ Kh_, const __nv_bfloat16* __restrict__ Kl_,
    const __nv_bfloat16* __restrict__ Vh_, const __nv_bfloat16* __restrict__ Vl_,
    const float* __restrict__ Eg, __nv_bfloat16* __restrict__ Ch,
    __nv_bfloat16* __restrict__ Cl) {
    constexpr int QS = 72, KS = 72, ES = 66, VS = 200, PS = 200, QES = 132;
    extern __shared__ char smraw[];
    __nv_bfloat16* Qsh = (__nv_bfloat16*)smraw;  // [64][QS]
    __nv_bfloat16* Qsl = Qsh + 64 * QS;
    __nv_bfloat16* Ksh = Qsl + 64 * QS;          // [192][KS]
    __nv_bfloat16* Ksl = Ksh + 192 * KS;
    __nv_bfloat16* Esh = Ksl + 192 * KS;         // [s=128][ES] hi only
    __nv_bfloat16* Vsh = Esh + 128 * ES;         // [d=64][VS]
    __nv_bfloat16* Vsl = Vsh + 64 * VS;
    __nv_bfloat16* Psh = Vsl + 64 * VS;          // [m=64][PS]
    __nv_bfloat16* Psl = Psh + 64 * PS;
    float* QEs = (float*)(Psl + 64 * PS);        // [64][QES]
    float* redmax = QEs + 64 * QES;              // [4][64]
    float* redsum = redmax + 256;                // [4][64]
    float* mrow = redsum + 256;                  // [64]
    float* lrow = mrow + 64;                     // [64]

    const int tid = threadIdx.x, lane = tid & 31, wid = tid >> 5;
    const int wm = wid >> 2, wn = wid & 3;  // 2 x 4 warps
    const int g = lane >> 2, t2 = (lane & 3) * 2;
    const int n = blockIdx.y, m0 = blockIdx.x * 64;
    const float SCl2 = 0.125f * 1.4426950408889634f;

    // stage Q tile
    {
        const uint4* sh = (const uint4*)(Qh + (((size_t)n * 1024 + m0) << 6));
        const uint4* sl = (const uint4*)(Ql + (((size_t)n * 1024 + m0) << 6));
#pragma unroll
        for (int it = 0; it < 2; it++) {
            int f = tid + it * 256;
            int m = f >> 3, j = f & 7;
            ((uint4*)(Qsh + m * QS))[j] = sh[f];
            ((uint4*)(Qsl + m * QS))[j] = sl[f];
        }
    }
    if (tid < 64) {
        mrow[tid] = -1e30f;
        lrow[tid] = 0.f;
    }

    float o[2][2][4] = {};

    for (int c = 0; c < 8; c++) {
        const int s0 = c * 128;
        const size_t kbase = ((size_t)n * 2048 + m0 + s0) << 6;
        __syncthreads();  // prior chunk's reads complete before overwrite

        // K chunk 192x64 hi/lo via cp.async (overlaps V/E staging below)
        {
            const __nv_bfloat16* sh = Kh_ + kbase;
            const __nv_bfloat16* sl = Kl_ + kbase;
#pragma unroll
            for (int it = 0; it < 6; it++) {
                int f = tid + it * 256;
                int kr = f >> 3, j = (f & 7) * 8;
                cp16(smem_u32(Ksh + kr * KS + j), sh + f * 8);
                cp16(smem_u32(Ksl + kr * KS + j), sl + f * 8);
            }
            cp_commit();
        }
        // V chunk transposed [d][key], hi and lo
        {
            int d2 = tid & 31, kp = tid >> 5;
#pragma unroll
            for (int it = 0; it < 12; it++) {
                int key = (kp + it * 8) * 2;
                uint32_t va = *(const uint32_t*)(Vh_ + kbase + (size_t)key * 64 + d2 * 2);
                uint32_t vb = *(const uint32_t*)(Vh_ + kbase + (size_t)(key + 1) * 64 + d2 * 2);
                __nv_bfloat162 x2 = *(__nv_bfloat162*)&va;
                __nv_bfloat162 y2 = *(__nv_bfloat162*)&vb;
                st_bf2(&Vsh[(2 * d2) * VS + key], x2.x, y2.x);
                st_bf2(&Vsh[(2 * d2 + 1) * VS + key], x2.y, y2.y);
                uint32_t wa = *(const uint32_t*)(Vl_ + kbase + (size_t)key * 64 + d2 * 2);
                uint32_t wb = *(const uint32_t*)(Vl_ + kbase + (size_t)(key + 1) * 64 + d2 * 2);
                __nv_bfloat162 z2 = *(__nv_bfloat162*)&wa;
                __nv_bfloat162 w2 = *(__nv_bfloat162*)&wb;
                st_bf2(&Vsl[(2 * d2) * VS + key], z2.x, w2.x);
                st_bf2(&Vsl[(2 * d2 + 1) * VS + key], z2.y, w2.y);
            }
        }
        // E chunk: Esh[s][d] = E[d][s0+s], hi only
#pragma unroll
        for (int it = 0; it < 16; it++) {
            int idx = tid + it * 256;
            int s2 = (idx & 63) * 2, d = idx >> 6;
            float2 e2 = *(const float2*)&Eg[(size_t)d * 1024 + s0 + s2];
            Esh[s2 * ES + d] = __float2bfloat16_rn(e2.x);
            Esh[(s2 + 1) * ES + d] = __float2bfloat16_rn(e2.y);
        }
        cp_wait<0>();
        __syncthreads();

        // ---- QK (64x192 bf16x3) + QE (64x128 1-pass) ----
        float sAcc[2][6][4] = {};
        float qeAcc[2][4][4] = {};
#pragma unroll
        for (int ks = 0; ks < 64; ks += 16) {
            uint32_t ah[2][4], al[2][4];
#pragma unroll
            for (int mf = 0; mf < 2; mf++) {
                int rb = wm * 32 + mf * 16 + g;
                ah[mf][0] = *(uint32_t*)&Qsh[rb * QS + ks + t2];
                ah[mf][1] = *(uint32_t*)&Qsh[(rb + 8) * QS + ks + t2];
                ah[mf][2] = *(uint32_t*)&Qsh[rb * QS + ks + 8 + t2];
                ah[mf][3] = *(uint32_t*)&Qsh[(rb + 8) * QS + ks + 8 + t2];
                al[mf][0] = *(uint32_t*)&Qsl[rb * QS + ks + t2];
                al[mf][1] = *(uint32_t*)&Qsl[(rb + 8) * QS + ks + t2];
                al[mf][2] = *(uint32_t*)&Qsl[rb * QS + ks + 8 + t2];
                al[mf][3] = *(uint32_t*)&Qsl[(rb + 8) * QS + ks + 8 + t2];
            }
#pragma unroll
            for (int nf = 0; nf < 6; nf++) {
                int cb = wn * 48 + nf * 8 + g;
                uint32_t kb0 = *(uint32_t*)&Ksh[cb * KS + ks + t2];
                uint32_t kb1 = *(uint32_t*)&Ksh[cb * KS + ks + 8 + t2];
                uint32_t kl0 = *(uint32_t*)&Ksl[cb * KS + ks + t2];
                uint32_t kl1 = *(uint32_t*)&Ksl[cb * KS + ks + 8 + t2];
#pragma unroll
                for (int mf = 0; mf < 2; mf++) {
                    mma_bf16(sAcc[mf][nf], ah[mf][0], ah[mf][1], ah[mf][2],
                             ah[mf][3], kb0, kb1);
                    mma_bf16(sAcc[mf][nf], ah[mf][0], ah[mf][1], ah[mf][2],
                             ah[mf][3], kl0, kl1);
                    mma_bf16(sAcc[mf][nf], al[mf][0], al[mf][1], al[mf][2],
                             al[mf][3], kb0, kb1);
                }
            }
#pragma unroll
            for (int nf = 0; nf < 4; nf++) {
                int cb = wn * 32 + nf * 8 + g;
                uint32_t eb0 = *(uint32_t*)&Esh[cb * ES + ks + t2];
                uint32_t eb1 = *(uint32_t*)&Esh[cb * ES + ks + 8 + t2];
#pragma unroll
                for (int mf = 0; mf < 2; mf++)
                    mma_bf16(qeAcc[mf][nf], ah[mf][0], ah[mf][1], ah[mf][2],
                             ah[mf][3], eb0, eb1);
            }
        }
        // stage QE fragments (diagonal gather needs smem)
#pragma unroll
        for (int mf = 0; mf < 2; mf++) {
            int R = wm * 32 + mf * 16 + g;
#pragma unroll
            for (int nf = 0; nf < 4; nf++) {
                int cc = wn * 32 + nf * 8 + t2;
                *(float2*)&QEs[R * QES + cc] =
                    make_float2(qeAcc[mf][nf][0], qeAcc[mf][nf][1]);
                *(float2*)&QEs[(R + 8) * QES + cc] =
                    make_float2(qeAcc[mf][nf][2], qeAcc[mf][nf][3]);
            }
        }
        __syncthreads();

        // ---- phase 1: masked z = S + QE, per-warp row-max partials ----
#pragma unroll
        for (int mf = 0; mf < 2; mf++) {
            int R = wm * 32 + mf * 16 + g;
            float mx0 = -3e38f, mx1 = -3e38f;
#pragma unroll
            for (int nf = 0; nf < 6; nf++) {
                int cc = wn * 48 + nf * 8 + t2;
#pragma unroll
                for (int e = 0; e < 4; e++) {
                    int r = R + ((e >> 1) << 3);
                    int col = cc + (e & 1);
                    int diff = col - r;
                    float z = -3e38f;
                    if ((unsigned)diff < 128u)
                        z = sAcc[mf][nf][e] + QEs[r * QES + diff];
                    sAcc[mf][nf][e] = z;
                    if (e < 2) mx0 = fmaxf(mx0, z);
                    else mx1 = fmaxf(mx1, z);
                }
            }
            mx0 = fmaxf(mx0, __shfl_xor_sync(0xffffffffu, mx0, 1));
            mx0 = fmaxf(mx0, __shfl_xor_sync(0xffffffffu, mx0, 2));
            mx1 = fmaxf(mx1, __shfl_xor_sync(0xffffffffu, mx1, 1));
            mx1 = fmaxf(mx1, __shfl_xor_sync(0xffffffffu, mx1, 2));
            if ((lane & 3) == 0) {
                redmax[wn * 64 + R] = mx0;
                redmax[wn * 64 + R + 8] = mx1;
            }
        }
        __syncthreads();

        // ---- phase 2: exp, P store, sums, O rescale ----
        float mn[2][2], alpha[2][2];
#pragma unroll
        for (int mf = 0; mf < 2; mf++) {
            int R = wm * 32 + mf * 16 + g;
#pragma unroll
            for (int h = 0; h < 2; h++) {
                int r = R + h * 8;
                float rm = fmaxf(fmaxf(redmax[r], redmax[64 + r]),
                                 fmaxf(redmax[128 + r], redmax[192 + r]));
                float mo = mrow[r];
                float m2 = fmaxf(mo, rm * SCl2);
                mn[mf][h] = m2;
                alpha[mf][h] = exp2f(mo - m2);
            }
        }
#pragma unroll
        for (int mf = 0; mf < 2; mf++) {
            int R = wm * 32 + mf * 16 + g;
            float sum0 = 0.f, sum1 = 0.f;
#pragma unroll
            for (int nf = 0; nf < 6; nf++) {
                int cc = wn * 48 + nf * 8 + t2;
                float p[4];
#pragma unroll
                for (int e = 0; e < 4; e++) {
                    int r = R + ((e >> 1) << 3);
                    int col = cc + (e & 1);
                    int diff = col - r;
                    float pv = 0.f;
                    if ((unsigned)diff < 128u)
                        pv = exp2f(sAcc[mf][nf][e] * SCl2 - mn[mf][e >> 1]);
                    p[e] = pv;
                    if (e < 2) sum0 += pv;
                    else sum1 += pv;
                }
                __nv_bfloat16 h0, l0, h1, l1;
                split_bf(p[0], h0, l0);
                split_bf(p[1], h1, l1);
                st_bf2(&Psh[R * PS + cc], h0, h1);
                st_bf2(&Psl[R * PS + cc], l0, l1);
                split_bf(p[2], h0, l0);
                split_bf(p[3], h1, l1);
                st_bf2(&Psh[(R + 8) * PS + cc], h0, h1);
                st_bf2(&Psl[(R + 8) * PS + cc], l0, l1);
            }
            sum0 += __shfl_xor_sync(0xffffffffu, sum0, 1);
            sum0 += __shfl_xor_sync(0xffffffffu, sum0, 2);
            sum1 += __shfl_xor_sync(0xffffffffu, sum1, 1);
            sum1 += __shfl_xor_sync(0xffffffffu, sum1, 2);
            if ((lane & 3) == 0) {
                redsum[wn * 64 + R] = sum0;
                redsum[wn * 64 + R + 8] = sum1;
            }
#pragma unroll
            for (int nf = 0; nf < 2; nf++) {
                o[mf][nf][0] *= alpha[mf][0];
                o[mf][nf][1] *= alpha[mf][0];
                o[mf][nf][2] *= alpha[mf][1];
                o[mf][nf][3] *= alpha[mf][1];
            }
        }
        __syncthreads();

        // state update (one writer per row)
        if (wn == 0 && (lane & 3) == 0) {
#pragma unroll
            for (int mf = 0; mf < 2; mf++) {
                int R = wm * 32 + mf * 16 + g;
#pragma unroll
                for (int h = 0; h < 2; h++) {
                    int r = R + h * 8;
                    float s = redsum[r] + redsum[64 + r] + redsum[128 + r] +
                              redsum[192 + r];
                    lrow[r] = lrow[r] * alpha[mf][h] + s;
                    mrow[r] = mn[mf][h];
                }
            }
        }

        // ---- PV: O += P(64x192) @ V^T (full bf16x3) ----
#pragma unroll
        for (int ks = 0; ks < 192; ks += 16) {
            uint32_t ph[2][4], pl[2][4];
#pragma unroll
            for (int mf = 0; mf < 2; mf++) {
                int rb = wm * 32 + mf * 16 + g;
                ph[mf][0] = *(uint32_t*)&Psh[rb * PS + ks + t2];
                ph[mf][1] = *(uint32_t*)&Psh[(rb + 8) * PS + ks + t2];
                ph[mf][2] = *(uint32_t*)&Psh[rb * PS + ks + 8 + t2];
                ph[mf][3] = *(uint32_t*)&Psh[(rb + 8) * PS + ks + 8 + t2];
                pl[mf][0] = *(uint32_t*)&Psl[rb * PS + ks + t2];
                pl[mf][1] = *(uint32_t*)&Psl[(rb + 8) * PS + ks + t2];
                pl[mf][2] = *(uint32_t*)&Psl[rb * PS + ks + 8 + t2];
                pl[mf][3] = *(uint32_t*)&Psl[(rb + 8) * PS + ks + 8 + t2];
            }
#pragma unroll
            for (int nf = 0; nf < 2; nf++) {
                int cb = wn * 16 + nf * 8 + g;
                uint32_t vh0 = *(uint32_t*)&Vsh[cb * VS + ks + t2];
                uint32_t vh1 = *(uint32_t*)&Vsh[cb * VS + ks + 8 + t2];
                uint32_t vl0 = *(uint32_t*)&Vsl[cb * VS + ks + t2];
                uint32_t vl1 = *(uint32_t*)&Vsl[cb * VS + ks + 8 + t2];
#pragma unroll
                for (int mf = 0; mf < 2; mf++) {
                    mma_bf16(o[mf][nf], ph[mf][0], ph[mf][1], ph[mf][2],
                             ph[mf][3], vh0, vh1);
                    mma_bf16(o[mf][nf], ph[mf][0], ph[mf][1], ph[mf][2],
                             ph[mf][3], vl0, vl1);
                    mma_bf16(o[mf][nf], pl[mf][0], pl[mf][1], pl[mf][2],
                             pl[mf][3], vh0, vh1);
                }
            }
        }
    }

    __syncthreads();
    // epilogue: normalize, write context pre-split bf16 hi/lo in [B,M,H]
    const int b = n >> 3, kh = n & 7;
#pragma unroll
    for (int mf = 0; mf < 2; mf++) {
        int r = wm * 32 + mf * 16 + g;
        float i0 = 1.0f / lrow[r];
        float i1 = 1.0f / lrow[r + 8];
#pragma unroll
        for (int nf = 0; nf < 2; nf++) {
            int cc = kh * 64 + wn * 16 + nf * 8 + t2;
            size_t base = ((size_t)b * 1024 + m0 + r) * 512 + cc;
            __nv_bfloat16 h0, l0, h1, l1;
            split_bf(o[mf][nf][0] * i0, h0, l0);
            split_bf(o[mf][nf][1] * i0, h1, l1);
            st_bf2(&Ch[base], h0, h1);
            st_bf2(&Cl[base], l0, l1);
            split_bf(o[mf][nf][2] * i1, h0, l0);
            split_bf(o[mf][nf][3] * i1, h1, l1);
            st_bf2(&Ch[base + 8 * 512], h0, h1);
            st_bf2(&Cl[base + 8 * 512], l0, l1);
        }
    }
}

// ---------------- launcher ----------------------------------------------------
extern "C" void kernel_launch(void* const* d_in, const int* in_sizes, int n_in,
                              void* d_out, int out_size) {
    const float* query = (const float*)d_in[0];
    const float* key = (const float*)d_in[1];
    const float* value = (const float*)d_in[2];
    const float* pos = (const float*)d_in[3];
    const float* Wq = (const float*)d_in[4];
    const float* Wk = (const float*)d_in[5];
    const float* Wv = (const float*)d_in[6];
    const float* Wo = (const float*)d_in[7];
    float* out = (float*)d_out;

    __nv_bfloat16 *qh, *ql, *kh, *kl, *vh, *vl;
    __nv_bfloat16 *xqh, *xql, *xkh, *xkl, *xvh, *xvl;
    __nv_bfloat16 *wqth, *wqtl, *wkth, *wktl, *wvth, *wvtl, *woth, *wotl;
    __nv_bfloat16 *ch, *cl;
    cudaGetSymbolAddress((void**)&qh, g_Qh);
    cudaGetSymbolAddress((void**)&ql, g_Ql);
    cudaGetSymbolAddress((void**)&kh, g_Kh);
    cudaGetSymbolAddress((void**)&kl, g_Kl);
    cudaGetSymbolAddress((void**)&vh, g_Vh);
    cudaGetSymbolAddress((void**)&vl, g_Vl);
    cudaGetSymbolAddress((void**)&xqh, g_Xqh);
    cudaGetSymbolAddress((void**)&xql, g_Xql);
    cudaGetSymbolAddress((void**)&xkh, g_Xkh);
    cudaGetSymbolAddress((void**)&xkl, g_Xkl);
    cudaGetSymbolAddress((void**)&xvh, g_Xvh);
    cudaGetSymbolAddress((void**)&xvl, g_Xvl);
    cudaGetSymbolAddress((void**)&wqth, g_WqTh);
    cudaGetSymbolAddress((void**)&wqtl, g_WqTl);
    cudaGetSymbolAddress((void**)&wkth, g_WkTh);
    cudaGetSymbolAddress((void**)&wktl, g_WkTl);
    cudaGetSymbolAddress((void**)&wvth, g_WvTh);
    cudaGetSymbolAddress((void**)&wvtl, g_WvTl);
    cudaGetSymbolAddress((void**)&woth, g_WoTh);
    cudaGetSymbolAddress((void**)&wotl, g_WoTl);
    cudaGetSymbolAddress((void**)&ch, g_Ch);
    cudaGetSymbolAddress((void**)&cl, g_Cl);

    // splits
    split_x<<<4096, 256>>>(query, xqh, xql, 1048576);
    split_x<<<8192, 256>>>(key, xkh, xkl, 2097152);
    split_x<<<8192, 256>>>(value, xvh, xvl, 2097152);
    split_wT<<<dim3(16, 16), dim3(32, 8)>>>(Wq, wqth, wqtl);
    split_wT<<<dim3(16, 16), dim3(32, 8)>>>(Wk, wkth, wktl);
    split_wT<<<dim3(16, 16), dim3(32, 8)>>>(Wv, wvth, wvtl);
    split_wT<<<dim3(16, 16), dim3(32, 8)>>>(Wo, woth, wotl);

    // projections
    const int gsm = 2 * 4 * TSZ * 2;  // 81920 bytes
    cudaFuncSetAttribute(gemm_ps<1>, cudaFuncAttributeMaxDynamicSharedMemorySize,
                         gsm);
    cudaFuncSetAttribute(gemm_ps<0>, cudaFuncAttributeMaxDynamicSharedMemorySize,
                         gsm);
    gemm_ps<1><<<dim3(64, 4), 256, gsm>>>(xqh, xql, wqth, wqtl, nullptr, qh, ql,
                                          1024);
    gemm_ps<1><<<dim3(128, 4), 256, gsm>>>(xkh, xkl, wkth, wktl, nullptr, kh, kl,
                                           2048);
    gemm_ps<1><<<dim3(128, 4), 256, gsm>>>(xvh, xvl, wvth, wvtl, nullptr, vh, vl,
                                           2048);

    // attention (round-4 layout)
    const int smem_bytes =
        (2 * 64 * 72 + 2 * 192 * 72 + 128 * 66 + 2 * 64 * 200 + 2 * 64 * 200) * 2 +
        (64 * 132 + 256 + 256 + 64 + 64) * 4;
    cudaFuncSetAttribute(attn_tc6, cudaFuncAttributeMaxDynamicSharedMemorySize,
                         smem_bytes);
    attn_tc6<<<dim3(16, 64), 256, smem_bytes>>>(qh, ql, kh, kl, vh, vl, pos, ch,
                                                cl);

    // output projection
    gemm_ps<0><<<dim3(64, 4), 256, gsm>>>(ch, cl, woth, wotl, out, nullptr,
                                          nullptr, 1024);
}

// round 9
// speedup vs baseline: 1.7576x; 1.1469x over previous
#include <cuda_runtime.h>
#include <cuda_bf16.h>
#include <stdint.h>
#include <math.h>

// B=8, M=1024, H=512, K=8 heads, D=64, SPAN=1024, MK=2048
#define DINLINE __device__ __forceinline__

// ---------------- scratch ----------------------------------------------------
__device__ __align__(16) __nv_bfloat16 g_Qh[64 * 1024 * 64];
__device__ __align__(16) __nv_bfloat16 g_Ql[64 * 1024 * 64];
__device__ __align__(16) __nv_bfloat16 g_Kh[64 * 2048 * 64];
__device__ __align__(16) __nv_bfloat16 g_Kl[64 * 2048 * 64];
__device__ __align__(16) __nv_bfloat16 g_Vh[64 * 2048 * 64];
__device__ __align__(16) __nv_bfloat16 g_Vl[64 * 2048 * 64];
__device__ __align__(16) __nv_bfloat16 g_Vth[64 * 64 * 2048];  // V^T [n][d][t]
__device__ __align__(16) __nv_bfloat16 g_Vtl[64 * 64 * 2048];
__device__ __align__(16) __nv_bfloat16 g_Et[1024 * 64];        // E^T [s][d] hi
__device__ __align__(16) __nv_bfloat16 g_Xqh[8 * 1024 * 512], g_Xql[8 * 1024 * 512];
__device__ __align__(16) __nv_bfloat16 g_Xkh[8 * 2048 * 512], g_Xkl[8 * 2048 * 512];
__device__ __align__(16) __nv_bfloat16 g_Xvh[8 * 2048 * 512], g_Xvl[8 * 2048 * 512];
__device__ __align__(16) __nv_bfloat16 g_WqTh[512 * 512], g_WqTl[512 * 512];
__device__ __align__(16) __nv_bfloat16 g_WkTh[512 * 512], g_WkTl[512 * 512];
__device__ __align__(16) __nv_bfloat16 g_WvTh[512 * 512], g_WvTl[512 * 512];
__device__ __align__(16) __nv_bfloat16 g_WoTh[512 * 512], g_WoTl[512 * 512];
__device__ __align__(16) __nv_bfloat16 g_Ch[8 * 1024 * 512], g_Cl[8 * 1024 * 512];

// ---------------- helpers ----------------------------------------------------
DINLINE void mma_bf16(float c[4], uint32_t a0, uint32_t a1, uint32_t a2,
                      uint32_t a3, uint32_t b0, uint32_t b1) {
    asm volatile(
        "mma.sync.aligned.m16n8k16.row.col.f32.bf16.bf16.f32 "
        "{%0,%1,%2,%3}, {%4,%5,%6,%7}, {%8,%9}, {%0,%1,%2,%3};\n"
        : "+f"(c[0]), "+f"(c[1]), "+f"(c[2]), "+f"(c[3])
        : "r"(a0), "r"(a1), "r"(a2), "r"(a3), "r"(b0), "r"(b1));
}

DINLINE uint32_t smem_u32(const void* p) {
    return (uint32_t)__cvta_generic_to_shared(p);
}

DINLINE void cp16(uint32_t dst, const void* src) {
    asm volatile("cp.async.cg.shared.global [%0], [%1], 16;\n" ::"r"(dst),
                 "l"(src));
}
DINLINE void cp_commit() { asm volatile("cp.async.commit_group;\n" ::); }
template <int N>
DINLINE void cp_wait() {
    asm volatile("cp.async.wait_group %0;\n" ::"n"(N));
}

DINLINE void split_bf(float x, __nv_bfloat16& h, __nv_bfloat16& l) {
    h = __float2bfloat16_rn(x);
    l = __float2bfloat16_rn(x - __bfloat162float(h));
}

DINLINE void st_bf2(__nv_bfloat16* p, __nv_bfloat16 a, __nv_bfloat16 b) {
    __nv_bfloat162 t;
    t.x = a;
    t.y = b;
    *(__nv_bfloat162*)p = t;
}

// ---------------- split / transpose kernels ------------------------------------
__global__ void __launch_bounds__(256) split_x(const float* __restrict__ in,
                                               __nv_bfloat16* __restrict__ h,
                                               __nv_bfloat16* __restrict__ l,
                                               int n4) {
    int i = blockIdx.x * blockDim.x + threadIdx.x;
    if (i >= n4) return;
    float4 v = ((const float4*)in)[i];
    __nv_bfloat16 h0, l0, h1, l1, h2, l2, h3, l3;
    split_bf(v.x, h0, l0);
    split_bf(v.y, h1, l1);
    split_bf(v.z, h2, l2);
    split_bf(v.w, h3, l3);
    st_bf2(h + (size_t)i * 4, h0, h1);
    st_bf2(h + (size_t)i * 4 + 2, h2, h3);
    st_bf2(l + (size_t)i * 4, l0, l1);
    st_bf2(l + (size_t)i * 4 + 2, l2, l3);
}

// W[k][n] (512x512) -> T[n][k] split hi/lo
__global__ void __launch_bounds__(256) split_wT(const float* __restrict__ W,
                                                __nv_bfloat16* __restrict__ Th,
                                                __nv_bfloat16* __restrict__ Tl) {
    __shared__ float tile[32][33];
    int tx = threadIdx.x & 31, ty = threadIdx.x >> 5;  // 32 x 8
    int n0 = blockIdx.x * 32, k0 = blockIdx.y * 32;
#pragma unroll
    for (int i = 0; i < 4; i++)
        tile[ty + i * 8][tx] = W[(size_t)(k0 + ty + i * 8) * 512 + n0 + tx];
    __syncthreads();
#pragma unroll
    for (int i = 0; i < 4; i++) {
        float v = tile[tx][ty + i * 8];
        __nv_bfloat16 h, l;
        split_bf(v, h, l);
        Th[(size_t)(n0 + ty + i * 8) * 512 + k0 + tx] = h;
        Tl[(size_t)(n0 + ty + i * 8) * 512 + k0 + tx] = l;
    }
}

// V [n][t][d] bf16 -> V^T [n][d][t]
__global__ void __launch_bounds__(256) transpose_v(
    const __nv_bfloat16* __restrict__ in, __nv_bfloat16* __restrict__ out) {
    __shared__ __nv_bfloat16 tile[32][33];
    int tx = threadIdx.x & 31, ty = threadIdx.x >> 5;  // 32 x 8
    int n = blockIdx.z;
    int t0 = blockIdx.x * 32, d0 = blockIdx.y * 32;
    const __nv_bfloat16* src = in + ((size_t)n * 2048 + t0) * 64 + d0;
#pragma unroll
    for (int i = 0; i < 4; i++)
        tile[ty + i * 8][tx] = src[(size_t)(ty + i * 8) * 64 + tx];
    __syncthreads();
    __nv_bfloat16* dst = out + ((size_t)n * 64 + d0) * 2048 + t0;
#pragma unroll
    for (int i = 0; i < 4; i++)
        dst[(size_t)(ty + i * 8) * 2048 + tx] = tile[tx][ty + i * 8];
}

// E fp32 [d=64][s=1024] -> E^T bf16 [s][d]
__global__ void __launch_bounds__(256) conv_eT(const float* __restrict__ E,
                                               __nv_bfloat16* __restrict__ Et) {
    __shared__ float tile[32][33];
    int tx = threadIdx.x & 31, ty = threadIdx.x >> 5;
    int s0 = blockIdx.x * 32, d0 = blockIdx.y * 32;
#pragma unroll
    for (int i = 0; i < 4; i++)
        tile[ty + i * 8][tx] = E[(size_t)(d0 + ty + i * 8) * 1024 + s0 + tx];
    __syncthreads();
#pragma unroll
    for (int i = 0; i < 4; i++)
        Et[(size_t)(s0 + ty + i * 8) * 64 + d0 + tx] =
            __float2bfloat16_rn(tile[tx][ty + i * 8]);
}

// ---------------- pre-split bf16x3 GEMM with cp.async double buffer -----------
constexpr int AS2 = 40;
constexpr int TSZ = 128 * AS2;

template <int EPI>
__global__ void __launch_bounds__(256, 1) gemm_ps(
    const __nv_bfloat16* __restrict__ Ah_g, const __nv_bfloat16* __restrict__ Al_g,
    const __nv_bfloat16* __restrict__ Th_g, const __nv_bfloat16* __restrict__ Tl_g,
    float* __restrict__ outF, __nv_bfloat16* __restrict__ outH,
    __nv_bfloat16* __restrict__ outL, int T) {
    extern __shared__ __nv_bfloat16 smg[];

    const int tid = threadIdx.x;
    const int lane = tid & 31, wid = tid >> 5;
    const int wm = wid >> 2, wn = wid & 3;  // 2 x 4 warps
    const int row0 = blockIdx.x * 128, col0 = blockIdx.y * 128;
    const int g = lane >> 2, t2 = (lane & 3) * 2;

    const int lr = tid >> 2;
    const int lc = (tid & 3) * 8;

    float acc[4][4][4] = {};

    {
        __nv_bfloat16* Ah = smg;
        __nv_bfloat16* Al = Ah + TSZ;
        __nv_bfloat16* Bh = Al + TSZ;
        __nv_bfloat16* Bl = Bh + TSZ;
#pragma unroll
        for (int half = 0; half < 2; half++) {
            int r = lr + half * 64;
            cp16(smem_u32(Ah + r * AS2 + lc), Ah_g + (size_t)(row0 + r) * 512 + lc);
            cp16(smem_u32(Al + r * AS2 + lc), Al_g + (size_t)(row0 + r) * 512 + lc);
            cp16(smem_u32(Bh + r * AS2 + lc), Th_g + (size_t)(col0 + r) * 512 + lc);
            cp16(smem_u32(Bl + r * AS2 + lc), Tl_g + (size_t)(col0 + r) * 512 + lc);
        }
        cp_commit();
    }

    int buf = 0;
    for (int kk = 0; kk < 512; kk += 32) {
        if (kk + 32 < 512) {
            __nv_bfloat16* Ah = smg + (buf ^ 1) * 4 * TSZ;
            __nv_bfloat16* Al = Ah + TSZ;
            __nv_bfloat16* Bh = Al + TSZ;
            __nv_bfloat16* Bl = Bh + TSZ;
            int kn = kk + 32;
#pragma unroll
            for (int half = 0; half < 2; half++) {
                int r = lr + half * 64;
                cp16(smem_u32(Ah + r * AS2 + lc),
                     Ah_g + (size_t)(row0 + r) * 512 + kn + lc);
                cp16(smem_u32(Al + r * AS2 + lc),
                     Al_g + (size_t)(row0 + r) * 512 + kn + lc);
                cp16(smem_u32(Bh + r * AS2 + lc),
                     Th_g + (size_t)(col0 + r) * 512 + kn + lc);
                cp16(smem_u32(Bl + r * AS2 + lc),
                     Tl_g + (size_t)(col0 + r) * 512 + kn + lc);
            }
            cp_commit();
            cp_wait<1>();
        } else {
            cp_wait<0>();
        }
        __syncthreads();

        const __nv_bfloat16* Ah = smg + buf * 4 * TSZ;
        const __nv_bfloat16* Al = Ah + TSZ;
        const __nv_bfloat16* Bh = Al + TSZ;
        const __nv_bfloat16* Bl = Bh + TSZ;
#pragma unroll
        for (int ks = 0; ks < 32; ks += 16) {
            uint32_t ah[4][4], al[4][4], bh[4][2], bl[4][2];
#pragma unroll
            for (int mf = 0; mf < 4; mf++) {
                int rb = wm * 64 + mf * 16 + g;
                ah[mf][0] = *(uint32_t*)&Ah[rb * AS2 + ks + t2];
                ah[mf][1] = *(uint32_t*)&Ah[(rb + 8) * AS2 + ks + t2];
                ah[mf][2] = *(uint32_t*)&Ah[rb * AS2 + ks + 8 + t2];
                ah[mf][3] = *(uint32_t*)&Ah[(rb + 8) * AS2 + ks + 8 + t2];
                al[mf][0] = *(uint32_t*)&Al[rb * AS2 + ks + t2];
                al[mf][1] = *(uint32_t*)&Al[(rb + 8) * AS2 + ks + t2];
                al[mf][2] = *(uint32_t*)&Al[rb * AS2 + ks + 8 + t2];
                al[mf][3] = *(uint32_t*)&Al[(rb + 8) * AS2 + ks + 8 + t2];
            }
#pragma unroll
            for (int nf = 0; nf < 4; nf++) {
                int cb = wn * 32 + nf * 8 + g;
                bh[nf][0] = *(uint32_t*)&Bh[cb * AS2 + ks + t2];
                bh[nf][1] = *(uint32_t*)&Bh[cb * AS2 + ks + 8 + t2];
                bl[nf][0] = *(uint32_t*)&Bl[cb * AS2 + ks + t2];
                bl[nf][1] = *(uint32_t*)&Bl[cb * AS2 + ks + 8 + t2];
            }
#pragma unroll
            for (int mf = 0; mf < 4; mf++)
#pragma unroll
                for (int nf = 0; nf < 4; nf++) {
                    mma_bf16(acc[mf][nf], ah[mf][0], ah[mf][1], ah[mf][2],
                             ah[mf][3], bh[nf][0], bh[nf][1]);
                    mma_bf16(acc[mf][nf], ah[mf][0], ah[mf][1], ah[mf][2],
                             ah[mf][3], bl[nf][0], bl[nf][1]);
                    mma_bf16(acc[mf][nf], al[mf][0], al[mf][1], al[mf][2],
                             al[mf][3], bh[nf][0], bh[nf][1]);
                }
        }
        __syncthreads();
        buf ^= 1;
    }

#pragma unroll
    for (int mf = 0; mf < 4; mf++) {
#pragma unroll
        for (int nf = 0; nf < 4; nf++) {
            int rr = row0 + wm * 64 + mf * 16 + g;
            int cc = col0 + wn * 32 + nf * 8 + t2;
            if (EPI == 0) {
                *(float2*)&outF[(size_t)rr * 512 + cc] =
                    make_float2(acc[mf][nf][0], acc[mf][nf][1]);
                *(float2*)&outF[(size_t)(rr + 8) * 512 + cc] =
                    make_float2(acc[mf][nf][2], acc[mf][nf][3]);
            } else {
                int head = cc >> 6, d = cc & 63;
#pragma unroll
                for (int rh = 0; rh < 2; rh++) {
                    int grow = rr + rh * 8;
                    int b = grow / T, t = grow - b * T;
                    size_t idx = (((size_t)(b * 8 + head) * T + t) << 6) + d;
                    __nv_bfloat16 h0, l0, h1, l1;
                    split_bf(acc[mf][nf][rh * 2 + 0], h0, l0);
                    split_bf(acc[mf][nf][rh * 2 + 1], h1, l1);
                    st_bf2(&outH[idx], h0, h1);
                    st_bf2(&outL[idx], l0, l1);
                }
            }
        }
    }
}

// ---------------- fused banded attention v7 (pipelined cp.async staging) ------
__global__ void __launch_bounds__(256, 1) attn_tc7(
    const __nv_bfloat16* __restrict__ Qh, const __nv_bfloat16* __restrict__ Ql,
    const __nv_bfloat16* __restrict__ Kh_, const __nv_bfloat16* __restrict__ Kl_,
    const __nv_bfloat16* __restrict__ Vth, const __nv_bfloat16* __restrict__ Vtl,
    const __nv_bfloat16* __restrict__ Et, __nv_bfloat16* __restrict__ Ch,
    __nv_bfloat16* __restrict__ Cl) {
    constexpr int QS = 72, KS = 72, ES = 72, VS = 200, PS = 200, QES = 132;
    extern __shared__ char smraw[];
    __nv_bfloat16* Qsh = (__nv_bfloat16*)smraw;  // [64][QS]
    __nv_bfloat16* Qsl = Qsh + 64 * QS;
    __nv_bfloat16* Ksh = Qsl + 64 * QS;          // [192][KS]
    __nv_bfloat16* Ksl = Ksh + 192 * KS;
    __nv_bfloat16* Esh = Ksl + 192 * KS;         // [s=128][ES] hi only
    __nv_bfloat16* Vsh = Esh + 128 * ES;         // [d=64][VS]
    __nv_bfloat16* Vsl = Vsh + 64 * VS;
    __nv_bfloat16* Psh = Vsl + 64 * VS;          // [m=64][PS]
    __nv_bfloat16* Psl = Psh + 64 * PS;
    float* QEs = (float*)(Psl + 64 * PS);        // [64][QES]
    float* redmax = QEs + 64 * QES;              // [4][64]
    float* redsum = redmax + 256;                // [4][64]
    float* mrow = redsum + 256;                  // [64]
    float* lrow = mrow + 64;                     // [64]

    const int tid = threadIdx.x, lane = tid & 31, wid = tid >> 5;
    const int wm = wid >> 2, wn = wid & 3;  // 2 x 4 warps
    const int g = lane >> 2, t2 = (lane & 3) * 2;
    const int n = blockIdx.y, m0 = blockIdx.x * 64;
    const float SCl2 = 0.125f * 1.4426950408889634f;

    // async issue helpers
    auto issue_KE = [&](int c) {
        const size_t kbase = ((size_t)n * 2048 + m0 + c * 128) << 6;
        const __nv_bfloat16* sh = Kh_ + kbase;
        const __nv_bfloat16* sl = Kl_ + kbase;
#pragma unroll
        for (int it = 0; it < 6; it++) {
            int f = tid + it * 256;
            int kr = f >> 3, j = (f & 7) * 8;
            cp16(smem_u32(Ksh + kr * KS + j), sh + f * 8);
            cp16(smem_u32(Ksl + kr * KS + j), sl + f * 8);
        }
        const __nv_bfloat16* es = Et + (size_t)(c * 128) * 64;
#pragma unroll
        for (int it = 0; it < 4; it++) {
            int f = tid + it * 256;
            int s = f >> 3, j = (f & 7) * 8;
            cp16(smem_u32(Esh + s * ES + j), es + f * 8);
        }
    };
    auto issue_V = [&](int c) {
        const __nv_bfloat16* vh = Vth + (size_t)n * 64 * 2048 + m0 + c * 128;
        const __nv_bfloat16* vl = Vtl + (size_t)n * 64 * 2048 + m0 + c * 128;
#pragma unroll
        for (int it = 0; it < 6; it++) {
            int f = tid + it * 256;
            int d = f / 24, j = f - d * 24;
            cp16(smem_u32(Vsh + d * VS + j * 8), vh + (size_t)d * 2048 + j * 8);
            cp16(smem_u32(Vsl + d * VS + j * 8), vl + (size_t)d * 2048 + j * 8);
        }
    };

    // stage Q tile
    {
        const uint4* sh = (const uint4*)(Qh + (((size_t)n * 1024 + m0) << 6));
        const uint4* sl = (const uint4*)(Ql + (((size_t)n * 1024 + m0) << 6));
#pragma unroll
        for (int it = 0; it < 2; it++) {
            int f = tid + it * 256;
            int m = f >> 3, j = f & 7;
            ((uint4*)(Qsh + m * QS))[j] = sh[f];
            ((uint4*)(Qsl + m * QS))[j] = sl[f];
        }
    }
    if (tid < 64) {
        mrow[tid] = -1e30f;
        lrow[tid] = 0.f;
    }

    issue_KE(0);
    cp_commit();
    issue_V(0);
    cp_commit();

    float o[2][2][4] = {};

    for (int c = 0; c < 8; c++) {
        cp_wait<1>();  // KE(c) complete; V(c) may still be in flight
        __syncthreads();

        // ---- QK (64x192 bf16x3) + QE (64x128 1-pass) ----
        float sAcc[2][6][4] = {};
        float qeAcc[2][4][4] = {};
#pragma unroll
        for (int ks = 0; ks < 64; ks += 16) {
            uint32_t ah[2][4], al[2][4];
#pragma unroll
            for (int mf = 0; mf < 2; mf++) {
                int rb = wm * 32 + mf * 16 + g;
                ah[mf][0] = *(uint32_t*)&Qsh[rb * QS + ks + t2];
                ah[mf][1] = *(uint32_t*)&Qsh[(rb + 8) * QS + ks + t2];
                ah[mf][2] = *(uint32_t*)&Qsh[rb * QS + ks + 8 + t2];
                ah[mf][3] = *(uint32_t*)&Qsh[(rb + 8) * QS + ks + 8 + t2];
                al[mf][0] = *(uint32_t*)&Qsl[rb * QS + ks + t2];
                al[mf][1] = *(uint32_t*)&Qsl[(rb + 8) * QS + ks + t2];
                al[mf][2] = *(uint32_t*)&Qsl[rb * QS + ks + 8 + t2];
                al[mf][3] = *(uint32_t*)&Qsl[(rb + 8) * QS + ks + 8 + t2];
            }
#pragma unroll
            for (int nf = 0; nf < 6; nf++) {
                int cb = wn * 48 + nf * 8 + g;
                uint32_t kb0 = *(uint32_t*)&Ksh[cb * KS + ks + t2];
                uint32_t kb1 = *(uint32_t*)&Ksh[cb * KS + ks + 8 + t2];
                uint32_t kl0 = *(uint32_t*)&Ksl[cb * KS + ks + t2];
                uint32_t kl1 = *(uint32_t*)&Ksl[cb * KS + ks + 8 + t2];
#pragma unroll
                for (int mf = 0; mf < 2; mf++) {
                    mma_bf16(sAcc[mf][nf], ah[mf][0], ah[mf][1], ah[mf][2],
                             ah[mf][3], kb0, kb1);
                    mma_bf16(sAcc[mf][nf], ah[mf][0], ah[mf][1], ah[mf][2],
                             ah[mf][3], kl0, kl1);
                    mma_bf16(sAcc[mf][nf], al[mf][0], al[mf][1], al[mf][2],
                             al[mf][3], kb0, kb1);
                }
            }
#pragma unroll
            for (int nf = 0; nf < 4; nf++) {
                int cb = wn * 32 + nf * 8 + g;
                uint32_t eb0 = *(uint32_t*)&Esh[cb * ES + ks + t2];
                uint32_t eb1 = *(uint32_t*)&Esh[cb * ES + ks + 8 + t2];
#pragma unroll
                for (int mf = 0; mf < 2; mf++)
                    mma_bf16(qeAcc[mf][nf], ah[mf][0], ah[mf][1], ah[mf][2],
                             ah[mf][3], eb0, eb1);
            }
        }
        // stage QE fragments (diagonal gather needs smem)
#pragma unroll
        for (int mf = 0; mf < 2; mf++) {
            int R = wm * 32 + mf * 16 + g;
#pragma unroll
            for (int nf = 0; nf < 4; nf++) {
                int cc = wn * 32 + nf * 8 + t2;
                *(float2*)&QEs[R * QES + cc] =
                    make_float2(qeAcc[mf][nf][0], qeAcc[mf][nf][1]);
                *(float2*)&QEs[(R + 8) * QES + cc] =
                    make_float2(qeAcc[mf][nf][2], qeAcc[mf][nf][3]);
            }
        }
        __syncthreads();

        // K/E smem now dead for this chunk -> prefetch next chunk's K/E
        if (c < 7) issue_KE(c + 1);
        cp_commit();

        // ---- phase 1: masked z = S + QE, per-warp row-max partials ----
#pragma unroll
        for (int mf = 0; mf < 2; mf++) {
            int R = wm * 32 + mf * 16 + g;
            float mx0 = -3e38f, mx1 = -3e38f;
#pragma unroll
            for (int nf = 0; nf < 6; nf++) {
                int cc = wn * 48 + nf * 8 + t2;
#pragma unroll
                for (int e = 0; e < 4; e++) {
                    int r = R + ((e >> 1) << 3);
                    int col = cc + (e & 1);
                    int diff = col - r;
                    float z = -3e38f;
                    if ((unsigned)diff < 128u)
                        z = sAcc[mf][nf][e] + QEs[r * QES + diff];
                    sAcc[mf][nf][e] = z;
                    if (e < 2) mx0 = fmaxf(mx0, z);
                    else mx1 = fmaxf(mx1, z);
                }
            }
            mx0 = fmaxf(mx0, __shfl_xor_sync(0xffffffffu, mx0, 1));
            mx0 = fmaxf(mx0, __shfl_xor_sync(0xffffffffu, mx0, 2));
            mx1 = fmaxf(mx1, __shfl_xor_sync(0xffffffffu, mx1, 1));
            mx1 = fmaxf(mx1, __shfl_xor_sync(0xffffffffu, mx1, 2));
            if ((lane & 3) == 0) {
                redmax[wn * 64 + R] = mx0;
                redmax[wn * 64 + R + 8] = mx1;
            }
        }
        __syncthreads();

        // ---- phase 2: exp, P store, sums, O rescale ----
        float mn[2][2], alpha[2][2];
#pragma unroll
        for (int mf = 0; mf < 2; mf++) {
            int R = wm * 32 + mf * 16 + g;
#pragma unroll
            for (int h = 0; h < 2; h++) {
                int r = R + h * 8;
                float rm = fmaxf(fmaxf(redmax[r], redmax[64 + r]),
                                 fmaxf(redmax[128 + r], redmax[192 + r]));
                float mo = mrow[r];
                float m2 = fmaxf(mo, rm * SCl2);
                mn[mf][h] = m2;
                alpha[mf][h] = exp2f(mo - m2);
            }
        }
#pragma unroll
        for (int mf = 0; mf < 2; mf++) {
            int R = wm * 32 + mf * 16 + g;
            float sum0 = 0.f, sum1 = 0.f;
#pragma unroll
            for (int nf = 0; nf < 6; nf++) {
                int cc = wn * 48 + nf * 8 + t2;
                float p[4];
#pragma unroll
                for (int e = 0; e < 4; e++) {
                    int r = R + ((e >> 1) << 3);
                    int col = cc + (e & 1);
                    int diff = col - r;
                    float pv = 0.f;
                    if ((unsigned)diff < 128u)
                        pv = exp2f(sAcc[mf][nf][e] * SCl2 - mn[mf][e >> 1]);
                    p[e] = pv;
                    if (e < 2) sum0 += pv;
                    else sum1 += pv;
                }
                __nv_bfloat16 h0, l0, h1, l1;
                split_bf(p[0], h0, l0);
                split_bf(p[1], h1, l1);
                st_bf2(&Psh[R * PS + cc], h0, h1);
                st_bf2(&Psl[R * PS + cc], l0, l1);
                split_bf(p[2], h0, l0);
                split_bf(p[3], h1, l1);
                st_bf2(&Psh[(R + 8) * PS + cc], h0, h1);
                st_bf2(&Psl[(R + 8) * PS + cc], l0, l1);
            }
            sum0 += __shfl_xor_sync(0xffffffffu, sum0, 1);
            sum0 += __shfl_xor_sync(0xffffffffu, sum0, 2);
            sum1 += __shfl_xor_sync(0xffffffffu, sum1, 1);
            sum1 += __shfl_xor_sync(0xffffffffu, sum1, 2);
            if ((lane & 3) == 0) {
                redsum[wn * 64 + R] = sum0;
                redsum[wn * 64 + R + 8] = sum1;
            }
#pragma unroll
            for (int nf = 0; nf < 2; nf++) {
                o[mf][nf][0] *= alpha[mf][0];
                o[mf][nf][1] *= alpha[mf][0];
                o[mf][nf][2] *= alpha[mf][1];
                o[mf][nf][3] *= alpha[mf][1];
            }
        }
        cp_wait<1>();  // V(c) complete (KE(c+1) may still be in flight)
        __syncthreads();

        // state update (one writer per row)
        if (wn == 0 && (lane & 3) == 0) {
#pragma unroll
            for (int mf = 0; mf < 2; mf++) {
                int R = wm * 32 + mf * 16 + g;
#pragma unroll
                for (int h = 0; h < 2; h++) {
                    int r = R + h * 8;
                    float s = redsum[r] + redsum[64 + r] + redsum[128 + r] +
                              redsum[192 + r];
                    lrow[r] = lrow[r] * alpha[mf][h] + s;
                    mrow[r] = mn[mf][h];
                }
            }
        }

        // ---- PV: O += P(64x192) @ V^T (full bf16x3) ----
#pragma unroll
        for (int ks = 0; ks < 192; ks += 16) {
            uint32_t ph[2][4], pl[2][4];
#pragma unroll
            for (int mf = 0; mf < 2; mf++) {
                int rb = wm * 32 + mf * 16 + g;
                ph[mf][0] = *(uint32_t*)&Psh[rb * PS + ks + t2];
                ph[mf][1] = *(uint32_t*)&Psh[(rb + 8) * PS + ks + t2];
                ph[mf][2] = *(uint32_t*)&Psh[rb * PS + ks + 8 + t2];
                ph[mf][3] = *(uint32_t*)&Psh[(rb + 8) * PS + ks + 8 + t2];
                pl[mf][0] = *(uint32_t*)&Psl[rb * PS + ks + t2];
                pl[mf][1] = *(uint32_t*)&Psl[(rb + 8) * PS + ks + t2];
                pl[mf][2] = *(uint32_t*)&Psl[rb * PS + ks + 8 + t2];
                pl[mf][3] = *(uint32_t*)&Psl[(rb + 8) * PS + ks + 8 + t2];
            }
#pragma unroll
            for (int nf = 0; nf < 2; nf++) {
                int cb = wn * 16 + nf * 8 + g;
                uint32_t vh0 = *(uint32_t*)&Vsh[cb * VS + ks + t2];
                uint32_t vh1 = *(uint32_t*)&Vsh[cb * VS + ks + 8 + t2];
                uint32_t vl0 = *(uint32_t*)&Vsl[cb * VS + ks + t2];
                uint32_t vl1 = *(uint32_t*)&Vsl[cb * VS + ks + 8 + t2];
#pragma unroll
                for (int mf = 0; mf < 2; mf++) {
                    mma_bf16(o[mf][nf], ph[mf][0], ph[mf][1], ph[mf][2],
                             ph[mf][3], vh0, vh1);
                    mma_bf16(o[mf][nf], ph[mf][0], ph[mf][1], ph[mf][2],
                             ph[mf][3], vl0, vl1);
                    mma_bf16(o[mf][nf], pl[mf][0], pl[mf][1], pl[mf][2],
                             pl[mf][3], vh0, vh1);
                }
            }
        }
        __syncthreads();  // PV reads done before overwriting V

        if (c < 7) issue_V(c + 1);
        cp_commit();
    }

    // epilogue: normalize, write context pre-split bf16 hi/lo in [B,M,H]
    const int b = n >> 3, kh = n & 7;
#pragma unroll
    for (int mf = 0; mf < 2; mf++) {
        int r = wm * 32 + mf * 16 + g;
        float i0 = 1.0f / lrow[r];
        float i1 = 1.0f / lrow[r + 8];
#pragma unroll
        for (int nf = 0; nf < 2; nf++) {
            int cc = kh * 64 + wn * 16 + nf * 8 + t2;
            size_t base = ((size_t)b * 1024 + m0 + r) * 512 + cc;
            __nv_bfloat16 h0, l0, h1, l1;
            split_bf(o[mf][nf][0] * i0, h0, l0);
            split_bf(o[mf][nf][1] * i0, h1, l1);
            st_bf2(&Ch[base], h0, h1);
            st_bf2(&Cl[base], l0, l1);
            split_bf(o[mf][nf][2] * i1, h0, l0);
            split_bf(o[mf][nf][3] * i1, h1, l1);
            st_bf2(&Ch[base + 8 * 512], h0, h1);
            st_bf2(&Cl[base + 8 * 512], l0, l1);
        }
    }
}

// ---------------- launcher ----------------------------------------------------
extern "C" void kernel_launch(void* const* d_in, const int* in_sizes, int n_in,
                              void* d_out, int out_size) {
    const float* query = (const float*)d_in[0];
    const float* key = (const float*)d_in[1];
    const float* value = (const float*)d_in[2];
    const float* pos = (const float*)d_in[3];
    const float* Wq = (const float*)d_in[4];
    const float* Wk = (const float*)d_in[5];
    const float* Wv = (const float*)d_in[6];
    const float* Wo = (const float*)d_in[7];
    float* out = (float*)d_out;

    __nv_bfloat16 *qh, *ql, *kh, *kl, *vh, *vl, *vth, *vtl, *et;
    __nv_bfloat16 *xqh, *xql, *xkh, *xkl, *xvh, *xvl;
    __nv_bfloat16 *wqth, *wqtl, *wkth, *wktl, *wvth, *wvtl, *woth, *wotl;
    __nv_bfloat16 *ch, *cl;
    cudaGetSymbolAddress((void**)&qh, g_Qh);
    cudaGetSymbolAddress((void**)&ql, g_Ql);
    cudaGetSymbolAddress((void**)&kh, g_Kh);
    cudaGetSymbolAddress((void**)&kl, g_Kl);
    cudaGetSymbolAddress((void**)&vh, g_Vh);
    cudaGetSymbolAddress((void**)&vl, g_Vl);
    cudaGetSymbolAddress((void**)&vth, g_Vth);
    cudaGetSymbolAddress((void**)&vtl, g_Vtl);
    cudaGetSymbolAddress((void**)&et, g_Et);
    cudaGetSymbolAddress((void**)&xqh, g_Xqh);
    cudaGetSymbolAddress((void**)&xql, g_Xql);
    cudaGetSymbolAddress((void**)&xkh, g_Xkh);
    cudaGetSymbolAddress((void**)&xkl, g_Xkl);
    cudaGetSymbolAddress((void**)&xvh, g_Xvh);
    cudaGetSymbolAddress((void**)&xvl, g_Xvl);
    cudaGetSymbolAddress((void**)&wqth, g_WqTh);
    cudaGetSymbolAddress((void**)&wqtl, g_WqTl);
    cudaGetSymbolAddress((void**)&wkth, g_WkTh);
    cudaGetSymbolAddress((void**)&wktl, g_WkTl);
    cudaGetSymbolAddress((void**)&wvth, g_WvTh);
    cudaGetSymbolAddress((void**)&wvtl, g_WvTl);
    cudaGetSymbolAddress((void**)&woth, g_WoTh);
    cudaGetSymbolAddress((void**)&wotl, g_WoTl);
    cudaGetSymbolAddress((void**)&ch, g_Ch);
    cudaGetSymbolAddress((void**)&cl, g_Cl);

    // splits / transposes of inputs
    split_x<<<4096, 256>>>(query, xqh, xql, 1048576);
    split_x<<<8192, 256>>>(key, xkh, xkl, 2097152);
    split_x<<<8192, 256>>>(value, xvh, xvl, 2097152);
    split_wT<<<dim3(16, 16), dim3(256)>>>(Wq, wqth, wqtl);
    split_wT<<<dim3(16, 16), dim3(256)>>>(Wk, wkth, wktl);
    split_wT<<<dim3(16, 16), dim3(256)>>>(Wv, wvth, wvtl);
    split_wT<<<dim3(16, 16), dim3(256)>>>(Wo, woth, wotl);
    conv_eT<<<dim3(32, 2), 256>>>(pos, et);

    // projections
    const int gsm = 2 * 4 * TSZ * 2;  // 81920 bytes
    cudaFuncSetAttribute(gemm_ps<1>, cudaFuncAttributeMaxDynamicSharedMemorySize,
                         gsm);
    cudaFuncSetAttribute(gemm_ps<0>, cudaFuncAttributeMaxDynamicSharedMemorySize,
                         gsm);
    gemm_ps<1><<<dim3(64, 4), 256, gsm>>>(xqh, xql, wqth, wqtl, nullptr, qh, ql,
                                          1024);
    gemm_ps<1><<<dim3(128, 4), 256, gsm>>>(xkh, xkl, wkth, wktl, nullptr, kh, kl,
                                           2048);
    gemm_ps<1><<<dim3(128, 4), 256, gsm>>>(xvh, xvl, wvth, wvtl, nullptr, vh, vl,
                                           2048);

    // V transpose to [n][d][t]
    transpose_v<<<dim3(64, 2, 64), 256>>>(vh, vth);
    transpose_v<<<dim3(64, 2, 64), 256>>>(vl, vtl);

    // attention (pipelined)
    const int smem_bytes =
        (2 * 64 * 72 + 2 * 192 * 72 + 128 * 72 + 2 * 64 * 200 + 2 * 64 * 200) * 2 +
        (64 * 132 + 256 + 256 + 64 + 64) * 4;  // 230912
    cudaFuncSetAttribute(attn_tc7, cudaFuncAttributeMaxDynamicSharedMemorySize,
                         smem_bytes);
    attn_tc7<<<dim3(16, 64), 256, smem_bytes>>>(qh, ql, kh, kl, vth, vtl, et, ch,
                                                cl);

    // output projection
    gemm_ps<0><<<dim3(64, 4), 256, gsm>>>(ch, cl, woth, wotl, out, nullptr,
                                          nullptr, 1024);
}

// round 10
// speedup vs baseline: 1.7672x; 1.0054x over previous
#include <cuda_runtime.h>
#include <cuda_bf16.h>
#include <stdint.h>
#include <math.h>

// B=8, M=1024, H=512, K=8 heads, D=64, SPAN=1024, MK=2048
#define DINLINE __device__ __forceinline__

// ---------------- scratch ----------------------------------------------------
__device__ __align__(16) __nv_bfloat16 g_Qh[64 * 1024 * 64];
__device__ __align__(16) __nv_bfloat16 g_Ql[64 * 1024 * 64];
__device__ __align__(16) __nv_bfloat16 g_Kh[64 * 2048 * 64];
__device__ __align__(16) __nv_bfloat16 g_Kl[64 * 2048 * 64];
__device__ __align__(16) __nv_bfloat16 g_Vh[64 * 2048 * 64];
__device__ __align__(16) __nv_bfloat16 g_Vl[64 * 2048 * 64];
__device__ __align__(16) __nv_bfloat16 g_Vth[64 * 64 * 2048];  // V^T [n][d][t]
__device__ __align__(16) __nv_bfloat16 g_Vtl[64 * 64 * 2048];
__device__ __align__(16) __nv_bfloat16 g_Et[1024 * 64];        // E^T [s][d] hi
__device__ __align__(16) __nv_bfloat16 g_Xqh[8 * 1024 * 512], g_Xql[8 * 1024 * 512];
__device__ __align__(16) __nv_bfloat16 g_Xkh[8 * 2048 * 512], g_Xkl[8 * 2048 * 512];
__device__ __align__(16) __nv_bfloat16 g_Xvh[8 * 2048 * 512], g_Xvl[8 * 2048 * 512];
__device__ __align__(16) __nv_bfloat16 g_WqTh[512 * 512], g_WqTl[512 * 512];
__device__ __align__(16) __nv_bfloat16 g_WkTh[512 * 512], g_WkTl[512 * 512];
__device__ __align__(16) __nv_bfloat16 g_WvTh[512 * 512], g_WvTl[512 * 512];
__device__ __align__(16) __nv_bfloat16 g_WoTh[512 * 512], g_WoTl[512 * 512];
__device__ __align__(16) __nv_bfloat16 g_Ch[8 * 1024 * 512], g_Cl[8 * 1024 * 512];

// ---------------- helpers ----------------------------------------------------
DINLINE void mma_bf16(float c[4], uint32_t a0, uint32_t a1, uint32_t a2,
                      uint32_t a3, uint32_t b0, uint32_t b1) {
    asm volatile(
        "mma.sync.aligned.m16n8k16.row.col.f32.bf16.bf16.f32 "
        "{%0,%1,%2,%3}, {%4,%5,%6,%7}, {%8,%9}, {%0,%1,%2,%3};\n"
        : "+f"(c[0]), "+f"(c[1]), "+f"(c[2]), "+f"(c[3])
        : "r"(a0), "r"(a1), "r"(a2), "r"(a3), "r"(b0), "r"(b1));
}

DINLINE uint32_t smem_u32(const void* p) {
    return (uint32_t)__cvta_generic_to_shared(p);
}

DINLINE void cp16(uint32_t dst, const void* src) {
    asm volatile("cp.async.cg.shared.global [%0], [%1], 16;\n" ::"r"(dst),
                 "l"(src));
}
DINLINE void cp_commit() { asm volatile("cp.async.commit_group;\n" ::); }
template <int N>
DINLINE void cp_wait() {
    asm volatile("cp.async.wait_group %0;\n" ::"n"(N));
}

DINLINE void split_bf(float x, __nv_bfloat16& h, __nv_bfloat16& l) {
    h = __float2bfloat16_rn(x);
    l = __float2bfloat16_rn(x - __bfloat162float(h));
}

DINLINE void st_bf2(__nv_bfloat16* p, __nv_bfloat16 a, __nv_bfloat16 b) {
    __nv_bfloat162 t;
    t.x = a;
    t.y = b;
    *(__nv_bfloat162*)p = t;
}

DINLINE uint32_t pack_bf2(__nv_bfloat16 a, __nv_bfloat16 b) {
    __nv_bfloat162 t;
    t.x = a;
    t.y = b;
    return *(uint32_t*)&t;
}

// ---------------- split / transpose kernels ------------------------------------
__global__ void __launch_bounds__(256) split_x(const float* __restrict__ in,
                                               __nv_bfloat16* __restrict__ h,
                                               __nv_bfloat16* __restrict__ l,
                                               int n4) {
    int i = blockIdx.x * blockDim.x + threadIdx.x;
    if (i >= n4) return;
    float4 v = ((const float4*)in)[i];
    __nv_bfloat16 h0, l0, h1, l1, h2, l2, h3, l3;
    split_bf(v.x, h0, l0);
    split_bf(v.y, h1, l1);
    split_bf(v.z, h2, l2);
    split_bf(v.w, h3, l3);
    st_bf2(h + (size_t)i * 4, h0, h1);
    st_bf2(h + (size_t)i * 4 + 2, h2, h3);
    st_bf2(l + (size_t)i * 4, l0, l1);
    st_bf2(l + (size_t)i * 4 + 2, l2, l3);
}

// W[k][n] (512x512) -> T[n][k] split hi/lo
__global__ void __launch_bounds__(256) split_wT(const float* __restrict__ W,
                                                __nv_bfloat16* __restrict__ Th,
                                                __nv_bfloat16* __restrict__ Tl) {
    __shared__ float tile[32][33];
    int tx = threadIdx.x & 31, ty = threadIdx.x >> 5;  // 32 x 8
    int n0 = blockIdx.x * 32, k0 = blockIdx.y * 32;
#pragma unroll
    for (int i = 0; i < 4; i++)
        tile[ty + i * 8][tx] = W[(size_t)(k0 + ty + i * 8) * 512 + n0 + tx];
    __syncthreads();
#pragma unroll
    for (int i = 0; i < 4; i++) {
        float v = tile[tx][ty + i * 8];
        __nv_bfloat16 h, l;
        split_bf(v, h, l);
        Th[(size_t)(n0 + ty + i * 8) * 512 + k0 + tx] = h;
        Tl[(size_t)(n0 + ty + i * 8) * 512 + k0 + tx] = l;
    }
}

// V [n][t][d] bf16 -> V^T [n][d][t]
__global__ void __launch_bounds__(256) transpose_v(
    const __nv_bfloat16* __restrict__ in, __nv_bfloat16* __restrict__ out) {
    __shared__ __nv_bfloat16 tile[32][33];
    int tx = threadIdx.x & 31, ty = threadIdx.x >> 5;  // 32 x 8
    int n = blockIdx.z;
    int t0 = blockIdx.x * 32, d0 = blockIdx.y * 32;
    const __nv_bfloat16* src = in + ((size_t)n * 2048 + t0) * 64 + d0;
#pragma unroll
    for (int i = 0; i < 4; i++)
        tile[ty + i * 8][tx] = src[(size_t)(ty + i * 8) * 64 + tx];
    __syncthreads();
    __nv_bfloat16* dst = out + ((size_t)n * 64 + d0) * 2048 + t0;
#pragma unroll
    for (int i = 0; i < 4; i++)
        dst[(size_t)(ty + i * 8) * 2048 + tx] = tile[tx][ty + i * 8];
}

// E fp32 [d=64][s=1024] -> E^T bf16 [s][d]
__global__ void __launch_bounds__(256) conv_eT(const float* __restrict__ E,
                                               __nv_bfloat16* __restrict__ Et) {
    __shared__ float tile[32][33];
    int tx = threadIdx.x & 31, ty = threadIdx.x >> 5;
    int s0 = blockIdx.x * 32, d0 = blockIdx.y * 32;
#pragma unroll
    for (int i = 0; i < 4; i++)
        tile[ty + i * 8][tx] = E[(size_t)(d0 + ty + i * 8) * 1024 + s0 + tx];
    __syncthreads();
#pragma unroll
    for (int i = 0; i < 4; i++)
        Et[(size_t)(s0 + ty + i * 8) * 64 + d0 + tx] =
            __float2bfloat16_rn(tile[tx][ty + i * 8]);
}

// ---------------- pre-split bf16x3 GEMM with cp.async double buffer -----------
constexpr int AS2 = 40;
constexpr int TSZ = 128 * AS2;

template <int EPI>
__global__ void __launch_bounds__(256, 1) gemm_ps(
    const __nv_bfloat16* __restrict__ Ah_g, const __nv_bfloat16* __restrict__ Al_g,
    const __nv_bfloat16* __restrict__ Th_g, const __nv_bfloat16* __restrict__ Tl_g,
    float* __restrict__ outF, __nv_bfloat16* __restrict__ outH,
    __nv_bfloat16* __restrict__ outL, int T) {
    extern __shared__ __nv_bfloat16 smg[];

    const int tid = threadIdx.x;
    const int lane = tid & 31, wid = tid >> 5;
    const int wm = wid >> 2, wn = wid & 3;  // 2 x 4 warps
    const int row0 = blockIdx.x * 128, col0 = blockIdx.y * 128;
    const int g = lane >> 2, t2 = (lane & 3) * 2;

    const int lr = tid >> 2;
    const int lc = (tid & 3) * 8;

    float acc[4][4][4] = {};

    {
        __nv_bfloat16* Ah = smg;
        __nv_bfloat16* Al = Ah + TSZ;
        __nv_bfloat16* Bh = Al + TSZ;
        __nv_bfloat16* Bl = Bh + TSZ;
#pragma unroll
        for (int half = 0; half < 2; half++) {
            int r = lr + half * 64;
            cp16(smem_u32(Ah + r * AS2 + lc), Ah_g + (size_t)(row0 + r) * 512 + lc);
            cp16(smem_u32(Al + r * AS2 + lc), Al_g + (size_t)(row0 + r) * 512 + lc);
            cp16(smem_u32(Bh + r * AS2 + lc), Th_g + (size_t)(col0 + r) * 512 + lc);
            cp16(smem_u32(Bl + r * AS2 + lc), Tl_g + (size_t)(col0 + r) * 512 + lc);
        }
        cp_commit();
    }

    int buf = 0;
    for (int kk = 0; kk < 512; kk += 32) {
        if (kk + 32 < 512) {
            __nv_bfloat16* Ah = smg + (buf ^ 1) * 4 * TSZ;
            __nv_bfloat16* Al = Ah + TSZ;
            __nv_bfloat16* Bh = Al + TSZ;
            __nv_bfloat16* Bl = Bh + TSZ;
            int kn = kk + 32;
#pragma unroll
            for (int half = 0; half < 2; half++) {
                int r = lr + half * 64;
                cp16(smem_u32(Ah + r * AS2 + lc),
                     Ah_g + (size_t)(row0 + r) * 512 + kn + lc);
                cp16(smem_u32(Al + r * AS2 + lc),
                     Al_g + (size_t)(row0 + r) * 512 + kn + lc);
                cp16(smem_u32(Bh + r * AS2 + lc),
                     Th_g + (size_t)(col0 + r) * 512 + kn + lc);
                cp16(smem_u32(Bl + r * AS2 + lc),
                     Tl_g + (size_t)(col0 + r) * 512 + kn + lc);
            }
            cp_commit();
            cp_wait<1>();
        } else {
            cp_wait<0>();
        }
        __syncthreads();

        const __nv_bfloat16* Ah = smg + buf * 4 * TSZ;
        const __nv_bfloat16* Al = Ah + TSZ;
        const __nv_bfloat16* Bh = Al + TSZ;
        const __nv_bfloat16* Bl = Bh + TSZ;
#pragma unroll
        for (int ks = 0; ks < 32; ks += 16) {
            uint32_t ah[4][4], al[4][4], bh[4][2], bl[4][2];
#pragma unroll
            for (int mf = 0; mf < 4; mf++) {
                int rb = wm * 64 + mf * 16 + g;
                ah[mf][0] = *(uint32_t*)&Ah[rb * AS2 + ks + t2];
                ah[mf][1] = *(uint32_t*)&Ah[(rb + 8) * AS2 + ks + t2];
                ah[mf][2] = *(uint32_t*)&Ah[rb * AS2 + ks + 8 + t2];
                ah[mf][3] = *(uint32_t*)&Ah[(rb + 8) * AS2 + ks + 8 + t2];
                al[mf][0] = *(uint32_t*)&Al[rb * AS2 + ks + t2];
                al[mf][1] = *(uint32_t*)&Al[(rb + 8) * AS2 + ks + t2];
                al[mf][2] = *(uint32_t*)&Al[rb * AS2 + ks + 8 + t2];
                al[mf][3] = *(uint32_t*)&Al[(rb + 8) * AS2 + ks + 8 + t2];
            }
#pragma unroll
            for (int nf = 0; nf < 4; nf++) {
                int cb = wn * 32 + nf * 8 + g;
                bh[nf][0] = *(uint32_t*)&Bh[cb * AS2 + ks + t2];
                bh[nf][1] = *(uint32_t*)&Bh[cb * AS2 + ks + 8 + t2];
                bl[nf][0] = *(uint32_t*)&Bl[cb * AS2 + ks + t2];
                bl[nf][1] = *(uint32_t*)&Bl[cb * AS2 + ks + 8 + t2];
            }
#pragma unroll
            for (int mf = 0; mf < 4; mf++)
#pragma unroll
                for (int nf = 0; nf < 4; nf++) {
                    mma_bf16(acc[mf][nf], ah[mf][0], ah[mf][1], ah[mf][2],
                             ah[mf][3], bh[nf][0], bh[nf][1]);
                    mma_bf16(acc[mf][nf], ah[mf][0], ah[mf][1], ah[mf][2],
                             ah[mf][3], bl[nf][0], bl[nf][1]);
                    mma_bf16(acc[mf][nf], al[mf][0], al[mf][1], al[mf][2],
                             al[mf][3], bh[nf][0], bh[nf][1]);
                }
        }
        __syncthreads();
        buf ^= 1;
    }

#pragma unroll
    for (int mf = 0; mf < 4; mf++) {
#pragma unroll
        for (int nf = 0; nf < 4; nf++) {
            int rr = row0 + wm * 64 + mf * 16 + g;
            int cc = col0 + wn * 32 + nf * 8 + t2;
            if (EPI == 0) {
                *(float2*)&outF[(size_t)rr * 512 + cc] =
                    make_float2(acc[mf][nf][0], acc[mf][nf][1]);
                *(float2*)&outF[(size_t)(rr + 8) * 512 + cc] =
                    make_float2(acc[mf][nf][2], acc[mf][nf][3]);
            } else {
                int head = cc >> 6, d = cc & 63;
#pragma unroll
                for (int rh = 0; rh < 2; rh++) {
                    int grow = rr + rh * 8;
                    int b = grow / T, t = grow - b * T;
                    size_t idx = (((size_t)(b * 8 + head) * T + t) << 6) + d;
                    __nv_bfloat16 h0, l0, h1, l1;
                    split_bf(acc[mf][nf][rh * 2 + 0], h0, l0);
                    split_bf(acc[mf][nf][rh * 2 + 1], h1, l1);
                    st_bf2(&outH[idx], h0, h1);
                    st_bf2(&outL[idx], l0, l1);
                }
            }
        }
    }
}

// ---------------- fused banded attention v8: in-register P (FA2-style) --------
// PV split over keys per warp; warp-local partial O[32][64]; one final
// cross-warp reduction. No P staging in smem.
__global__ void __launch_bounds__(256, 1) attn_tc8(
    const __nv_bfloat16* __restrict__ Qh, const __nv_bfloat16* __restrict__ Ql,
    const __nv_bfloat16* __restrict__ Kh_, const __nv_bfloat16* __restrict__ Kl_,
    const __nv_bfloat16* __restrict__ Vth, const __nv_bfloat16* __restrict__ Vtl,
    const __nv_bfloat16* __restrict__ Et, __nv_bfloat16* __restrict__ Ch,
    __nv_bfloat16* __restrict__ Cl) {
    constexpr int QS = 72, KS = 72, ES = 72, VS = 200, QES = 132, OS = 68;
    extern __shared__ char smraw[];
    __nv_bfloat16* Qsh = (__nv_bfloat16*)smraw;  // [64][QS]
    __nv_bfloat16* Qsl = Qsh + 64 * QS;
    __nv_bfloat16* Ksh = Qsl + 64 * QS;          // [192][KS]
    __nv_bfloat16* Ksl = Ksh + 192 * KS;
    __nv_bfloat16* Esh = Ksl + 192 * KS;         // [s=128][ES] hi only
    __nv_bfloat16* Vsh = Esh + 128 * ES;         // [d=64][VS]
    __nv_bfloat16* Vsl = Vsh + 64 * VS;
    float* QEs = (float*)(Vsl + 64 * VS);        // [64][QES]
    float* redmax = QEs + 64 * QES;              // [4][64]
    float* redsum = redmax + 256;                // [4][64]
    float* mrow = redsum + 256;                  // [64]
    float* lrow = mrow + 64;                     // [64]
    // epilogue-only: alias over K/E regions (dead after last chunk)
    float* Ored = (float*)Ksh;                   // [8 warp][32][OS]

    const int tid = threadIdx.x, lane = tid & 31, wid = tid >> 5;
    const int wm = wid >> 2, wn = wid & 3;  // 2 x 4 warps
    const int g = lane >> 2, t2 = (lane & 3) * 2;
    const int n = blockIdx.y, m0 = blockIdx.x * 64;
    const float SCl2 = 0.125f * 1.4426950408889634f;

    auto issue_KE = [&](int c) {
        const size_t kbase = ((size_t)n * 2048 + m0 + c * 128) << 6;
        const __nv_bfloat16* sh = Kh_ + kbase;
        const __nv_bfloat16* sl = Kl_ + kbase;
#pragma unroll
        for (int it = 0; it < 6; it++) {
            int f = tid + it * 256;
            int kr = f >> 3, j = (f & 7) * 8;
            cp16(smem_u32(Ksh + kr * KS + j), sh + f * 8);
            cp16(smem_u32(Ksl + kr * KS + j), sl + f * 8);
        }
        const __nv_bfloat16* es = Et + (size_t)(c * 128) * 64;
#pragma unroll
        for (int it = 0; it < 4; it++) {
            int f = tid + it * 256;
            int s = f >> 3, j = (f & 7) * 8;
            cp16(smem_u32(Esh + s * ES + j), es + f * 8);
        }
    };
    auto issue_V = [&](int c) {
        const __nv_bfloat16* vh = Vth + (size_t)n * 64 * 2048 + m0 + c * 128;
        const __nv_bfloat16* vl = Vtl + (size_t)n * 64 * 2048 + m0 + c * 128;
#pragma unroll
        for (int it = 0; it < 6; it++) {
            int f = tid + it * 256;
            int d = f / 24, j = f - d * 24;
            cp16(smem_u32(Vsh + d * VS + j * 8), vh + (size_t)d * 2048 + j * 8);
            cp16(smem_u32(Vsl + d * VS + j * 8), vl + (size_t)d * 2048 + j * 8);
        }
    };

    // stage Q tile
    {
        const uint4* sh = (const uint4*)(Qh + (((size_t)n * 1024 + m0) << 6));
        const uint4* sl = (const uint4*)(Ql + (((size_t)n * 1024 + m0) << 6));
#pragma unroll
        for (int it = 0; it < 2; it++) {
            int f = tid + it * 256;
            int m = f >> 3, j = f & 7;
            ((uint4*)(Qsh + m * QS))[j] = sh[f];
            ((uint4*)(Qsl + m * QS))[j] = sl[f];
        }
    }
    if (tid < 64) {
        mrow[tid] = -1e30f;
        lrow[tid] = 0.f;
    }

    issue_KE(0);
    cp_commit();
    issue_V(0);
    cp_commit();

    // warp-local partial O: rows wm*32 + mf*16 + {g, g+8}, all 64 d-cols
    float o[2][8][4] = {};

    for (int c = 0; c < 8; c++) {
        cp_wait<1>();  // KE(c) ready; V(c) may be in flight
        __syncthreads();

        // ---- QE (64x128 1-pass) first (short fragment lifetime), then QK ----
        float qeAcc[2][4][4] = {};
#pragma unroll
        for (int ks = 0; ks < 64; ks += 16) {
            uint32_t ah[2][4];
#pragma unroll
            for (int mf = 0; mf < 2; mf++) {
                int rb = wm * 32 + mf * 16 + g;
                ah[mf][0] = *(uint32_t*)&Qsh[rb * QS + ks + t2];
                ah[mf][1] = *(uint32_t*)&Qsh[(rb + 8) * QS + ks + t2];
                ah[mf][2] = *(uint32_t*)&Qsh[rb * QS + ks + 8 + t2];
                ah[mf][3] = *(uint32_t*)&Qsh[(rb + 8) * QS + ks + 8 + t2];
            }
#pragma unroll
            for (int nf = 0; nf < 4; nf++) {
                int cb = wn * 32 + nf * 8 + g;
                uint32_t eb0 = *(uint32_t*)&Esh[cb * ES + ks + t2];
                uint32_t eb1 = *(uint32_t*)&Esh[cb * ES + ks + 8 + t2];
#pragma unroll
                for (int mf = 0; mf < 2; mf++)
                    mma_bf16(qeAcc[mf][nf], ah[mf][0], ah[mf][1], ah[mf][2],
                             ah[mf][3], eb0, eb1);
            }
        }
        // stage QE fragments (diagonal gather needs smem); qeAcc dies here
#pragma unroll
        for (int mf = 0; mf < 2; mf++) {
            int R = wm * 32 + mf * 16 + g;
#pragma unroll
            for (int nf = 0; nf < 4; nf++) {
                int cc = wn * 32 + nf * 8 + t2;
                *(float2*)&QEs[R * QES + cc] =
                    make_float2(qeAcc[mf][nf][0], qeAcc[mf][nf][1]);
                *(float2*)&QEs[(R + 8) * QES + cc] =
                    make_float2(qeAcc[mf][nf][2], qeAcc[mf][nf][3]);
            }
        }

        // ---- QK (64x192 bf16x3) ----
        float sAcc[2][6][4] = {};
#pragma unroll
        for (int ks = 0; ks < 64; ks += 16) {
            uint32_t ah[2][4], al[2][4];
#pragma unroll
            for (int mf = 0; mf < 2; mf++) {
                int rb = wm * 32 + mf * 16 + g;
                ah[mf][0] = *(uint32_t*)&Qsh[rb * QS + ks + t2];
                ah[mf][1] = *(uint32_t*)&Qsh[(rb + 8) * QS + ks + t2];
                ah[mf][2] = *(uint32_t*)&Qsh[rb * QS + ks + 8 + t2];
                ah[mf][3] = *(uint32_t*)&Qsh[(rb + 8) * QS + ks + 8 + t2];
                al[mf][0] = *(uint32_t*)&Qsl[rb * QS + ks + t2];
                al[mf][1] = *(uint32_t*)&Qsl[(rb + 8) * QS + ks + t2];
                al[mf][2] = *(uint32_t*)&Qsl[rb * QS + ks + 8 + t2];
                al[mf][3] = *(uint32_t*)&Qsl[(rb + 8) * QS + ks + 8 + t2];
            }
#pragma unroll
            for (int nf = 0; nf < 6; nf++) {
                int cb = wn * 48 + nf * 8 + g;
                uint32_t kb0 = *(uint32_t*)&Ksh[cb * KS + ks + t2];
                uint32_t kb1 = *(uint32_t*)&Ksh[cb * KS + ks + 8 + t2];
                uint32_t kl0 = *(uint32_t*)&Ksl[cb * KS + ks + t2];
                uint32_t kl1 = *(uint32_t*)&Ksl[cb * KS + ks + 8 + t2];
#pragma unroll
                for (int mf = 0; mf < 2; mf++) {
                    mma_bf16(sAcc[mf][nf], ah[mf][0], ah[mf][1], ah[mf][2],
                             ah[mf][3], kb0, kb1);
                    mma_bf16(sAcc[mf][nf], ah[mf][0], ah[mf][1], ah[mf][2],
                             ah[mf][3], kl0, kl1);
                    mma_bf16(sAcc[mf][nf], al[mf][0], al[mf][1], al[mf][2],
                             al[mf][3], kb0, kb1);
                }
            }
        }
        __syncthreads();  // QEs visible; K/E consumption complete

        if (c < 7) issue_KE(c + 1);
        cp_commit();

        // ---- phase 1: masked z = S + QE, per-warp row-max partials ----
#pragma unroll
        for (int mf = 0; mf < 2; mf++) {
            int R = wm * 32 + mf * 16 + g;
            float mx0 = -3e38f, mx1 = -3e38f;
#pragma unroll
            for (int nf = 0; nf < 6; nf++) {
                int cc = wn * 48 + nf * 8 + t2;
#pragma unroll
                for (int e = 0; e < 4; e++) {
                    int r = R + ((e >> 1) << 3);
                    int col = cc + (e & 1);
                    int diff = col - r;
                    float z = -3e38f;
                    if ((unsigned)diff < 128u)
                        z = sAcc[mf][nf][e] + QEs[r * QES + diff];
                    sAcc[mf][nf][e] = z;
                    if (e < 2) mx0 = fmaxf(mx0, z);
                    else mx1 = fmaxf(mx1, z);
                }
            }
            mx0 = fmaxf(mx0, __shfl_xor_sync(0xffffffffu, mx0, 1));
            mx0 = fmaxf(mx0, __shfl_xor_sync(0xffffffffu, mx0, 2));
            mx1 = fmaxf(mx1, __shfl_xor_sync(0xffffffffu, mx1, 1));
            mx1 = fmaxf(mx1, __shfl_xor_sync(0xffffffffu, mx1, 2));
            if ((lane & 3) == 0) {
                redmax[wn * 64 + R] = mx0;
                redmax[wn * 64 + R + 8] = mx1;
            }
        }
        __syncthreads();

        // ---- phase 2: exp, in-register P fragments, sums, O rescale ----
        float mn[2][2], alpha[2][2];
#pragma unroll
        for (int mf = 0; mf < 2; mf++) {
            int R = wm * 32 + mf * 16 + g;
#pragma unroll
            for (int h = 0; h < 2; h++) {
                int r = R + h * 8;
                float rm = fmaxf(fmaxf(redmax[r], redmax[64 + r]),
                                 fmaxf(redmax[128 + r], redmax[192 + r]));
                float mo = mrow[r];
                float m2 = fmaxf(mo, rm * SCl2);
                mn[mf][h] = m2;
                alpha[mf][h] = exp2f(mo - m2);
            }
        }
        uint32_t phf[2][3][4], plf[2][3][4];
#pragma unroll
        for (int mf = 0; mf < 2; mf++) {
            int R = wm * 32 + mf * 16 + g;
            float sum0 = 0.f, sum1 = 0.f;
#pragma unroll
            for (int nf = 0; nf < 6; nf++) {
                int cc = wn * 48 + nf * 8 + t2;
                float p[4];
#pragma unroll
                for (int e = 0; e < 4; e++) {
                    int r = R + ((e >> 1) << 3);
                    int col = cc + (e & 1);
                    int diff = col - r;
                    float pv = 0.f;
                    if ((unsigned)diff < 128u)
                        pv = exp2f(sAcc[mf][nf][e] * SCl2 - mn[mf][e >> 1]);
                    p[e] = pv;
                    if (e < 2) sum0 += pv;
                    else sum1 += pv;
                }
                __nv_bfloat16 h0, l0, h1, l1, h2, l2, h3, l3;
                split_bf(p[0], h0, l0);
                split_bf(p[1], h1, l1);
                split_bf(p[2], h2, l2);
                split_bf(p[3], h3, l3);
                int k = nf >> 1, hf = (nf & 1) * 2;
                // A-frag: [0]=row g (k lo), [1]=row g+8 (k lo), [2]=row g (k hi), [3]=row g+8 (k hi)
                phf[mf][k][hf + 0] = pack_bf2(h0, h1);
                phf[mf][k][hf + 1] = pack_bf2(h2, h3);
                plf[mf][k][hf + 0] = pack_bf2(l0, l1);
                plf[mf][k][hf + 1] = pack_bf2(l2, l3);
            }
            sum0 += __shfl_xor_sync(0xffffffffu, sum0, 1);
            sum0 += __shfl_xor_sync(0xffffffffu, sum0, 2);
            sum1 += __shfl_xor_sync(0xffffffffu, sum1, 1);
            sum1 += __shfl_xor_sync(0xffffffffu, sum1, 2);
            if ((lane & 3) == 0) {
                redsum[wn * 64 + R] = sum0;
                redsum[wn * 64 + R + 8] = sum1;
            }
            // rescale partial O
#pragma unroll
            for (int nfd = 0; nfd < 8; nfd++) {
                o[mf][nfd][0] *= alpha[mf][0];
                o[mf][nfd][1] *= alpha[mf][0];
                o[mf][nfd][2] *= alpha[mf][1];
                o[mf][nfd][3] *= alpha[mf][1];
            }
        }
        cp_wait<1>();  // V(c) ready (KE(c+1) may still be in flight)
        __syncthreads();

        // state update (one writer per row)
        if (wn == 0 && (lane & 3) == 0) {
#pragma unroll
            for (int mf = 0; mf < 2; mf++) {
                int R = wm * 32 + mf * 16 + g;
#pragma unroll
                for (int h = 0; h < 2; h++) {
                    int r = R + h * 8;
                    float s = redsum[r] + redsum[64 + r] + redsum[128 + r] +
                              redsum[192 + r];
                    lrow[r] = lrow[r] * alpha[mf][h] + s;
                    mrow[r] = mn[mf][h];
                }
            }
        }

        // ---- PV: warp-local keys slice (48), all 64 d; in-register P ----
#pragma unroll
        for (int k = 0; k < 3; k++) {
            int ks = wn * 48 + k * 16;
#pragma unroll
            for (int nfd = 0; nfd < 8; nfd++) {
                int cb = nfd * 8 + g;
                uint32_t vh0 = *(uint32_t*)&Vsh[cb * VS + ks + t2];
                uint32_t vh1 = *(uint32_t*)&Vsh[cb * VS + ks + 8 + t2];
                uint32_t vl0 = *(uint32_t*)&Vsl[cb * VS + ks + t2];
                uint32_t vl1 = *(uint32_t*)&Vsl[cb * VS + ks + 8 + t2];
#pragma unroll
                for (int mf = 0; mf < 2; mf++) {
                    mma_bf16(o[mf][nfd], phf[mf][k][0], phf[mf][k][1],
                             phf[mf][k][2], phf[mf][k][3], vh0, vh1);
                    mma_bf16(o[mf][nfd], phf[mf][k][0], phf[mf][k][1],
                             phf[mf][k][2], phf[mf][k][3], vl0, vl1);
                    mma_bf16(o[mf][nfd], plf[mf][k][0], plf[mf][k][1],
                             plf[mf][k][2], plf[mf][k][3], vh0, vh1);
                }
            }
        }
        __syncthreads();  // V consumption done before overwrite

        if (c < 7) issue_V(c + 1);
        cp_commit();
    }

    // ---- epilogue: cross-warp O reduction + normalize + store ----
    {
        int wbase = (wm * 4 + wn) * 32;
#pragma unroll
        for (int mf = 0; mf < 2; mf++) {
            int lr0 = mf * 16 + g;
#pragma unroll
            for (int nfd = 0; nfd < 8; nfd++) {
                int cc = nfd * 8 + t2;
                *(float2*)&Ored[(wbase + lr0) * OS + cc] =
                    make_float2(o[mf][nfd][0], o[mf][nfd][1]);
                *(float2*)&Ored[(wbase + lr0 + 8) * OS + cc] =
                    make_float2(o[mf][nfd][2], o[mf][nfd][3]);
            }
        }
    }
    __syncthreads();
    {
        const int b = n >> 3, kh = n & 7;
#pragma unroll
        for (int u = 0; u < 4; u++) {
            int id = tid + u * 256;       // 0..1023
            int r = id >> 4;              // 0..63
            int c4 = (id & 15) * 4;       // 0..60
            int wmr = r >> 5, lr = r & 31;
            float4 s = *(float4*)&Ored[((wmr * 4 + 0) * 32 + lr) * OS + c4];
            float4 s1 = *(float4*)&Ored[((wmr * 4 + 1) * 32 + lr) * OS + c4];
            float4 s2 = *(float4*)&Ored[((wmr * 4 + 2) * 32 + lr) * OS + c4];
            float4 s3 = *(float4*)&Ored[((wmr * 4 + 3) * 32 + lr) * OS + c4];
            s.x += s1.x + s2.x + s3.x;
            s.y += s1.y + s2.y + s3.y;
            s.z += s1.z + s2.z + s3.z;
            s.w += s1.w + s2.w + s3.w;
            float inv = 1.0f / lrow[r];
            __nv_bfloat16 h0, l0, h1, l1, h2, l2, h3, l3;
            split_bf(s.x * inv, h0, l0);
            split_bf(s.y * inv, h1, l1);
            split_bf(s.z * inv, h2, l2);
            split_bf(s.w * inv, h3, l3);
            size_t base = ((size_t)b * 1024 + m0 + r) * 512 + kh * 64 + c4;
            st_bf2(&Ch[base], h0, h1);
            st_bf2(&Ch[base + 2], h2, h3);
            st_bf2(&Cl[base], l0, l1);
            st_bf2(&Cl[base + 2], l2, l3);
        }
    }
}

// ---------------- launcher ----------------------------------------------------
extern "C" void kernel_launch(void* const* d_in, const int* in_sizes, int n_in,
                              void* d_out, int out_size) {
    const float* query = (const float*)d_in[0];
    const float* key = (const float*)d_in[1];
    const float* value = (const float*)d_in[2];
    const float* pos = (const float*)d_in[3];
    const float* Wq = (const float*)d_in[4];
    const float* Wk = (const float*)d_in[5];
    const float* Wv = (const float*)d_in[6];
    const float* Wo = (const float*)d_in[7];
    float* out = (float*)d_out;

    __nv_bfloat16 *qh, *ql, *kh, *kl, *vh, *vl, *vth, *vtl, *et;
    __nv_bfloat16 *xqh, *xql, *xkh, *xkl, *xvh, *xvl;
    __nv_bfloat16 *wqth, *wqtl, *wkth, *wktl, *wvth, *wvtl, *woth, *wotl;
    __nv_bfloat16 *ch, *cl;
    cudaGetSymbolAddress((void**)&qh, g_Qh);
    cudaGetSymbolAddress((void**)&ql, g_Ql);
    cudaGetSymbolAddress((void**)&kh, g_Kh);
    cudaGetSymbolAddress((void**)&kl, g_Kl);
    cudaGetSymbolAddress((void**)&vh, g_Vh);
    cudaGetSymbolAddress((void**)&vl, g_Vl);
    cudaGetSymbolAddress((void**)&vth, g_Vth);
    cudaGetSymbolAddress((void**)&vtl, g_Vtl);
    cudaGetSymbolAddress((void**)&et, g_Et);
    cudaGetSymbolAddress((void**)&xqh, g_Xqh);
    cudaGetSymbolAddress((void**)&xql, g_Xql);
    cudaGetSymbolAddress((void**)&xkh, g_Xkh);
    cudaGetSymbolAddress((void**)&xkl, g_Xkl);
    cudaGetSymbolAddress((void**)&xvh, g_Xvh);
    cudaGetSymbolAddress((void**)&xvl, g_Xvl);
    cudaGetSymbolAddress((void**)&wqth, g_WqTh);
    cudaGetSymbolAddress((void**)&wqtl, g_WqTl);
    cudaGetSymbolAddress((void**)&wkth, g_WkTh);
    cudaGetSymbolAddress((void**)&wktl, g_WkTl);
    cudaGetSymbolAddress((void**)&wvth, g_WvTh);
    cudaGetSymbolAddress((void**)&wvtl, g_WvTl);
    cudaGetSymbolAddress((void**)&woth, g_WoTh);
    cudaGetSymbolAddress((void**)&wotl, g_WoTl);
    cudaGetSymbolAddress((void**)&ch, g_Ch);
    cudaGetSymbolAddress((void**)&cl, g_Cl);

    // splits / transposes of inputs
    split_x<<<4096, 256>>>(query, xqh, xql, 1048576);
    split_x<<<8192, 256>>>(key, xkh, xkl, 2097152);
    split_x<<<8192, 256>>>(value, xvh, xvl, 2097152);
    split_wT<<<dim3(16, 16), dim3(256)>>>(Wq, wqth, wqtl);
    split_wT<<<dim3(16, 16), dim3(256)>>>(Wk, wkth, wktl);
    split_wT<<<dim3(16, 16), dim3(256)>>>(Wv, wvth, wvtl);
    split_wT<<<dim3(16, 16), dim3(256)>>>(Wo, woth, wotl);
    conv_eT<<<dim3(32, 2), 256>>>(pos, et);

    // projections
    const int gsm = 2 * 4 * TSZ * 2;  // 81920 bytes
    cudaFuncSetAttribute(gemm_ps<1>, cudaFuncAttributeMaxDynamicSharedMemorySize,
                         gsm);
    cudaFuncSetAttribute(gemm_ps<0>, cudaFuncAttributeMaxDynamicSharedMemorySize,
                         gsm);
    gemm_ps<1><<<dim3(64, 4), 256, gsm>>>(xqh, xql, wqth, wqtl, nullptr, qh, ql,
                                          1024);
    gemm_ps<1><<<dim3(128, 4), 256, gsm>>>(xkh, xkl, wkth, wktl, nullptr, kh, kl,
                                           2048);
    gemm_ps<1><<<dim3(128, 4), 256, gsm>>>(xvh, xvl, wvth, wvtl, nullptr, vh, vl,
                                           2048);

    // V transpose to [n][d][t]
    transpose_v<<<dim3(64, 2, 64), 256>>>(vh, vth);
    transpose_v<<<dim3(64, 2, 64), 256>>>(vl, vtl);

    // attention (pipelined, in-register P)
    const int smem_bytes =
        (2 * 64 * 72 + 2 * 192 * 72 + 128 * 72 + 2 * 64 * 200) * 2 +
        (64 * 132 + 256 + 256 + 64 + 64) * 4;  // 179712
    cudaFuncSetAttribute(attn_tc8, cudaFuncAttributeMaxDynamicSharedMemorySize,
                         smem_bytes);
    attn_tc8<<<dim3(16, 64), 256, smem_bytes>>>(qh, ql, kh, kl, vth, vtl, et, ch,
                                                cl);

    // output projection
    gemm_ps<0><<<dim3(64, 4), 256, gsm>>>(ch, cl, woth, wotl, out, nullptr,
                                          nullptr, 1024);
}

// round 11
// speedup vs baseline: 1.8213x; 1.0306x over previous
#include <cuda_runtime.h>
#include <cuda_bf16.h>
#include <cuda_fp16.h>
#include <stdint.h>
#include <math.h>

// B=8, M=1024, H=512, K=8 heads, D=64, SPAN=1024, MK=2048
#define DINLINE __device__ __forceinline__

// ---------------- scratch ----------------------------------------------------
__device__ __align__(16) __nv_bfloat16 g_Qh[64 * 1024 * 64];
__device__ __align__(16) __nv_bfloat16 g_Ql[64 * 1024 * 64];
__device__ __align__(16) __nv_bfloat16 g_Kh[64 * 2048 * 64];
__device__ __align__(16) __nv_bfloat16 g_Kl[64 * 2048 * 64];
__device__ __align__(16) __half g_Vh[64 * 2048 * 64];          // fp16 V hi
__device__ __align__(16) __half g_Vl[64 * 2048 * 64];          // fp16 V lo
__device__ __align__(16) __half g_Vth[64 * 64 * 2048];         // V^T [n][d][t]
__device__ __align__(16) __half g_Vtl[64 * 64 * 2048];
__device__ __align__(16) __nv_bfloat16 g_Et[1024 * 64];        // E^T [s][d] hi
__device__ __align__(16) __nv_bfloat16 g_Xqh[8 * 1024 * 512], g_Xql[8 * 1024 * 512];
__device__ __align__(16) __nv_bfloat16 g_Xkh[8 * 2048 * 512], g_Xkl[8 * 2048 * 512];
__device__ __align__(16) __nv_bfloat16 g_Xvh[8 * 2048 * 512], g_Xvl[8 * 2048 * 512];
__device__ __align__(16) __nv_bfloat16 g_WqTh[512 * 512], g_WqTl[512 * 512];
__device__ __align__(16) __nv_bfloat16 g_WkTh[512 * 512], g_WkTl[512 * 512];
__device__ __align__(16) __nv_bfloat16 g_WvTh[512 * 512], g_WvTl[512 * 512];
__device__ __align__(16) __nv_bfloat16 g_WoTh[512 * 512], g_WoTl[512 * 512];
__device__ __align__(16) __nv_bfloat16 g_Ch[8 * 1024 * 512], g_Cl[8 * 1024 * 512];

// ---------------- helpers ----------------------------------------------------
DINLINE void mma_bf16(float c[4], uint32_t a0, uint32_t a1, uint32_t a2,
                      uint32_t a3, uint32_t b0, uint32_t b1) {
    asm volatile(
        "mma.sync.aligned.m16n8k16.row.col.f32.bf16.bf16.f32 "
        "{%0,%1,%2,%3}, {%4,%5,%6,%7}, {%8,%9}, {%0,%1,%2,%3};\n"
        : "+f"(c[0]), "+f"(c[1]), "+f"(c[2]), "+f"(c[3])
        : "r"(a0), "r"(a1), "r"(a2), "r"(a3), "r"(b0), "r"(b1));
}

DINLINE void mma_f16(float c[4], uint32_t a0, uint32_t a1, uint32_t a2,
                     uint32_t a3, uint32_t b0, uint32_t b1) {
    asm volatile(
        "mma.sync.aligned.m16n8k16.row.col.f32.f16.f16.f32 "
        "{%0,%1,%2,%3}, {%4,%5,%6,%7}, {%8,%9}, {%0,%1,%2,%3};\n"
        : "+f"(c[0]), "+f"(c[1]), "+f"(c[2]), "+f"(c[3])
        : "r"(a0), "r"(a1), "r"(a2), "r"(a3), "r"(b0), "r"(b1));
}

DINLINE uint32_t smem_u32(const void* p) {
    return (uint32_t)__cvta_generic_to_shared(p);
}

DINLINE void cp16(uint32_t dst, const void* src) {
    asm volatile("cp.async.cg.shared.global [%0], [%1], 16;\n" ::"r"(dst),
                 "l"(src));
}
DINLINE void cp_commit() { asm volatile("cp.async.commit_group;\n" ::); }
template <int N>
DINLINE void cp_wait() {
    asm volatile("cp.async.wait_group %0;\n" ::"n"(N));
}

DINLINE void split_bf(float x, __nv_bfloat16& h, __nv_bfloat16& l) {
    h = __float2bfloat16_rn(x);
    l = __float2bfloat16_rn(x - __bfloat162float(h));
}

DINLINE void split_h(float x, __half& h, __half& l) {
    h = __float2half_rn(x);
    l = __float2half_rn(x - __half2float(h));
}

DINLINE void st_bf2(__nv_bfloat16* p, __nv_bfloat16 a, __nv_bfloat16 b) {
    __nv_bfloat162 t;
    t.x = a;
    t.y = b;
    *(__nv_bfloat162*)p = t;
}

DINLINE void st_h2(__half* p, __half a, __half b) {
    __half2 t;
    t.x = a;
    t.y = b;
    *(__half2*)p = t;
}

DINLINE uint32_t pack_h2(float a, float b) {
    __half2 t = __floats2half2_rn(a, b);
    return *(uint32_t*)&t;
}

// ---------------- split / transpose kernels ------------------------------------
__global__ void __launch_bounds__(256) split_x(const float* __restrict__ in,
                                               __nv_bfloat16* __restrict__ h,
                                               __nv_bfloat16* __restrict__ l,
                                               int n4) {
    int i = blockIdx.x * blockDim.x + threadIdx.x;
    if (i >= n4) return;
    float4 v = ((const float4*)in)[i];
    __nv_bfloat16 h0, l0, h1, l1, h2, l2, h3, l3;
    split_bf(v.x, h0, l0);
    split_bf(v.y, h1, l1);
    split_bf(v.z, h2, l2);
    split_bf(v.w, h3, l3);
    st_bf2(h + (size_t)i * 4, h0, h1);
    st_bf2(h + (size_t)i * 4 + 2, h2, h3);
    st_bf2(l + (size_t)i * 4, l0, l1);
    st_bf2(l + (size_t)i * 4 + 2, l2, l3);
}

// W[k][n] (512x512) -> T[n][k] split hi/lo
__global__ void __launch_bounds__(256) split_wT(const float* __restrict__ W,
                                                __nv_bfloat16* __restrict__ Th,
                                                __nv_bfloat16* __restrict__ Tl) {
    __shared__ float tile[32][33];
    int tx = threadIdx.x & 31, ty = threadIdx.x >> 5;  // 32 x 8
    int n0 = blockIdx.x * 32, k0 = blockIdx.y * 32;
#pragma unroll
    for (int i = 0; i < 4; i++)
        tile[ty + i * 8][tx] = W[(size_t)(k0 + ty + i * 8) * 512 + n0 + tx];
    __syncthreads();
#pragma unroll
    for (int i = 0; i < 4; i++) {
        float v = tile[tx][ty + i * 8];
        __nv_bfloat16 h, l;
        split_bf(v, h, l);
        Th[(size_t)(n0 + ty + i * 8) * 512 + k0 + tx] = h;
        Tl[(size_t)(n0 + ty + i * 8) * 512 + k0 + tx] = l;
    }
}

// 16-bit [n][t][d] -> [n][d][t]
__global__ void __launch_bounds__(256) transpose_v(
    const uint16_t* __restrict__ in, uint16_t* __restrict__ out) {
    __shared__ uint16_t tile[32][33];
    int tx = threadIdx.x & 31, ty = threadIdx.x >> 5;  // 32 x 8
    int n = blockIdx.z;
    int t0 = blockIdx.x * 32, d0 = blockIdx.y * 32;
    const uint16_t* src = in + ((size_t)n * 2048 + t0) * 64 + d0;
#pragma unroll
    for (int i = 0; i < 4; i++)
        tile[ty + i * 8][tx] = src[(size_t)(ty + i * 8) * 64 + tx];
    __syncthreads();
    uint16_t* dst = out + ((size_t)n * 64 + d0) * 2048 + t0;
#pragma unroll
    for (int i = 0; i < 4; i++)
        dst[(size_t)(ty + i * 8) * 2048 + tx] = tile[tx][ty + i * 8];
}

// E fp32 [d=64][s=1024] -> E^T bf16 [s][d]
__global__ void __launch_bounds__(256) conv_eT(const float* __restrict__ E,
                                               __nv_bfloat16* __restrict__ Et) {
    __shared__ float tile[32][33];
    int tx = threadIdx.x & 31, ty = threadIdx.x >> 5;
    int s0 = blockIdx.x * 32, d0 = blockIdx.y * 32;
#pragma unroll
    for (int i = 0; i < 4; i++)
        tile[ty + i * 8][tx] = E[(size_t)(d0 + ty + i * 8) * 1024 + s0 + tx];
    __syncthreads();
#pragma unroll
    for (int i = 0; i < 4; i++)
        Et[(size_t)(s0 + ty + i * 8) * 64 + d0 + tx] =
            __float2bfloat16_rn(tile[tx][ty + i * 8]);
}

// ---------------- pre-split bf16x3 GEMM with cp.async double buffer -----------
// EPI=0: fp32 out. EPI=1: head-scatter bf16 hi/lo. EPI=2: head-scatter fp16 hi/lo.
constexpr int AS2 = 40;
constexpr int TSZ = 128 * AS2;

template <int EPI>
__global__ void __launch_bounds__(256, 1) gemm_ps(
    const __nv_bfloat16* __restrict__ Ah_g, const __nv_bfloat16* __restrict__ Al_g,
    const __nv_bfloat16* __restrict__ Th_g, const __nv_bfloat16* __restrict__ Tl_g,
    float* __restrict__ outF, void* __restrict__ outH, void* __restrict__ outL,
    int T) {
    extern __shared__ __nv_bfloat16 smg[];

    const int tid = threadIdx.x;
    const int lane = tid & 31, wid = tid >> 5;
    const int wm = wid >> 2, wn = wid & 3;  // 2 x 4 warps
    const int row0 = blockIdx.x * 128, col0 = blockIdx.y * 128;
    const int g = lane >> 2, t2 = (lane & 3) * 2;

    const int lr = tid >> 2;
    const int lc = (tid & 3) * 8;

    float acc[4][4][4] = {};

    {
        __nv_bfloat16* Ah = smg;
        __nv_bfloat16* Al = Ah + TSZ;
        __nv_bfloat16* Bh = Al + TSZ;
        __nv_bfloat16* Bl = Bh + TSZ;
#pragma unroll
        for (int half = 0; half < 2; half++) {
            int r = lr + half * 64;
            cp16(smem_u32(Ah + r * AS2 + lc), Ah_g + (size_t)(row0 + r) * 512 + lc);
            cp16(smem_u32(Al + r * AS2 + lc), Al_g + (size_t)(row0 + r) * 512 + lc);
            cp16(smem_u32(Bh + r * AS2 + lc), Th_g + (size_t)(col0 + r) * 512 + lc);
            cp16(smem_u32(Bl + r * AS2 + lc), Tl_g + (size_t)(col0 + r) * 512 + lc);
        }
        cp_commit();
    }

    int buf = 0;
    for (int kk = 0; kk < 512; kk += 32) {
        if (kk + 32 < 512) {
            __nv_bfloat16* Ah = smg + (buf ^ 1) * 4 * TSZ;
            __nv_bfloat16* Al = Ah + TSZ;
            __nv_bfloat16* Bh = Al + TSZ;
            __nv_bfloat16* Bl = Bh + TSZ;
            int kn = kk + 32;
#pragma unroll
            for (int half = 0; half < 2; half++) {
                int r = lr + half * 64;
                cp16(smem_u32(Ah + r * AS2 + lc),
                     Ah_g + (size_t)(row0 + r) * 512 + kn + lc);
                cp16(smem_u32(Al + r * AS2 + lc),
                     Al_g + (size_t)(row0 + r) * 512 + kn + lc);
                cp16(smem_u32(Bh + r * AS2 + lc),
                     Th_g + (size_t)(col0 + r) * 512 + kn + lc);
                cp16(smem_u32(Bl + r * AS2 + lc),
                     Tl_g + (size_t)(col0 + r) * 512 + kn + lc);
            }
            cp_commit();
            cp_wait<1>();
        } else {
            cp_wait<0>();
        }
        __syncthreads();

        const __nv_bfloat16* Ah = smg + buf * 4 * TSZ;
        const __nv_bfloat16* Al = Ah + TSZ;
        const __nv_bfloat16* Bh = Al + TSZ;
        const __nv_bfloat16* Bl = Bh + TSZ;
#pragma unroll
        for (int ks = 0; ks < 32; ks += 16) {
            uint32_t ah[4][4], al[4][4], bh[4][2], bl[4][2];
#pragma unroll
            for (int mf = 0; mf < 4; mf++) {
                int rb = wm * 64 + mf * 16 + g;
                ah[mf][0] = *(uint32_t*)&Ah[rb * AS2 + ks + t2];
                ah[mf][1] = *(uint32_t*)&Ah[(rb + 8) * AS2 + ks + t2];
                ah[mf][2] = *(uint32_t*)&Ah[rb * AS2 + ks + 8 + t2];
                ah[mf][3] = *(uint32_t*)&Ah[(rb + 8) * AS2 + ks + 8 + t2];
                al[mf][0] = *(uint32_t*)&Al[rb * AS2 + ks + t2];
                al[mf][1] = *(uint32_t*)&Al[(rb + 8) * AS2 + ks + t2];
                al[mf][2] = *(uint32_t*)&Al[rb * AS2 + ks + 8 + t2];
                al[mf][3] = *(uint32_t*)&Al[(rb + 8) * AS2 + ks + 8 + t2];
            }
#pragma unroll
            for (int nf = 0; nf < 4; nf++) {
                int cb = wn * 32 + nf * 8 + g;
                bh[nf][0] = *(uint32_t*)&Bh[cb * AS2 + ks + t2];
                bh[nf][1] = *(uint32_t*)&Bh[cb * AS2 + ks + 8 + t2];
                bl[nf][0] = *(uint32_t*)&Bl[cb * AS2 + ks + t2];
                bl[nf][1] = *(uint32_t*)&Bl[cb * AS2 + ks + 8 + t2];
            }
#pragma unroll
            for (int mf = 0; mf < 4; mf++)
#pragma unroll
                for (int nf = 0; nf < 4; nf++) {
                    mma_bf16(acc[mf][nf], ah[mf][0], ah[mf][1], ah[mf][2],
                             ah[mf][3], bh[nf][0], bh[nf][1]);
                    mma_bf16(acc[mf][nf], ah[mf][0], ah[mf][1], ah[mf][2],
                             ah[mf][3], bl[nf][0], bl[nf][1]);
                    mma_bf16(acc[mf][nf], al[mf][0], al[mf][1], al[mf][2],
                             al[mf][3], bh[nf][0], bh[nf][1]);
                }
        }
        __syncthreads();
        buf ^= 1;
    }

#pragma unroll
    for (int mf = 0; mf < 4; mf++) {
#pragma unroll
        for (int nf = 0; nf < 4; nf++) {
            int rr = row0 + wm * 64 + mf * 16 + g;
            int cc = col0 + wn * 32 + nf * 8 + t2;
            if (EPI == 0) {
                *(float2*)&outF[(size_t)rr * 512 + cc] =
                    make_float2(acc[mf][nf][0], acc[mf][nf][1]);
                *(float2*)&outF[(size_t)(rr + 8) * 512 + cc] =
                    make_float2(acc[mf][nf][2], acc[mf][nf][3]);
            } else {
                int head = cc >> 6, d = cc & 63;
#pragma unroll
                for (int rh = 0; rh < 2; rh++) {
                    int grow = rr + rh * 8;
                    int b = grow / T, t = grow - b * T;
                    size_t idx = (((size_t)(b * 8 + head) * T + t) << 6) + d;
                    if (EPI == 1) {
                        __nv_bfloat16 h0, l0, h1, l1;
                        split_bf(acc[mf][nf][rh * 2 + 0], h0, l0);
                        split_bf(acc[mf][nf][rh * 2 + 1], h1, l1);
                        st_bf2((__nv_bfloat16*)outH + idx, h0, h1);
                        st_bf2((__nv_bfloat16*)outL + idx, l0, l1);
                    } else {
                        __half h0, l0, h1, l1;
                        split_h(acc[mf][nf][rh * 2 + 0], h0, l0);
                        split_h(acc[mf][nf][rh * 2 + 1], h1, l1);
                        st_h2((__half*)outH + idx, h0, h1);
                        st_h2((__half*)outL + idx, l0, l1);
                    }
                }
            }
        }
    }
}

// ---------------- fused banded attention v9 ------------------------------------
// In-register P (fp16, no split), fp16 2-pass PV, warp-local online softmax
// with exact cross-warp merge in the epilogue.
__global__ void __launch_bounds__(256, 1) attn_tc9(
    const __nv_bfloat16* __restrict__ Qh, const __nv_bfloat16* __restrict__ Ql,
    const __nv_bfloat16* __restrict__ Kh_, const __nv_bfloat16* __restrict__ Kl_,
    const __half* __restrict__ Vth, const __half* __restrict__ Vtl,
    const __nv_bfloat16* __restrict__ Et, __nv_bfloat16* __restrict__ Ch,
    __nv_bfloat16* __restrict__ Cl) {
    constexpr int QS = 72, KS = 72, ES = 72, VS = 200, QES = 132, OS = 68;
    extern __shared__ char smraw[];
    __nv_bfloat16* Qsh = (__nv_bfloat16*)smraw;  // [64][QS]
    __nv_bfloat16* Qsl = Qsh + 64 * QS;
    __nv_bfloat16* Ksh = Qsl + 64 * QS;          // [192][KS]
    __nv_bfloat16* Ksl = Ksh + 192 * KS;
    __nv_bfloat16* Esh = Ksl + 192 * KS;         // [s=128][ES] hi only
    __half* Vsh = (__half*)(Esh + 128 * ES);     // [d=64][VS] fp16
    __half* Vsl = Vsh + 64 * VS;
    float* QEs = (float*)(Vsl + 64 * VS);        // [64][QES]
    float* mls = QEs + 64 * QES;                 // [4][64] warp m
    float* lls = mls + 256;                      // [4][64] warp l
    // epilogue-only: alias over K/E regions (dead after last chunk)
    float* Ored = (float*)Ksh;                   // [8 warp][32][OS]

    const int tid = threadIdx.x, lane = tid & 31, wid = tid >> 5;
    const int wm = wid >> 2, wn = wid & 3;  // 2 x 4 warps
    const int g = lane >> 2, t2 = (lane & 3) * 2;
    const int n = blockIdx.y, m0 = blockIdx.x * 64;
    const float SCl2 = 0.125f * 1.4426950408889634f;

    auto issue_KE = [&](int c) {
        const size_t kbase = ((size_t)n * 2048 + m0 + c * 128) << 6;
        const __nv_bfloat16* sh = Kh_ + kbase;
        const __nv_bfloat16* sl = Kl_ + kbase;
#pragma unroll
        for (int it = 0; it < 6; it++) {
            int f = tid + it * 256;
            int kr = f >> 3, j = (f & 7) * 8;
            cp16(smem_u32(Ksh + kr * KS + j), sh + f * 8);
            cp16(smem_u32(Ksl + kr * KS + j), sl + f * 8);
        }
        const __nv_bfloat16* es = Et + (size_t)(c * 128) * 64;
#pragma unroll
        for (int it = 0; it < 4; it++) {
            int f = tid + it * 256;
            int s = f >> 3, j = (f & 7) * 8;
            cp16(smem_u32(Esh + s * ES + j), es + f * 8);
        }
    };
    auto issue_V = [&](int c) {
        const __half* vh = Vth + (size_t)n * 64 * 2048 + m0 + c * 128;
        const __half* vl = Vtl + (size_t)n * 64 * 2048 + m0 + c * 128;
#pragma unroll
        for (int it = 0; it < 6; it++) {
            int f = tid + it * 256;
            int d = f / 24, j = f - d * 24;
            cp16(smem_u32(Vsh + d * VS + j * 8), vh + (size_t)d * 2048 + j * 8);
            cp16(smem_u32(Vsl + d * VS + j * 8), vl + (size_t)d * 2048 + j * 8);
        }
    };

    // stage Q tile
    {
        const uint4* sh = (const uint4*)(Qh + (((size_t)n * 1024 + m0) << 6));
        const uint4* sl = (const uint4*)(Ql + (((size_t)n * 1024 + m0) << 6));
#pragma unroll
        for (int it = 0; it < 2; it++) {
            int f = tid + it * 256;
            int m = f >> 3, j = f & 7;
            ((uint4*)(Qsh + m * QS))[j] = sh[f];
            ((uint4*)(Qsl + m * QS))[j] = sl[f];
        }
    }

    issue_KE(0);
    cp_commit();
    issue_V(0);
    cp_commit();

    // warp-local state
    float o[2][8][4] = {};
    float mreg[2][2] = {{-1e30f, -1e30f}, {-1e30f, -1e30f}};
    float lreg[2][2] = {};

    for (int c = 0; c < 8; c++) {
        cp_wait<1>();  // KE(c) ready; V(c) may be in flight
        __syncthreads();

        // ---- QE (64x128 1-pass) ----
        float qeAcc[2][4][4] = {};
#pragma unroll
        for (int ks = 0; ks < 64; ks += 16) {
            uint32_t ah[2][4];
#pragma unroll
            for (int mf = 0; mf < 2; mf++) {
                int rb = wm * 32 + mf * 16 + g;
                ah[mf][0] = *(uint32_t*)&Qsh[rb * QS + ks + t2];
                ah[mf][1] = *(uint32_t*)&Qsh[(rb + 8) * QS + ks + t2];
                ah[mf][2] = *(uint32_t*)&Qsh[rb * QS + ks + 8 + t2];
                ah[mf][3] = *(uint32_t*)&Qsh[(rb + 8) * QS + ks + 8 + t2];
            }
#pragma unroll
            for (int nf = 0; nf < 4; nf++) {
                int cb = wn * 32 + nf * 8 + g;
                uint32_t eb0 = *(uint32_t*)&Esh[cb * ES + ks + t2];
                uint32_t eb1 = *(uint32_t*)&Esh[cb * ES + ks + 8 + t2];
#pragma unroll
                for (int mf = 0; mf < 2; mf++)
                    mma_bf16(qeAcc[mf][nf], ah[mf][0], ah[mf][1], ah[mf][2],
                             ah[mf][3], eb0, eb1);
            }
        }
        // stage QE fragments (diagonal gather needs smem)
#pragma unroll
        for (int mf = 0; mf < 2; mf++) {
            int R = wm * 32 + mf * 16 + g;
#pragma unroll
            for (int nf = 0; nf < 4; nf++) {
                int cc = wn * 32 + nf * 8 + t2;
                *(float2*)&QEs[R * QES + cc] =
                    make_float2(qeAcc[mf][nf][0], qeAcc[mf][nf][1]);
                *(float2*)&QEs[(R + 8) * QES + cc] =
                    make_float2(qeAcc[mf][nf][2], qeAcc[mf][nf][3]);
            }
        }

        // ---- QK (64x192 bf16x3) ----
        float sAcc[2][6][4] = {};
#pragma unroll
        for (int ks = 0; ks < 64; ks += 16) {
            uint32_t ah[2][4], al[2][4];
#pragma unroll
            for (int mf = 0; mf < 2; mf++) {
                int rb = wm * 32 + mf * 16 + g;
                ah[mf][0] = *(uint32_t*)&Qsh[rb * QS + ks + t2];
                ah[mf][1] = *(uint32_t*)&Qsh[(rb + 8) * QS + ks + t2];
                ah[mf][2] = *(uint32_t*)&Qsh[rb * QS + ks + 8 + t2];
                ah[mf][3] = *(uint32_t*)&Qsh[(rb + 8) * QS + ks + 8 + t2];
                al[mf][0] = *(uint32_t*)&Qsl[rb * QS + ks + t2];
                al[mf][1] = *(uint32_t*)&Qsl[(rb + 8) * QS + ks + t2];
                al[mf][2] = *(uint32_t*)&Qsl[rb * QS + ks + 8 + t2];
                al[mf][3] = *(uint32_t*)&Qsl[(rb + 8) * QS + ks + 8 + t2];
            }
#pragma unroll
            for (int nf = 0; nf < 6; nf++) {
                int cb = wn * 48 + nf * 8 + g;
                uint32_t kb0 = *(uint32_t*)&Ksh[cb * KS + ks + t2];
                uint32_t kb1 = *(uint32_t*)&Ksh[cb * KS + ks + 8 + t2];
                uint32_t kl0 = *(uint32_t*)&Ksl[cb * KS + ks + t2];
                uint32_t kl1 = *(uint32_t*)&Ksl[cb * KS + ks + 8 + t2];
#pragma unroll
                for (int mf = 0; mf < 2; mf++) {
                    mma_bf16(sAcc[mf][nf], ah[mf][0], ah[mf][1], ah[mf][2],
                             ah[mf][3], kb0, kb1);
                    mma_bf16(sAcc[mf][nf], ah[mf][0], ah[mf][1], ah[mf][2],
                             ah[mf][3], kl0, kl1);
                    mma_bf16(sAcc[mf][nf], al[mf][0], al[mf][1], al[mf][2],
                             al[mf][3], kb0, kb1);
                }
            }
        }
        __syncthreads();  // QEs visible to all warps; K/E consumption done

        if (c < 7) issue_KE(c + 1);
        cp_commit();

        // ---- warp-local masked softmax over this warp's 48-key slice ----
        uint32_t pf[2][3][4];
#pragma unroll
        for (int mf = 0; mf < 2; mf++) {
            int R = wm * 32 + mf * 16 + g;
            float mx0 = -3e38f, mx1 = -3e38f;
#pragma unroll
            for (int nf = 0; nf < 6; nf++) {
                int cc = wn * 48 + nf * 8 + t2;
#pragma unroll
                for (int e = 0; e < 4; e++) {
                    int r = R + ((e >> 1) << 3);
                    int col = cc + (e & 1);
                    int diff = col - r;
                    float z = -3e38f;
                    if ((unsigned)diff < 128u)
                        z = sAcc[mf][nf][e] + QEs[r * QES + diff];
                    sAcc[mf][nf][e] = z;
                    if (e < 2) mx0 = fmaxf(mx0, z);
                    else mx1 = fmaxf(mx1, z);
                }
            }
            mx0 = fmaxf(mx0, __shfl_xor_sync(0xffffffffu, mx0, 1));
            mx0 = fmaxf(mx0, __shfl_xor_sync(0xffffffffu, mx0, 2));
            mx1 = fmaxf(mx1, __shfl_xor_sync(0xffffffffu, mx1, 1));
            mx1 = fmaxf(mx1, __shfl_xor_sync(0xffffffffu, mx1, 2));
            float mn0 = fmaxf(mreg[mf][0], mx0 * SCl2);
            float mn1 = fmaxf(mreg[mf][1], mx1 * SCl2);
            float al0 = exp2f(mreg[mf][0] - mn0);
            float al1 = exp2f(mreg[mf][1] - mn1);
            float sum0 = 0.f, sum1 = 0.f;
#pragma unroll
            for (int nf = 0; nf < 6; nf++) {
                float p0 = exp2f(sAcc[mf][nf][0] * SCl2 - mn0);
                float p1 = exp2f(sAcc[mf][nf][1] * SCl2 - mn0);
                float p2 = exp2f(sAcc[mf][nf][2] * SCl2 - mn1);
                float p3 = exp2f(sAcc[mf][nf][3] * SCl2 - mn1);
                sum0 += p0 + p1;
                sum1 += p2 + p3;
                int k = nf >> 1, hf = (nf & 1) * 2;
                pf[mf][k][hf + 0] = pack_h2(p0, p1);
                pf[mf][k][hf + 1] = pack_h2(p2, p3);
            }
            sum0 += __shfl_xor_sync(0xffffffffu, sum0, 1);
            sum0 += __shfl_xor_sync(0xffffffffu, sum0, 2);
            sum1 += __shfl_xor_sync(0xffffffffu, sum1, 1);
            sum1 += __shfl_xor_sync(0xffffffffu, sum1, 2);
            lreg[mf][0] = lreg[mf][0] * al0 + sum0;
            lreg[mf][1] = lreg[mf][1] * al1 + sum1;
            mreg[mf][0] = mn0;
            mreg[mf][1] = mn1;
#pragma unroll
            for (int nfd = 0; nfd < 8; nfd++) {
                o[mf][nfd][0] *= al0;
                o[mf][nfd][1] *= al0;
                o[mf][nfd][2] *= al1;
                o[mf][nfd][3] *= al1;
            }
        }
        cp_wait<1>();  // V(c) ready (KE(c+1) may still be in flight)
        __syncthreads();

        // ---- PV: warp's 48-key slice x all 64 d; fp16, 2 passes ----
#pragma unroll
        for (int k = 0; k < 3; k++) {
            int ks = wn * 48 + k * 16;
#pragma unroll
            for (int nfd = 0; nfd < 8; nfd++) {
                int cb = nfd * 8 + g;
                uint32_t vh0 = *(uint32_t*)&Vsh[cb * VS + ks + t2];
                uint32_t vh1 = *(uint32_t*)&Vsh[cb * VS + ks + 8 + t2];
                uint32_t vl0 = *(uint32_t*)&Vsl[cb * VS + ks + t2];
                uint32_t vl1 = *(uint32_t*)&Vsl[cb * VS + ks + 8 + t2];
#pragma unroll
                for (int mf = 0; mf < 2; mf++) {
                    mma_f16(o[mf][nfd], pf[mf][k][0], pf[mf][k][1],
                            pf[mf][k][2], pf[mf][k][3], vh0, vh1);
                    mma_f16(o[mf][nfd], pf[mf][k][0], pf[mf][k][1],
                            pf[mf][k][2], pf[mf][k][3], vl0, vl1);
                }
            }
        }
        __syncthreads();  // V consumption done before overwrite

        if (c < 7) issue_V(c + 1);
        cp_commit();
    }

    // ---- epilogue: cross-warp (m,l,O) merge + normalize + store ----
    {
        int wbase = (wm * 4 + wn) * 32;
#pragma unroll
        for (int mf = 0; mf < 2; mf++) {
            int lr0 = mf * 16 + g;
            if ((lane & 3) == 0) {
                mls[wn * 64 + wm * 32 + lr0] = mreg[mf][0];
                mls[wn * 64 + wm * 32 + lr0 + 8] = mreg[mf][1];
                lls[wn * 64 + wm * 32 + lr0] = lreg[mf][0];
                lls[wn * 64 + wm * 32 + lr0 + 8] = lreg[mf][1];
            }
#pragma unroll
            for (int nfd = 0; nfd < 8; nfd++) {
                int cc = nfd * 8 + t2;
                *(float2*)&Ored[(wbase + lr0) * OS + cc] =
                    make_float2(o[mf][nfd][0], o[mf][nfd][1]);
                *(float2*)&Ored[(wbase + lr0 + 8) * OS + cc] =
                    make_float2(o[mf][nfd][2], o[mf][nfd][3]);
            }
        }
    }
    __syncthreads();
    {
        const int b = n >> 3, kh = n & 7;
#pragma unroll
        for (int u = 0; u < 4; u++) {
            int id = tid + u * 256;       // 0..1023
            int r = id >> 4;              // 0..63
            int c4 = (id & 15) * 4;       // 0..60
            int wmr = r >> 5, lr = r & 31;
            float mw0 = mls[r], mw1 = mls[64 + r], mw2 = mls[128 + r],
                  mw3 = mls[192 + r];
            float ms = fmaxf(fmaxf(mw0, mw1), fmaxf(mw2, mw3));
            float e0 = exp2f(mw0 - ms), e1 = exp2f(mw1 - ms),
                  e2 = exp2f(mw2 - ms), e3 = exp2f(mw3 - ms);
            float lt = lls[r] * e0 + lls[64 + r] * e1 + lls[128 + r] * e2 +
                       lls[192 + r] * e3;
            float4 s0 = *(float4*)&Ored[((wmr * 4 + 0) * 32 + lr) * OS + c4];
            float4 s1 = *(float4*)&Ored[((wmr * 4 + 1) * 32 + lr) * OS + c4];
            float4 s2 = *(float4*)&Ored[((wmr * 4 + 2) * 32 + lr) * OS + c4];
            float4 s3 = *(float4*)&Ored[((wmr * 4 + 3) * 32 + lr) * OS + c4];
            float inv = 1.0f / lt;
            float x = (s0.x * e0 + s1.x * e1 + s2.x * e2 + s3.x * e3) * inv;
            float y = (s0.y * e0 + s1.y * e1 + s2.y * e2 + s3.y * e3) * inv;
            float z = (s0.z * e0 + s1.z * e1 + s2.z * e2 + s3.z * e3) * inv;
            float w = (s0.w * e0 + s1.w * e1 + s2.w * e2 + s3.w * e3) * inv;
            __nv_bfloat16 h0, l0, h1, l1, h2, l2, h3, l3;
            split_bf(x, h0, l0);
            split_bf(y, h1, l1);
            split_bf(z, h2, l2);
            split_bf(w, h3, l3);
            size_t base = ((size_t)b * 1024 + m0 + r) * 512 + kh * 64 + c4;
            st_bf2(&Ch[base], h0, h1);
            st_bf2(&Ch[base + 2], h2, h3);
            st_bf2(&Cl[base], l0, l1);
            st_bf2(&Cl[base + 2], l2, l3);
        }
    }
}

// ---------------- launcher ----------------------------------------------------
extern "C" void kernel_launch(void* const* d_in, const int* in_sizes, int n_in,
                              void* d_out, int out_size) {
    const float* query = (const float*)d_in[0];
    const float* key = (const float*)d_in[1];
    const float* value = (const float*)d_in[2];
    const float* pos = (const float*)d_in[3];
    const float* Wq = (const float*)d_in[4];
    const float* Wk = (const float*)d_in[5];
    const float* Wv = (const float*)d_in[6];
    const float* Wo = (const float*)d_in[7];
    float* out = (float*)d_out;

    __nv_bfloat16 *qh, *ql, *kh, *kl, *et;
    __half *vh, *vl, *vth, *vtl;
    __nv_bfloat16 *xqh, *xql, *xkh, *xkl, *xvh, *xvl;
    __nv_bfloat16 *wqth, *wqtl, *wkth, *wktl, *wvth, *wvtl, *woth, *wotl;
    __nv_bfloat16 *ch, *cl;
    cudaGetSymbolAddress((void**)&qh, g_Qh);
    cudaGetSymbolAddress((void**)&ql, g_Ql);
    cudaGetSymbolAddress((void**)&kh, g_Kh);
    cudaGetSymbolAddress((void**)&kl, g_Kl);
    cudaGetSymbolAddress((void**)&vh, g_Vh);
    cudaGetSymbolAddress((void**)&vl, g_Vl);
    cudaGetSymbolAddress((void**)&vth, g_Vth);
    cudaGetSymbolAddress((void**)&vtl, g_Vtl);
    cudaGetSymbolAddress((void**)&et, g_Et);
    cudaGetSymbolAddress((void**)&xqh, g_Xqh);
    cudaGetSymbolAddress((void**)&xql, g_Xql);
    cudaGetSymbolAddress((void**)&xkh, g_Xkh);
    cudaGetSymbolAddress((void**)&xkl, g_Xkl);
    cudaGetSymbolAddress((void**)&xvh, g_Xvh);
    cudaGetSymbolAddress((void**)&xvl, g_Xvl);
    cudaGetSymbolAddress((void**)&wqth, g_WqTh);
    cudaGetSymbolAddress((void**)&wqtl, g_WqTl);
    cudaGetSymbolAddress((void**)&wkth, g_WkTh);
    cudaGetSymbolAddress((void**)&wktl, g_WkTl);
    cudaGetSymbolAddress((void**)&wvth, g_WvTh);
    cudaGetSymbolAddress((void**)&wvtl, g_WvTl);
    cudaGetSymbolAddress((void**)&woth, g_WoTh);
    cudaGetSymbolAddress((void**)&wotl, g_WoTl);
    cudaGetSymbolAddress((void**)&ch, g_Ch);
    cudaGetSymbolAddress((void**)&cl, g_Cl);

    // splits / transposes of inputs
    split_x<<<4096, 256>>>(query, xqh, xql, 1048576);
    split_x<<<8192, 256>>>(key, xkh, xkl, 2097152);
    split_x<<<8192, 256>>>(value, xvh, xvl, 2097152);
    split_wT<<<dim3(16, 16), dim3(256)>>>(Wq, wqth, wqtl);
    split_wT<<<dim3(16, 16), dim3(256)>>>(Wk, wkth, wktl);
    split_wT<<<dim3(16, 16), dim3(256)>>>(Wv, wvth, wvtl);
    split_wT<<<dim3(16, 16), dim3(256)>>>(Wo, woth, wotl);
    conv_eT<<<dim3(32, 2), 256>>>(pos, et);

    // projections
    const int gsm = 2 * 4 * TSZ * 2;  // 81920 bytes
    cudaFuncSetAttribute(gemm_ps<1>, cudaFuncAttributeMaxDynamicSharedMemorySize,
                         gsm);
    cudaFuncSetAttribute(gemm_ps<0>, cudaFuncAttributeMaxDynamicSharedMemorySize,
                         gsm);
    cudaFuncSetAttribute(gemm_ps<2>, cudaFuncAttributeMaxDynamicSharedMemorySize,
                         gsm);
    gemm_ps<1><<<dim3(64, 4), 256, gsm>>>(xqh, xql, wqth, wqtl, nullptr, qh, ql,
                                          1024);
    gemm_ps<1><<<dim3(128, 4), 256, gsm>>>(xkh, xkl, wkth, wktl, nullptr, kh, kl,
                                           2048);
    gemm_ps<2><<<dim3(128, 4), 256, gsm>>>(xvh, xvl, wvth, wvtl, nullptr, vh, vl,
                                           2048);

    // V transpose to [n][d][t] (16-bit payload)
    transpose_v<<<dim3(64, 2, 64), 256>>>((const uint16_t*)vh, (uint16_t*)vth);
    transpose_v<<<dim3(64, 2, 64), 256>>>((const uint16_t*)vl, (uint16_t*)vtl);

    // attention
    const int smem_bytes =
        (2 * 64 * 72 + 2 * 192 * 72 + 128 * 72 + 2 * 64 * 200) * 2 +
        (64 * 132 + 256 + 256) * 4;  // 178688
    cudaFuncSetAttribute(attn_tc9, cudaFuncAttributeMaxDynamicSharedMemorySize,
                         smem_bytes);
    attn_tc9<<<dim3(16, 64), 256, smem_bytes>>>(qh, ql, kh, kl, vth, vtl, et, ch,
                                                cl);

    // output projection
    gemm_ps<0><<<dim3(64, 4), 256, gsm>>>(ch, cl, woth, wotl, out, nullptr,
                                          nullptr, 1024);
}

// round 12
// speedup vs baseline: 2.0736x; 1.1385x over previous
#include <cuda_runtime.h>
#include <cuda_bf16.h>
#include <cuda_fp16.h>
#include <stdint.h>
#include <math.h>

// B=8, M=1024, H=512, K=8 heads, D=64, SPAN=1024, MK=2048
#define DINLINE __device__ __forceinline__

// ---------------- scratch ----------------------------------------------------
__device__ __align__(16) __half g_Qh[64 * 1024 * 64];          // fp16 Q (single)
__device__ __align__(16) __half g_Kh[64 * 2048 * 64];          // fp16 K (single)
__device__ __align__(16) __half g_Vh[64 * 2048 * 64];          // fp16 V hi
__device__ __align__(16) __half g_Vl[64 * 2048 * 64];          // fp16 V lo
__device__ __align__(16) __half g_Vth[64 * 64 * 2048];         // V^T [n][d][t]
__device__ __align__(16) __half g_Vtl[64 * 64 * 2048];
__device__ __align__(16) __half g_Et[1024 * 64];               // E^T [s][d] fp16
__device__ __align__(16) __nv_bfloat16 g_Xqh[8 * 1024 * 512], g_Xql[8 * 1024 * 512];
__device__ __align__(16) __nv_bfloat16 g_Xkh[8 * 2048 * 512], g_Xkl[8 * 2048 * 512];
__device__ __align__(16) __nv_bfloat16 g_Xvh[8 * 2048 * 512], g_Xvl[8 * 2048 * 512];
__device__ __align__(16) __nv_bfloat16 g_WqTh[512 * 512], g_WqTl[512 * 512];
__device__ __align__(16) __nv_bfloat16 g_WkTh[512 * 512], g_WkTl[512 * 512];
__device__ __align__(16) __nv_bfloat16 g_WvTh[512 * 512], g_WvTl[512 * 512];
__device__ __align__(16) __nv_bfloat16 g_WoTh[512 * 512], g_WoTl[512 * 512];
__device__ __align__(16) __nv_bfloat16 g_Ch[8 * 1024 * 512], g_Cl[8 * 1024 * 512];

// ---------------- helpers ----------------------------------------------------
DINLINE void mma_bf16(float c[4], uint32_t a0, uint32_t a1, uint32_t a2,
                      uint32_t a3, uint32_t b0, uint32_t b1) {
    asm volatile(
        "mma.sync.aligned.m16n8k16.row.col.f32.bf16.bf16.f32 "
        "{%0,%1,%2,%3}, {%4,%5,%6,%7}, {%8,%9}, {%0,%1,%2,%3};\n"
        : "+f"(c[0]), "+f"(c[1]), "+f"(c[2]), "+f"(c[3])
        : "r"(a0), "r"(a1), "r"(a2), "r"(a3), "r"(b0), "r"(b1));
}

DINLINE void mma_f16(float c[4], uint32_t a0, uint32_t a1, uint32_t a2,
                     uint32_t a3, uint32_t b0, uint32_t b1) {
    asm volatile(
        "mma.sync.aligned.m16n8k16.row.col.f32.f16.f16.f32 "
        "{%0,%1,%2,%3}, {%4,%5,%6,%7}, {%8,%9}, {%0,%1,%2,%3};\n"
        : "+f"(c[0]), "+f"(c[1]), "+f"(c[2]), "+f"(c[3])
        : "r"(a0), "r"(a1), "r"(a2), "r"(a3), "r"(b0), "r"(b1));
}

DINLINE uint32_t smem_u32(const void* p) {
    return (uint32_t)__cvta_generic_to_shared(p);
}

DINLINE void cp16(uint32_t dst, const void* src) {
    asm volatile("cp.async.cg.shared.global [%0], [%1], 16;\n" ::"r"(dst),
                 "l"(src));
}
DINLINE void cp_commit() { asm volatile("cp.async.commit_group;\n" ::); }
template <int N>
DINLINE void cp_wait() {
    asm volatile("cp.async.wait_group %0;\n" ::"n"(N));
}

DINLINE void split_bf(float x, __nv_bfloat16& h, __nv_bfloat16& l) {
    h = __float2bfloat16_rn(x);
    l = __float2bfloat16_rn(x - __bfloat162float(h));
}

DINLINE void split_h(float x, __half& h, __half& l) {
    h = __float2half_rn(x);
    l = __float2half_rn(x - __half2float(h));
}

DINLINE void st_bf2(__nv_bfloat16* p, __nv_bfloat16 a, __nv_bfloat16 b) {
    __nv_bfloat162 t;
    t.x = a;
    t.y = b;
    *(__nv_bfloat162*)p = t;
}

DINLINE void st_h2(__half* p, __half a, __half b) {
    __half2 t;
    t.x = a;
    t.y = b;
    *(__half2*)p = t;
}

DINLINE uint32_t pack_h2(float a, float b) {
    __half2 t = __floats2half2_rn(a, b);
    return *(uint32_t*)&t;
}

// ---------------- split / transpose kernels ------------------------------------
__global__ void __launch_bounds__(256) split_x(const float* __restrict__ in,
                                               __nv_bfloat16* __restrict__ h,
                                               __nv_bfloat16* __restrict__ l,
                                               int n4) {
    int i = blockIdx.x * blockDim.x + threadIdx.x;
    if (i >= n4) return;
    float4 v = ((const float4*)in)[i];
    __nv_bfloat16 h0, l0, h1, l1, h2, l2, h3, l3;
    split_bf(v.x, h0, l0);
    split_bf(v.y, h1, l1);
    split_bf(v.z, h2, l2);
    split_bf(v.w, h3, l3);
    st_bf2(h + (size_t)i * 4, h0, h1);
    st_bf2(h + (size_t)i * 4 + 2, h2, h3);
    st_bf2(l + (size_t)i * 4, l0, l1);
    st_bf2(l + (size_t)i * 4 + 2, l2, l3);
}

// W[k][n] (512x512) -> T[n][k] split hi/lo
__global__ void __launch_bounds__(256) split_wT(const float* __restrict__ W,
                                                __nv_bfloat16* __restrict__ Th,
                                                __nv_bfloat16* __restrict__ Tl) {
    __shared__ float tile[32][33];
    int tx = threadIdx.x & 31, ty = threadIdx.x >> 5;  // 32 x 8
    int n0 = blockIdx.x * 32, k0 = blockIdx.y * 32;
#pragma unroll
    for (int i = 0; i < 4; i++)
        tile[ty + i * 8][tx] = W[(size_t)(k0 + ty + i * 8) * 512 + n0 + tx];
    __syncthreads();
#pragma unroll
    for (int i = 0; i < 4; i++) {
        float v = tile[tx][ty + i * 8];
        __nv_bfloat16 h, l;
        split_bf(v, h, l);
        Th[(size_t)(n0 + ty + i * 8) * 512 + k0 + tx] = h;
        Tl[(size_t)(n0 + ty + i * 8) * 512 + k0 + tx] = l;
    }
}

// 16-bit [n][t][d] -> [n][d][t]
__global__ void __launch_bounds__(256) transpose_v(
    const uint16_t* __restrict__ in, uint16_t* __restrict__ out) {
    __shared__ uint16_t tile[32][33];
    int tx = threadIdx.x & 31, ty = threadIdx.x >> 5;  // 32 x 8
    int n = blockIdx.z;
    int t0 = blockIdx.x * 32, d0 = blockIdx.y * 32;
    const uint16_t* src = in + ((size_t)n * 2048 + t0) * 64 + d0;
#pragma unroll
    for (int i = 0; i < 4; i++)
        tile[ty + i * 8][tx] = src[(size_t)(ty + i * 8) * 64 + tx];
    __syncthreads();
    uint16_t* dst = out + ((size_t)n * 64 + d0) * 2048 + t0;
#pragma unroll
    for (int i = 0; i < 4; i++)
        dst[(size_t)(ty + i * 8) * 2048 + tx] = tile[tx][ty + i * 8];
}

// E fp32 [d=64][s=1024] -> E^T fp16 [s][d]
__global__ void __launch_bounds__(256) conv_eT(const float* __restrict__ E,
                                               __half* __restrict__ Et) {
    __shared__ float tile[32][33];
    int tx = threadIdx.x & 31, ty = threadIdx.x >> 5;
    int s0 = blockIdx.x * 32, d0 = blockIdx.y * 32;
#pragma unroll
    for (int i = 0; i < 4; i++)
        tile[ty + i * 8][tx] = E[(size_t)(d0 + ty + i * 8) * 1024 + s0 + tx];
    __syncthreads();
#pragma unroll
    for (int i = 0; i < 4; i++)
        Et[(size_t)(s0 + ty + i * 8) * 64 + d0 + tx] =
            __float2half_rn(tile[tx][ty + i * 8]);
}

// ---------------- pre-split bf16x3 GEMM with cp.async double buffer -----------
// EPI=0: fp32 out. EPI=2: head-scatter fp16 hi/lo. EPI=3: head-scatter fp16 hi.
constexpr int AS2 = 40;
constexpr int TSZ = 128 * AS2;

template <int EPI>
__global__ void __launch_bounds__(256, 1) gemm_ps(
    const __nv_bfloat16* __restrict__ Ah_g, const __nv_bfloat16* __restrict__ Al_g,
    const __nv_bfloat16* __restrict__ Th_g, const __nv_bfloat16* __restrict__ Tl_g,
    float* __restrict__ outF, void* __restrict__ outH, void* __restrict__ outL,
    int T) {
    extern __shared__ __nv_bfloat16 smg[];

    const int tid = threadIdx.x;
    const int lane = tid & 31, wid = tid >> 5;
    const int wm = wid >> 2, wn = wid & 3;  // 2 x 4 warps
    const int row0 = blockIdx.x * 128, col0 = blockIdx.y * 128;
    const int g = lane >> 2, t2 = (lane & 3) * 2;

    const int lr = tid >> 2;
    const int lc = (tid & 3) * 8;

    float acc[4][4][4] = {};

    {
        __nv_bfloat16* Ah = smg;
        __nv_bfloat16* Al = Ah + TSZ;
        __nv_bfloat16* Bh = Al + TSZ;
        __nv_bfloat16* Bl = Bh + TSZ;
#pragma unroll
        for (int half = 0; half < 2; half++) {
            int r = lr + half * 64;
            cp16(smem_u32(Ah + r * AS2 + lc), Ah_g + (size_t)(row0 + r) * 512 + lc);
            cp16(smem_u32(Al + r * AS2 + lc), Al_g + (size_t)(row0 + r) * 512 + lc);
            cp16(smem_u32(Bh + r * AS2 + lc), Th_g + (size_t)(col0 + r) * 512 + lc);
            cp16(smem_u32(Bl + r * AS2 + lc), Tl_g + (size_t)(col0 + r) * 512 + lc);
        }
        cp_commit();
    }

    int buf = 0;
    for (int kk = 0; kk < 512; kk += 32) {
        if (kk + 32 < 512) {
            __nv_bfloat16* Ah = smg + (buf ^ 1) * 4 * TSZ;
            __nv_bfloat16* Al = Ah + TSZ;
            __nv_bfloat16* Bh = Al + TSZ;
            __nv_bfloat16* Bl = Bh + TSZ;
            int kn = kk + 32;
#pragma unroll
            for (int half = 0; half < 2; half++) {
                int r = lr + half * 64;
                cp16(smem_u32(Ah + r * AS2 + lc),
                     Ah_g + (size_t)(row0 + r) * 512 + kn + lc);
                cp16(smem_u32(Al + r * AS2 + lc),
                     Al_g + (size_t)(row0 + r) * 512 + kn + lc);
                cp16(smem_u32(Bh + r * AS2 + lc),
                     Th_g + (size_t)(col0 + r) * 512 + kn + lc);
                cp16(smem_u32(Bl + r * AS2 + lc),
                     Tl_g + (size_t)(col0 + r) * 512 + kn + lc);
            }
            cp_commit();
            cp_wait<1>();
        } else {
            cp_wait<0>();
        }
        __syncthreads();

        const __nv_bfloat16* Ah = smg + buf * 4 * TSZ;
        const __nv_bfloat16* Al = Ah + TSZ;
        const __nv_bfloat16* Bh = Al + TSZ;
        const __nv_bfloat16* Bl = Bh + TSZ;
#pragma unroll
        for (int ks = 0; ks < 32; ks += 16) {
            uint32_t ah[4][4], al[4][4], bh[4][2], bl[4][2];
#pragma unroll
            for (int mf = 0; mf < 4; mf++) {
                int rb = wm * 64 + mf * 16 + g;
                ah[mf][0] = *(uint32_t*)&Ah[rb * AS2 + ks + t2];
                ah[mf][1] = *(uint32_t*)&Ah[(rb + 8) * AS2 + ks + t2];
                ah[mf][2] = *(uint32_t*)&Ah[rb * AS2 + ks + 8 + t2];
                ah[mf][3] = *(uint32_t*)&Ah[(rb + 8) * AS2 + ks + 8 + t2];
                al[mf][0] = *(uint32_t*)&Al[rb * AS2 + ks + t2];
                al[mf][1] = *(uint32_t*)&Al[(rb + 8) * AS2 + ks + t2];
                al[mf][2] = *(uint32_t*)&Al[rb * AS2 + ks + 8 + t2];
                al[mf][3] = *(uint32_t*)&Al[(rb + 8) * AS2 + ks + 8 + t2];
            }
#pragma unroll
            for (int nf = 0; nf < 4; nf++) {
                int cb = wn * 32 + nf * 8 + g;
                bh[nf][0] = *(uint32_t*)&Bh[cb * AS2 + ks + t2];
                bh[nf][1] = *(uint32_t*)&Bh[cb * AS2 + ks + 8 + t2];
                bl[nf][0] = *(uint32_t*)&Bl[cb * AS2 + ks + t2];
                bl[nf][1] = *(uint32_t*)&Bl[cb * AS2 + ks + 8 + t2];
            }
#pragma unroll
            for (int mf = 0; mf < 4; mf++)
#pragma unroll
                for (int nf = 0; nf < 4; nf++) {
                    mma_bf16(acc[mf][nf], ah[mf][0], ah[mf][1], ah[mf][2],
                             ah[mf][3], bh[nf][0], bh[nf][1]);
                    mma_bf16(acc[mf][nf], ah[mf][0], ah[mf][1], ah[mf][2],
                             ah[mf][3], bl[nf][0], bl[nf][1]);
                    mma_bf16(acc[mf][nf], al[mf][0], al[mf][1], al[mf][2],
                             al[mf][3], bh[nf][0], bh[nf][1]);
                }
        }
        __syncthreads();
        buf ^= 1;
    }

#pragma unroll
    for (int mf = 0; mf < 4; mf++) {
#pragma unroll
        for (int nf = 0; nf < 4; nf++) {
            int rr = row0 + wm * 64 + mf * 16 + g;
            int cc = col0 + wn * 32 + nf * 8 + t2;
            if (EPI == 0) {
                *(float2*)&outF[(size_t)rr * 512 + cc] =
                    make_float2(acc[mf][nf][0], acc[mf][nf][1]);
                *(float2*)&outF[(size_t)(rr + 8) * 512 + cc] =
                    make_float2(acc[mf][nf][2], acc[mf][nf][3]);
            } else {
                int head = cc >> 6, d = cc & 63;
#pragma unroll
                for (int rh = 0; rh < 2; rh++) {
                    int grow = rr + rh * 8;
                    int b = grow / T, t = grow - b * T;
                    size_t idx = (((size_t)(b * 8 + head) * T + t) << 6) + d;
                    if (EPI == 2) {
                        __half h0, l0, h1, l1;
                        split_h(acc[mf][nf][rh * 2 + 0], h0, l0);
                        split_h(acc[mf][nf][rh * 2 + 1], h1, l1);
                        st_h2((__half*)outH + idx, h0, h1);
                        st_h2((__half*)outL + idx, l0, l1);
                    } else {  // EPI == 3: hi only
                        st_h2((__half*)outH + idx,
                              __float2half_rn(acc[mf][nf][rh * 2 + 0]),
                              __float2half_rn(acc[mf][nf][rh * 2 + 1]));
                    }
                }
            }
        }
    }
}

// ---------------- fused banded attention v10 -----------------------------------
// fp16-single Q/K: 1-pass QK + QE fused in one ks loop; in-register fp16 P;
// fp16 2-pass PV; warp-local online softmax, exact cross-warp merge at end.
__global__ void __launch_bounds__(256, 1) attn_tc10(
    const __half* __restrict__ Qg, const __half* __restrict__ Kg,
    const __half* __restrict__ Vth, const __half* __restrict__ Vtl,
    const __half* __restrict__ Et, __nv_bfloat16* __restrict__ Ch,
    __nv_bfloat16* __restrict__ Cl) {
    constexpr int QS = 72, KS = 72, ES = 72, VS = 200, QES = 132, OS = 68;
    extern __shared__ char smraw[];
    __half* Qsh = (__half*)smraw;                // [64][QS]
    __half* Ksh = Qsh + 64 * QS;                 // [192][KS]
    __half* Esh = Ksh + 192 * KS;                // [128][ES]
    __half* Vsh = Esh + 128 * ES;                // [64][VS]
    __half* Vsl = Vsh + 64 * VS;
    float* QEs = (float*)(Vsl + 64 * VS);        // [64][QES]
    float* mls = QEs + 64 * QES;                 // [4][64]
    float* lls = mls + 256;                      // [4][64]
    // epilogue-only alias (K/E/V regions dead after last chunk)
    float* Ored = (float*)Ksh;                   // [8 warp][32][OS] = 69632 B

    const int tid = threadIdx.x, lane = tid & 31, wid = tid >> 5;
    const int wm = wid >> 2, wn = wid & 3;  // 2 x 4 warps
    const int g = lane >> 2, t2 = (lane & 3) * 2;
    const int n = blockIdx.y, m0 = blockIdx.x * 64;
    const float SCl2 = 0.125f * 1.4426950408889634f;

    auto issue_KE = [&](int c) {
        const size_t kbase = ((size_t)n * 2048 + m0 + c * 128) << 6;
        const __half* sh = Kg + kbase;
#pragma unroll
        for (int it = 0; it < 6; it++) {
            int f = tid + it * 256;
            int kr = f >> 3, j = (f & 7) * 8;
            cp16(smem_u32(Ksh + kr * KS + j), sh + f * 8);
        }
        const __half* es = Et + (size_t)(c * 128) * 64;
#pragma unroll
        for (int it = 0; it < 4; it++) {
            int f = tid + it * 256;
            int s = f >> 3, j = (f & 7) * 8;
            cp16(smem_u32(Esh + s * ES + j), es + f * 8);
        }
    };
    auto issue_V = [&](int c) {
        const __half* vh = Vth + (size_t)n * 64 * 2048 + m0 + c * 128;
        const __half* vl = Vtl + (size_t)n * 64 * 2048 + m0 + c * 128;
#pragma unroll
        for (int it = 0; it < 6; it++) {
            int f = tid + it * 256;
            int d = f / 24, j = f - d * 24;
            cp16(smem_u32(Vsh + d * VS + j * 8), vh + (size_t)d * 2048 + j * 8);
            cp16(smem_u32(Vsl + d * VS + j * 8), vl + (size_t)d * 2048 + j * 8);
        }
    };

    // stage Q tile (fp16 single)
    {
        const uint4* sh = (const uint4*)(Qg + (((size_t)n * 1024 + m0) << 6));
#pragma unroll
        for (int it = 0; it < 2; it++) {
            int f = tid + it * 256;
            int m = f >> 3, j = f & 7;
            ((uint4*)(Qsh + m * QS))[j] = sh[f];
        }
    }

    issue_KE(0);
    cp_commit();
    issue_V(0);
    cp_commit();

    // warp-local state
    float o[2][8][4] = {};
    float mreg[2][2] = {{-1e30f, -1e30f}, {-1e30f, -1e30f}};
    float lreg[2][2] = {};

    for (int c = 0; c < 8; c++) {
        cp_wait<1>();  // KE(c) ready; V(c) may be in flight
        __syncthreads();

        // ---- fused QK (1 pass) + QE (1 pass) ----
        float sAcc[2][6][4] = {};
        float qeAcc[2][4][4] = {};
#pragma unroll
        for (int ks = 0; ks < 64; ks += 16) {
            uint32_t ah[2][4];
#pragma unroll
            for (int mf = 0; mf < 2; mf++) {
                int rb = wm * 32 + mf * 16 + g;
                ah[mf][0] = *(uint32_t*)&Qsh[rb * QS + ks + t2];
                ah[mf][1] = *(uint32_t*)&Qsh[(rb + 8) * QS + ks + t2];
                ah[mf][2] = *(uint32_t*)&Qsh[rb * QS + ks + 8 + t2];
                ah[mf][3] = *(uint32_t*)&Qsh[(rb + 8) * QS + ks + 8 + t2];
            }
#pragma unroll
            for (int nf = 0; nf < 6; nf++) {
                int cb = wn * 48 + nf * 8 + g;
                uint32_t kb0 = *(uint32_t*)&Ksh[cb * KS + ks + t2];
                uint32_t kb1 = *(uint32_t*)&Ksh[cb * KS + ks + 8 + t2];
#pragma unroll
                for (int mf = 0; mf < 2; mf++)
                    mma_f16(sAcc[mf][nf], ah[mf][0], ah[mf][1], ah[mf][2],
                            ah[mf][3], kb0, kb1);
            }
#pragma unroll
            for (int nf = 0; nf < 4; nf++) {
                int cb = wn * 32 + nf * 8 + g;
                uint32_t eb0 = *(uint32_t*)&Esh[cb * ES + ks + t2];
                uint32_t eb1 = *(uint32_t*)&Esh[cb * ES + ks + 8 + t2];
#pragma unroll
                for (int mf = 0; mf < 2; mf++)
                    mma_f16(qeAcc[mf][nf], ah[mf][0], ah[mf][1], ah[mf][2],
                            ah[mf][3], eb0, eb1);
            }
        }
        // stage QE fragments (diagonal gather needs smem)
#pragma unroll
        for (int mf = 0; mf < 2; mf++) {
            int R = wm * 32 + mf * 16 + g;
#pragma unroll
            for (int nf = 0; nf < 4; nf++) {
                int cc = wn * 32 + nf * 8 + t2;
                *(float2*)&QEs[R * QES + cc] =
                    make_float2(qeAcc[mf][nf][0], qeAcc[mf][nf][1]);
                *(float2*)&QEs[(R + 8) * QES + cc] =
                    make_float2(qeAcc[mf][nf][2], qeAcc[mf][nf][3]);
            }
        }
        __syncthreads();  // QEs visible to all warps; K/E consumption done

        if (c < 7) issue_KE(c + 1);
        cp_commit();

        // ---- warp-local masked softmax over this warp's 48-key slice ----
        uint32_t pf[2][3][4];
#pragma unroll
        for (int mf = 0; mf < 2; mf++) {
            int R = wm * 32 + mf * 16 + g;
            float mx0 = -3e38f, mx1 = -3e38f;
#pragma unroll
            for (int nf = 0; nf < 6; nf++) {
                int cc = wn * 48 + nf * 8 + t2;
#pragma unroll
                for (int e = 0; e < 4; e++) {
                    int r = R + ((e >> 1) << 3);
                    int col = cc + (e & 1);
                    int diff = col - r;
                    float z = -3e38f;
                    if ((unsigned)diff < 128u)
                        z = sAcc[mf][nf][e] + QEs[r * QES + diff];
                    sAcc[mf][nf][e] = z;
                    if (e < 2) mx0 = fmaxf(mx0, z);
                    else mx1 = fmaxf(mx1, z);
                }
            }
            mx0 = fmaxf(mx0, __shfl_xor_sync(0xffffffffu, mx0, 1));
            mx0 = fmaxf(mx0, __shfl_xor_sync(0xffffffffu, mx0, 2));
            mx1 = fmaxf(mx1, __shfl_xor_sync(0xffffffffu, mx1, 1));
            mx1 = fmaxf(mx1, __shfl_xor_sync(0xffffffffu, mx1, 2));
            float mn0 = fmaxf(mreg[mf][0], mx0 * SCl2);
            float mn1 = fmaxf(mreg[mf][1], mx1 * SCl2);
            float al0 = exp2f(mreg[mf][0] - mn0);
            float al1 = exp2f(mreg[mf][1] - mn1);
            float sum0 = 0.f, sum1 = 0.f;
#pragma unroll
            for (int nf = 0; nf < 6; nf++) {
                float p0 = exp2f(sAcc[mf][nf][0] * SCl2 - mn0);
                float p1 = exp2f(sAcc[mf][nf][1] * SCl2 - mn0);
                float p2 = exp2f(sAcc[mf][nf][2] * SCl2 - mn1);
                float p3 = exp2f(sAcc[mf][nf][3] * SCl2 - mn1);
                sum0 += p0 + p1;
                sum1 += p2 + p3;
                int k = nf >> 1, hf = (nf & 1) * 2;
                pf[mf][k][hf + 0] = pack_h2(p0, p1);
                pf[mf][k][hf + 1] = pack_h2(p2, p3);
            }
            sum0 += __shfl_xor_sync(0xffffffffu, sum0, 1);
            sum0 += __shfl_xor_sync(0xffffffffu, sum0, 2);
            sum1 += __shfl_xor_sync(0xffffffffu, sum1, 1);
            sum1 += __shfl_xor_sync(0xffffffffu, sum1, 2);
            lreg[mf][0] = lreg[mf][0] * al0 + sum0;
            lreg[mf][1] = lreg[mf][1] * al1 + sum1;
            mreg[mf][0] = mn0;
            mreg[mf][1] = mn1;
#pragma unroll
            for (int nfd = 0; nfd < 8; nfd++) {
                o[mf][nfd][0] *= al0;
                o[mf][nfd][1] *= al0;
                o[mf][nfd][2] *= al1;
                o[mf][nfd][3] *= al1;
            }
        }
        cp_wait<1>();  // V(c) ready (KE(c+1) may still be in flight)
        __syncthreads();

        // ---- PV: warp's 48-key slice x all 64 d; fp16, 2 passes ----
#pragma unroll
        for (int k = 0; k < 3; k++) {
            int ks = wn * 48 + k * 16;
#pragma unroll
            for (int nfd = 0; nfd < 8; nfd++) {
                int cb = nfd * 8 + g;
                uint32_t vh0 = *(uint32_t*)&Vsh[cb * VS + ks + t2];
                uint32_t vh1 = *(uint32_t*)&Vsh[cb * VS + ks + 8 + t2];
                uint32_t vl0 = *(uint32_t*)&Vsl[cb * VS + ks + t2];
                uint32_t vl1 = *(uint32_t*)&Vsl[cb * VS + ks + 8 + t2];
#pragma unroll
                for (int mf = 0; mf < 2; mf++) {
                    mma_f16(o[mf][nfd], pf[mf][k][0], pf[mf][k][1],
                            pf[mf][k][2], pf[mf][k][3], vh0, vh1);
                    mma_f16(o[mf][nfd], pf[mf][k][0], pf[mf][k][1],
                            pf[mf][k][2], pf[mf][k][3], vl0, vl1);
                }
            }
        }
        __syncthreads();  // V consumption done before overwrite

        if (c < 7) issue_V(c + 1);
        cp_commit();
    }

    // ---- epilogue: cross-warp (m,l,O) merge + normalize + store ----
    {
        int wbase = (wm * 4 + wn) * 32;
#pragma unroll
        for (int mf = 0; mf < 2; mf++) {
            int lr0 = mf * 16 + g;
            if ((lane & 3) == 0) {
                mls[wn * 64 + wm * 32 + lr0] = mreg[mf][0];
                mls[wn * 64 + wm * 32 + lr0 + 8] = mreg[mf][1];
                lls[wn * 64 + wm * 32 + lr0] = lreg[mf][0];
                lls[wn * 64 + wm * 32 + lr0 + 8] = lreg[mf][1];
            }
#pragma unroll
            for (int nfd = 0; nfd < 8; nfd++) {
                int cc = nfd * 8 + t2;
                *(float2*)&Ored[(wbase + lr0) * OS + cc] =
                    make_float2(o[mf][nfd][0], o[mf][nfd][1]);
                *(float2*)&Ored[(wbase + lr0 + 8) * OS + cc] =
                    make_float2(o[mf][nfd][2], o[mf][nfd][3]);
            }
        }
    }
    __syncthreads();
    {
        const int b = n >> 3, kh = n & 7;
#pragma unroll
        for (int u = 0; u < 4; u++) {
            int id = tid + u * 256;       // 0..1023
            int r = id >> 4;              // 0..63
            int c4 = (id & 15) * 4;       // 0..60
            int wmr = r >> 5, lr = r & 31;
            float mw0 = mls[r], mw1 = mls[64 + r], mw2 = mls[128 + r],
                  mw3 = mls[192 + r];
            float ms = fmaxf(fmaxf(mw0, mw1), fmaxf(mw2, mw3));
            float e0 = exp2f(mw0 - ms), e1 = exp2f(mw1 - ms),
                  e2 = exp2f(mw2 - ms), e3 = exp2f(mw3 - ms);
            float lt = lls[r] * e0 + lls[64 + r] * e1 + lls[128 + r] * e2 +
                       lls[192 + r] * e3;
            float4 s0 = *(float4*)&Ored[((wmr * 4 + 0) * 32 + lr) * OS + c4];
            float4 s1 = *(float4*)&Ored[((wmr * 4 + 1) * 32 + lr) * OS + c4];
            float4 s2 = *(float4*)&Ored[((wmr * 4 + 2) * 32 + lr) * OS + c4];
            float4 s3 = *(float4*)&Ored[((wmr * 4 + 3) * 32 + lr) * OS + c4];
            float inv = 1.0f / lt;
            float x = (s0.x * e0 + s1.x * e1 + s2.x * e2 + s3.x * e3) * inv;
            float y = (s0.y * e0 + s1.y * e1 + s2.y * e2 + s3.y * e3) * inv;
            float z = (s0.z * e0 + s1.z * e1 + s2.z * e2 + s3.z * e3) * inv;
            float w = (s0.w * e0 + s1.w * e1 + s2.w * e2 + s3.w * e3) * inv;
            __nv_bfloat16 h0, l0, h1, l1, h2, l2, h3, l3;
            split_bf(x, h0, l0);
            split_bf(y, h1, l1);
            split_bf(z, h2, l2);
            split_bf(w, h3, l3);
            size_t base = ((size_t)b * 1024 + m0 + r) * 512 + kh * 64 + c4;
            st_bf2(&Ch[base], h0, h1);
            st_bf2(&Ch[base + 2], h2, h3);
            st_bf2(&Cl[base], l0, l1);
            st_bf2(&Cl[base + 2], l2, l3);
        }
    }
}

// ---------------- launcher ----------------------------------------------------
extern "C" void kernel_launch(void* const* d_in, const int* in_sizes, int n_in,
                              void* d_out, int out_size) {
    const float* query = (const float*)d_in[0];
    const float* key = (const float*)d_in[1];
    const float* value = (const float*)d_in[2];
    const float* pos = (const float*)d_in[3];
    const float* Wq = (const float*)d_in[4];
    const float* Wk = (const float*)d_in[5];
    const float* Wv = (const float*)d_in[6];
    const float* Wo = (const float*)d_in[7];
    float* out = (float*)d_out;

    __half *qg, *kg, *vh, *vl, *vth, *vtl, *et;
    __nv_bfloat16 *xqh, *xql, *xkh, *xkl, *xvh, *xvl;
    __nv_bfloat16 *wqth, *wqtl, *wkth, *wktl, *wvth, *wvtl, *woth, *wotl;
    __nv_bfloat16 *ch, *cl;
    cudaGetSymbolAddress((void**)&qg, g_Qh);
    cudaGetSymbolAddress((void**)&kg, g_Kh);
    cudaGetSymbolAddress((void**)&vh, g_Vh);
    cudaGetSymbolAddress((void**)&vl, g_Vl);
    cudaGetSymbolAddress((void**)&vth, g_Vth);
    cudaGetSymbolAddress((void**)&vtl, g_Vtl);
    cudaGetSymbolAddress((void**)&et, g_Et);
    cudaGetSymbolAddress((void**)&xqh, g_Xqh);
    cudaGetSymbolAddress((void**)&xql, g_Xql);
    cudaGetSymbolAddress((void**)&xkh, g_Xkh);
    cudaGetSymbolAddress((void**)&xkl, g_Xkl);
    cudaGetSymbolAddress((void**)&xvh, g_Xvh);
    cudaGetSymbolAddress((void**)&xvl, g_Xvl);
    cudaGetSymbolAddress((void**)&wqth, g_WqTh);
    cudaGetSymbolAddress((void**)&wqtl, g_WqTl);
    cudaGetSymbolAddress((void**)&wkth, g_WkTh);
    cudaGetSymbolAddress((void**)&wktl, g_WkTl);
    cudaGetSymbolAddress((void**)&wvth, g_WvTh);
    cudaGetSymbolAddress((void**)&wvtl, g_WvTl);
    cudaGetSymbolAddress((void**)&woth, g_WoTh);
    cudaGetSymbolAddress((void**)&wotl, g_WoTl);
    cudaGetSymbolAddress((void**)&ch, g_Ch);
    cudaGetSymbolAddress((void**)&cl, g_Cl);

    // splits / transposes of inputs
    split_x<<<4096, 256>>>(query, xqh, xql, 1048576);
    split_x<<<8192, 256>>>(key, xkh, xkl, 2097152);
    split_x<<<8192, 256>>>(value, xvh, xvl, 2097152);
    split_wT<<<dim3(16, 16), dim3(256)>>>(Wq, wqth, wqtl);
    split_wT<<<dim3(16, 16), dim3(256)>>>(Wk, wkth, wktl);
    split_wT<<<dim3(16, 16), dim3(256)>>>(Wv, wvth, wvtl);
    split_wT<<<dim3(16, 16), dim3(256)>>>(Wo, woth, wotl);
    conv_eT<<<dim3(32, 2), 256>>>(pos, et);

    // projections
    const int gsm = 2 * 4 * TSZ * 2;  // 81920 bytes
    cudaFuncSetAttribute(gemm_ps<0>, cudaFuncAttributeMaxDynamicSharedMemorySize,
                         gsm);
    cudaFuncSetAttribute(gemm_ps<2>, cudaFuncAttributeMaxDynamicSharedMemorySize,
                         gsm);
    cudaFuncSetAttribute(gemm_ps<3>, cudaFuncAttributeMaxDynamicSharedMemorySize,
                         gsm);
    gemm_ps<3><<<dim3(64, 4), 256, gsm>>>(xqh, xql, wqth, wqtl, nullptr, qg,
                                          nullptr, 1024);
    gemm_ps<3><<<dim3(128, 4), 256, gsm>>>(xkh, xkl, wkth, wktl, nullptr, kg,
                                           nullptr, 2048);
    gemm_ps<2><<<dim3(128, 4), 256, gsm>>>(xvh, xvl, wvth, wvtl, nullptr, vh, vl,
                                           2048);

    // V transpose to [n][d][t]
    transpose_v<<<dim3(64, 2, 64), 256>>>((const uint16_t*)vh, (uint16_t*)vth);
    transpose_v<<<dim3(64, 2, 64), 256>>>((const uint16_t*)vl, (uint16_t*)vtl);

    // attention
    const int smem_bytes =
        (64 * 72 + 192 * 72 + 128 * 72 + 2 * 64 * 200) * 2 +
        (64 * 132 + 256 + 256) * 4;  // 140800
    cudaFuncSetAttribute(attn_tc10, cudaFuncAttributeMaxDynamicSharedMemorySize,
                         smem_bytes);
    attn_tc10<<<dim3(16, 64), 256, smem_bytes>>>(qg, kg, vth, vtl, et, ch, cl);

    // output projection
    gemm_ps<0><<<dim3(64, 4), 256, gsm>>>(ch, cl, woth, wotl, out, nullptr,
                                          nullptr, 1024);
}

// round 13
// speedup vs baseline: 2.2716x; 1.0955x over previous
#include <cuda_runtime.h>
#include <cuda_bf16.h>
#include <cuda_fp16.h>
#include <stdint.h>
#include <math.h>

// B=8, M=1024, H=512, K=8 heads, D=64, SPAN=1024, MK=2048
#define DINLINE __device__ __forceinline__

// ---------------- scratch ----------------------------------------------------
__device__ __align__(16) __half g_Qh[64 * 1024 * 64];          // fp16 Q (single)
__device__ __align__(16) __half g_Kh[64 * 2048 * 64];          // fp16 K (single)
__device__ __align__(16) __half g_Vh[64 * 2048 * 64];          // fp16 V (single)
__device__ __align__(16) __half g_Vth[64 * 64 * 2048];         // V^T [n][d][t]
__device__ __align__(16) __half g_Et[1024 * 64];               // E^T [s][d] fp16
__device__ __align__(16) __nv_bfloat16 g_Xqh[8 * 1024 * 512], g_Xql[8 * 1024 * 512];
__device__ __align__(16) __nv_bfloat16 g_Xkh[8 * 2048 * 512], g_Xkl[8 * 2048 * 512];
__device__ __align__(16) __nv_bfloat16 g_Xvh[8 * 2048 * 512], g_Xvl[8 * 2048 * 512];
__device__ __align__(16) __nv_bfloat16 g_WqTh[512 * 512], g_WqTl[512 * 512];
__device__ __align__(16) __nv_bfloat16 g_WkTh[512 * 512], g_WkTl[512 * 512];
__device__ __align__(16) __nv_bfloat16 g_WvTh[512 * 512], g_WvTl[512 * 512];
__device__ __align__(16) __nv_bfloat16 g_WoTh[512 * 512], g_WoTl[512 * 512];
__device__ __align__(16) __nv_bfloat16 g_Ch[8 * 1024 * 512], g_Cl[8 * 1024 * 512];

// ---------------- helpers ----------------------------------------------------
DINLINE void mma_bf16(float c[4], uint32_t a0, uint32_t a1, uint32_t a2,
                      uint32_t a3, uint32_t b0, uint32_t b1) {
    asm volatile(
        "mma.sync.aligned.m16n8k16.row.col.f32.bf16.bf16.f32 "
        "{%0,%1,%2,%3}, {%4,%5,%6,%7}, {%8,%9}, {%0,%1,%2,%3};\n"
        : "+f"(c[0]), "+f"(c[1]), "+f"(c[2]), "+f"(c[3])
        : "r"(a0), "r"(a1), "r"(a2), "r"(a3), "r"(b0), "r"(b1));
}

DINLINE void mma_f16(float c[4], uint32_t a0, uint32_t a1, uint32_t a2,
                     uint32_t a3, uint32_t b0, uint32_t b1) {
    asm volatile(
        "mma.sync.aligned.m16n8k16.row.col.f32.f16.f16.f32 "
        "{%0,%1,%2,%3}, {%4,%5,%6,%7}, {%8,%9}, {%0,%1,%2,%3};\n"
        : "+f"(c[0]), "+f"(c[1]), "+f"(c[2]), "+f"(c[3])
        : "r"(a0), "r"(a1), "r"(a2), "r"(a3), "r"(b0), "r"(b1));
}

DINLINE uint32_t smem_u32(const void* p) {
    return (uint32_t)__cvta_generic_to_shared(p);
}

DINLINE void cp16(uint32_t dst, const void* src) {
    asm volatile("cp.async.cg.shared.global [%0], [%1], 16;\n" ::"r"(dst),
                 "l"(src));
}
DINLINE void cp_commit() { asm volatile("cp.async.commit_group;\n" ::); }
template <int N>
DINLINE void cp_wait() {
    asm volatile("cp.async.wait_group %0;\n" ::"n"(N));
}

DINLINE void split_bf(float x, __nv_bfloat16& h, __nv_bfloat16& l) {
    h = __float2bfloat16_rn(x);
    l = __float2bfloat16_rn(x - __bfloat162float(h));
}

DINLINE void st_bf2(__nv_bfloat16* p, __nv_bfloat16 a, __nv_bfloat16 b) {
    __nv_bfloat162 t;
    t.x = a;
    t.y = b;
    *(__nv_bfloat162*)p = t;
}

DINLINE void st_h2(__half* p, __half a, __half b) {
    __half2 t;
    t.x = a;
    t.y = b;
    *(__half2*)p = t;
}

DINLINE uint32_t pack_h2(float a, float b) {
    __half2 t = __floats2half2_rn(a, b);
    return *(uint32_t*)&t;
}

// ---------------- split / transpose kernels ------------------------------------
__global__ void __launch_bounds__(256) split_x(const float* __restrict__ in,
                                               __nv_bfloat16* __restrict__ h,
                                               __nv_bfloat16* __restrict__ l,
                                               int n4) {
    int i = blockIdx.x * blockDim.x + threadIdx.x;
    if (i >= n4) return;
    float4 v = ((const float4*)in)[i];
    __nv_bfloat16 h0, l0, h1, l1, h2, l2, h3, l3;
    split_bf(v.x, h0, l0);
    split_bf(v.y, h1, l1);
    split_bf(v.z, h2, l2);
    split_bf(v.w, h3, l3);
    st_bf2(h + (size_t)i * 4, h0, h1);
    st_bf2(h + (size_t)i * 4 + 2, h2, h3);
    st_bf2(l + (size_t)i * 4, l0, l1);
    st_bf2(l + (size_t)i * 4 + 2, l2, l3);
}

// W[k][n] (512x512) -> T[n][k] split hi/lo
__global__ void __launch_bounds__(256) split_wT(const float* __restrict__ W,
                                                __nv_bfloat16* __restrict__ Th,
                                                __nv_bfloat16* __restrict__ Tl) {
    __shared__ float tile[32][33];
    int tx = threadIdx.x & 31, ty = threadIdx.x >> 5;  // 32 x 8
    int n0 = blockIdx.x * 32, k0 = blockIdx.y * 32;
#pragma unroll
    for (int i = 0; i < 4; i++)
        tile[ty + i * 8][tx] = W[(size_t)(k0 + ty + i * 8) * 512 + n0 + tx];
    __syncthreads();
#pragma unroll
    for (int i = 0; i < 4; i++) {
        float v = tile[tx][ty + i * 8];
        __nv_bfloat16 h, l;
        split_bf(v, h, l);
        Th[(size_t)(n0 + ty + i * 8) * 512 + k0 + tx] = h;
        Tl[(size_t)(n0 + ty + i * 8) * 512 + k0 + tx] = l;
    }
}

// 16-bit [n][t][d] -> [n][d][t]
__global__ void __launch_bounds__(256) transpose_v(
    const uint16_t* __restrict__ in, uint16_t* __restrict__ out) {
    __shared__ uint16_t tile[32][33];
    int tx = threadIdx.x & 31, ty = threadIdx.x >> 5;  // 32 x 8
    int n = blockIdx.z;
    int t0 = blockIdx.x * 32, d0 = blockIdx.y * 32;
    const uint16_t* src = in + ((size_t)n * 2048 + t0) * 64 + d0;
#pragma unroll
    for (int i = 0; i < 4; i++)
        tile[ty + i * 8][tx] = src[(size_t)(ty + i * 8) * 64 + tx];
    __syncthreads();
    uint16_t* dst = out + ((size_t)n * 64 + d0) * 2048 + t0;
#pragma unroll
    for (int i = 0; i < 4; i++)
        dst[(size_t)(ty + i * 8) * 2048 + tx] = tile[tx][ty + i * 8];
}

// E fp32 [d=64][s=1024] -> E^T fp16 [s][d]
__global__ void __launch_bounds__(256) conv_eT(const float* __restrict__ E,
                                               __half* __restrict__ Et) {
    __shared__ float tile[32][33];
    int tx = threadIdx.x & 31, ty = threadIdx.x >> 5;
    int s0 = blockIdx.x * 32, d0 = blockIdx.y * 32;
#pragma unroll
    for (int i = 0; i < 4; i++)
        tile[ty + i * 8][tx] = E[(size_t)(d0 + ty + i * 8) * 1024 + s0 + tx];
    __syncthreads();
#pragma unroll
    for (int i = 0; i < 4; i++)
        Et[(size_t)(s0 + ty + i * 8) * 64 + d0 + tx] =
            __float2half_rn(tile[tx][ty + i * 8]);
}

// ---------------- pre-split bf16x3 GEMM with cp.async double buffer -----------
// EPI=0: fp32 out. EPI=3: head-scatter fp16 hi only.
constexpr int AS2 = 40;
constexpr int TSZ = 128 * AS2;

template <int EPI>
__global__ void __launch_bounds__(256, 1) gemm_ps(
    const __nv_bfloat16* __restrict__ Ah_g, const __nv_bfloat16* __restrict__ Al_g,
    const __nv_bfloat16* __restrict__ Th_g, const __nv_bfloat16* __restrict__ Tl_g,
    float* __restrict__ outF, void* __restrict__ outH, int T) {
    extern __shared__ __nv_bfloat16 smg[];

    const int tid = threadIdx.x;
    const int lane = tid & 31, wid = tid >> 5;
    const int wm = wid >> 2, wn = wid & 3;  // 2 x 4 warps
    const int row0 = blockIdx.x * 128, col0 = blockIdx.y * 128;
    const int g = lane >> 2, t2 = (lane & 3) * 2;

    const int lr = tid >> 2;
    const int lc = (tid & 3) * 8;

    float acc[4][4][4] = {};

    {
        __nv_bfloat16* Ah = smg;
        __nv_bfloat16* Al = Ah + TSZ;
        __nv_bfloat16* Bh = Al + TSZ;
        __nv_bfloat16* Bl = Bh + TSZ;
#pragma unroll
        for (int half = 0; half < 2; half++) {
            int r = lr + half * 64;
            cp16(smem_u32(Ah + r * AS2 + lc), Ah_g + (size_t)(row0 + r) * 512 + lc);
            cp16(smem_u32(Al + r * AS2 + lc), Al_g + (size_t)(row0 + r) * 512 + lc);
            cp16(smem_u32(Bh + r * AS2 + lc), Th_g + (size_t)(col0 + r) * 512 + lc);
            cp16(smem_u32(Bl + r * AS2 + lc), Tl_g + (size_t)(col0 + r) * 512 + lc);
        }
        cp_commit();
    }

    int buf = 0;
    for (int kk = 0; kk < 512; kk += 32) {
        if (kk + 32 < 512) {
            __nv_bfloat16* Ah = smg + (buf ^ 1) * 4 * TSZ;
            __nv_bfloat16* Al = Ah + TSZ;
            __nv_bfloat16* Bh = Al + TSZ;
            __nv_bfloat16* Bl = Bh + TSZ;
            int kn = kk + 32;
#pragma unroll
            for (int half = 0; half < 2; half++) {
                int r = lr + half * 64;
                cp16(smem_u32(Ah + r * AS2 + lc),
                     Ah_g + (size_t)(row0 + r) * 512 + kn + lc);
                cp16(smem_u32(Al + r * AS2 + lc),
                     Al_g + (size_t)(row0 + r) * 512 + kn + lc);
                cp16(smem_u32(Bh + r * AS2 + lc),
                     Th_g + (size_t)(col0 + r) * 512 + kn + lc);
                cp16(smem_u32(Bl + r * AS2 + lc),
                     Tl_g + (size_t)(col0 + r) * 512 + kn + lc);
            }
            cp_commit();
            cp_wait<1>();
        } else {
            cp_wait<0>();
        }
        __syncthreads();

        const __nv_bfloat16* Ah = smg + buf * 4 * TSZ;
        const __nv_bfloat16* Al = Ah + TSZ;
        const __nv_bfloat16* Bh = Al + TSZ;
        const __nv_bfloat16* Bl = Bh + TSZ;
#pragma unroll
        for (int ks = 0; ks < 32; ks += 16) {
            uint32_t ah[4][4], al[4][4], bh[4][2], bl[4][2];
#pragma unroll
            for (int mf = 0; mf < 4; mf++) {
                int rb = wm * 64 + mf * 16 + g;
                ah[mf][0] = *(uint32_t*)&Ah[rb * AS2 + ks + t2];
                ah[mf][1] = *(uint32_t*)&Ah[(rb + 8) * AS2 + ks + t2];
                ah[mf][2] = *(uint32_t*)&Ah[rb * AS2 + ks + 8 + t2];
                ah[mf][3] = *(uint32_t*)&Ah[(rb + 8) * AS2 + ks + 8 + t2];
                al[mf][0] = *(uint32_t*)&Al[rb * AS2 + ks + t2];
                al[mf][1] = *(uint32_t*)&Al[(rb + 8) * AS2 + ks + t2];
                al[mf][2] = *(uint32_t*)&Al[rb * AS2 + ks + 8 + t2];
                al[mf][3] = *(uint32_t*)&Al[(rb + 8) * AS2 + ks + 8 + t2];
            }
#pragma unroll
            for (int nf = 0; nf < 4; nf++) {
                int cb = wn * 32 + nf * 8 + g;
                bh[nf][0] = *(uint32_t*)&Bh[cb * AS2 + ks + t2];
                bh[nf][1] = *(uint32_t*)&Bh[cb * AS2 + ks + 8 + t2];
                bl[nf][0] = *(uint32_t*)&Bl[cb * AS2 + ks + t2];
                bl[nf][1] = *(uint32_t*)&Bl[cb * AS2 + ks + 8 + t2];
            }
#pragma unroll
            for (int mf = 0; mf < 4; mf++)
#pragma unroll
                for (int nf = 0; nf < 4; nf++) {
                    mma_bf16(acc[mf][nf], ah[mf][0], ah[mf][1], ah[mf][2],
                             ah[mf][3], bh[nf][0], bh[nf][1]);
                    mma_bf16(acc[mf][nf], ah[mf][0], ah[mf][1], ah[mf][2],
                             ah[mf][3], bl[nf][0], bl[nf][1]);
                    mma_bf16(acc[mf][nf], al[mf][0], al[mf][1], al[mf][2],
                             al[mf][3], bh[nf][0], bh[nf][1]);
                }
        }
        __syncthreads();
        buf ^= 1;
    }

#pragma unroll
    for (int mf = 0; mf < 4; mf++) {
#pragma unroll
        for (int nf = 0; nf < 4; nf++) {
            int rr = row0 + wm * 64 + mf * 16 + g;
            int cc = col0 + wn * 32 + nf * 8 + t2;
            if (EPI == 0) {
                *(float2*)&outF[(size_t)rr * 512 + cc] =
                    make_float2(acc[mf][nf][0], acc[mf][nf][1]);
                *(float2*)&outF[(size_t)(rr + 8) * 512 + cc] =
                    make_float2(acc[mf][nf][2], acc[mf][nf][3]);
            } else {
                int head = cc >> 6, d = cc & 63;
#pragma unroll
                for (int rh = 0; rh < 2; rh++) {
                    int grow = rr + rh * 8;
                    int b = grow / T, t = grow - b * T;
                    size_t idx = (((size_t)(b * 8 + head) * T + t) << 6) + d;
                    st_h2((__half*)outH + idx,
                          __float2half_rn(acc[mf][nf][rh * 2 + 0]),
                          __float2half_rn(acc[mf][nf][rh * 2 + 1]));
                }
            }
        }
    }
}

// ---------------- fused banded attention v11 -----------------------------------
// fp16-single Q/K/V: 1-pass QK, 1-pass QE, 1-pass PV; in-register fp16 P;
// warp-local online softmax, exact cross-warp merge at end.
__global__ void __launch_bounds__(256, 1) attn_tc11(
    const __half* __restrict__ Qg, const __half* __restrict__ Kg,
    const __half* __restrict__ Vth, const __half* __restrict__ Et,
    __nv_bfloat16* __restrict__ Ch, __nv_bfloat16* __restrict__ Cl) {
    constexpr int QS = 72, KS = 72, ES = 72, VS = 200, QES = 132, OS = 68;
    extern __shared__ char smraw[];
    __half* Qsh = (__half*)smraw;                // [64][QS]
    __half* Ksh = Qsh + 64 * QS;                 // [192][KS]
    __half* Esh = Ksh + 192 * KS;                // [128][ES]
    __half* Vsh = Esh + 128 * ES;                // [64][VS]
    float* QEs = (float*)(Vsh + 64 * VS);        // [64][QES]
    float* mls = QEs + 64 * QES;                 // [4][64]
    float* lls = mls + 256;                      // [4][64]
    // epilogue-only alias (K/E/V regions dead after last chunk): 69632 B needed,
    // K+E+V = 27648+18432+25600 = 71680 B available.
    float* Ored = (float*)Ksh;                   // [8 warp][32][OS]

    const int tid = threadIdx.x, lane = tid & 31, wid = tid >> 5;
    const int wm = wid >> 2, wn = wid & 3;  // 2 x 4 warps
    const int g = lane >> 2, t2 = (lane & 3) * 2;
    const int n = blockIdx.y, m0 = blockIdx.x * 64;
    const float SCl2 = 0.125f * 1.4426950408889634f;

    auto issue_KE = [&](int c) {
        const size_t kbase = ((size_t)n * 2048 + m0 + c * 128) << 6;
        const __half* sh = Kg + kbase;
#pragma unroll
        for (int it = 0; it < 6; it++) {
            int f = tid + it * 256;
            int kr = f >> 3, j = (f & 7) * 8;
            cp16(smem_u32(Ksh + kr * KS + j), sh + f * 8);
        }
        const __half* es = Et + (size_t)(c * 128) * 64;
#pragma unroll
        for (int it = 0; it < 4; it++) {
            int f = tid + it * 256;
            int s = f >> 3, j = (f & 7) * 8;
            cp16(smem_u32(Esh + s * ES + j), es + f * 8);
        }
    };
    auto issue_V = [&](int c) {
        const __half* vh = Vth + (size_t)n * 64 * 2048 + m0 + c * 128;
#pragma unroll
        for (int it = 0; it < 6; it++) {
            int f = tid + it * 256;
            int d = f / 24, j = f - d * 24;
            cp16(smem_u32(Vsh + d * VS + j * 8), vh + (size_t)d * 2048 + j * 8);
        }
    };

    // stage Q tile (fp16 single)
    {
        const uint4* sh = (const uint4*)(Qg + (((size_t)n * 1024 + m0) << 6));
#pragma unroll
        for (int it = 0; it < 2; it++) {
            int f = tid + it * 256;
            int m = f >> 3, j = f & 7;
            ((uint4*)(Qsh + m * QS))[j] = sh[f];
        }
    }

    issue_KE(0);
    cp_commit();
    issue_V(0);
    cp_commit();

    // warp-local state
    float o[2][8][4] = {};
    float mreg[2][2] = {{-1e30f, -1e30f}, {-1e30f, -1e30f}};
    float lreg[2][2] = {};

    for (int c = 0; c < 8; c++) {
        cp_wait<1>();  // KE(c) ready; V(c) may be in flight
        __syncthreads();

        // ---- fused QK (1 pass) + QE (1 pass) ----
        float sAcc[2][6][4] = {};
        float qeAcc[2][4][4] = {};
#pragma unroll
        for (int ks = 0; ks < 64; ks += 16) {
            uint32_t ah[2][4];
#pragma unroll
            for (int mf = 0; mf < 2; mf++) {
                int rb = wm * 32 + mf * 16 + g;
                ah[mf][0] = *(uint32_t*)&Qsh[rb * QS + ks + t2];
                ah[mf][1] = *(uint32_t*)&Qsh[(rb + 8) * QS + ks + t2];
                ah[mf][2] = *(uint32_t*)&Qsh[rb * QS + ks + 8 + t2];
                ah[mf][3] = *(uint32_t*)&Qsh[(rb + 8) * QS + ks + 8 + t2];
            }
#pragma unroll
            for (int nf = 0; nf < 6; nf++) {
                int cb = wn * 48 + nf * 8 + g;
                uint32_t kb0 = *(uint32_t*)&Ksh[cb * KS + ks + t2];
                uint32_t kb1 = *(uint32_t*)&Ksh[cb * KS + ks + 8 + t2];
#pragma unroll
                for (int mf = 0; mf < 2; mf++)
                    mma_f16(sAcc[mf][nf], ah[mf][0], ah[mf][1], ah[mf][2],
                            ah[mf][3], kb0, kb1);
            }
#pragma unroll
            for (int nf = 0; nf < 4; nf++) {
                int cb = wn * 32 + nf * 8 + g;
                uint32_t eb0 = *(uint32_t*)&Esh[cb * ES + ks + t2];
                uint32_t eb1 = *(uint32_t*)&Esh[cb * ES + ks + 8 + t2];
#pragma unroll
                for (int mf = 0; mf < 2; mf++)
                    mma_f16(qeAcc[mf][nf], ah[mf][0], ah[mf][1], ah[mf][2],
                            ah[mf][3], eb0, eb1);
            }
        }
        // stage QE fragments (diagonal gather needs smem)
#pragma unroll
        for (int mf = 0; mf < 2; mf++) {
            int R = wm * 32 + mf * 16 + g;
#pragma unroll
            for (int nf = 0; nf < 4; nf++) {
                int cc = wn * 32 + nf * 8 + t2;
                *(float2*)&QEs[R * QES + cc] =
                    make_float2(qeAcc[mf][nf][0], qeAcc[mf][nf][1]);
                *(float2*)&QEs[(R + 8) * QES + cc] =
                    make_float2(qeAcc[mf][nf][2], qeAcc[mf][nf][3]);
            }
        }
        __syncthreads();  // QEs visible to all warps; K/E consumption done

        if (c < 7) issue_KE(c + 1);
        cp_commit();

        // ---- warp-local masked softmax over this warp's 48-key slice ----
        uint32_t pf[2][3][4];
#pragma unroll
        for (int mf = 0; mf < 2; mf++) {
            int R = wm * 32 + mf * 16 + g;
            float mx0 = -3e38f, mx1 = -3e38f;
#pragma unroll
            for (int nf = 0; nf < 6; nf++) {
                int cc = wn * 48 + nf * 8 + t2;
#pragma unroll
                for (int e = 0; e < 4; e++) {
                    int r = R + ((e >> 1) << 3);
                    int col = cc + (e & 1);
                    int diff = col - r;
                    float z = -3e38f;
                    if ((unsigned)diff < 128u)
                        z = sAcc[mf][nf][e] + QEs[r * QES + diff];
                    sAcc[mf][nf][e] = z;
                    if (e < 2) mx0 = fmaxf(mx0, z);
                    else mx1 = fmaxf(mx1, z);
                }
            }
            mx0 = fmaxf(mx0, __shfl_xor_sync(0xffffffffu, mx0, 1));
            mx0 = fmaxf(mx0, __shfl_xor_sync(0xffffffffu, mx0, 2));
            mx1 = fmaxf(mx1, __shfl_xor_sync(0xffffffffu, mx1, 1));
            mx1 = fmaxf(mx1, __shfl_xor_sync(0xffffffffu, mx1, 2));
            float mn0 = fmaxf(mreg[mf][0], mx0 * SCl2);
            float mn1 = fmaxf(mreg[mf][1], mx1 * SCl2);
            float al0 = exp2f(mreg[mf][0] - mn0);
            float al1 = exp2f(mreg[mf][1] - mn1);
            float sum0 = 0.f, sum1 = 0.f;
#pragma unroll
            for (int nf = 0; nf < 6; nf++) {
                float p0 = exp2f(sAcc[mf][nf][0] * SCl2 - mn0);
                float p1 = exp2f(sAcc[mf][nf][1] * SCl2 - mn0);
                float p2 = exp2f(sAcc[mf][nf][2] * SCl2 - mn1);
                float p3 = exp2f(sAcc[mf][nf][3] * SCl2 - mn1);
                sum0 += p0 + p1;
                sum1 += p2 + p3;
                int k = nf >> 1, hf = (nf & 1) * 2;
                pf[mf][k][hf + 0] = pack_h2(p0, p1);
                pf[mf][k][hf + 1] = pack_h2(p2, p3);
            }
            sum0 += __shfl_xor_sync(0xffffffffu, sum0, 1);
            sum0 += __shfl_xor_sync(0xffffffffu, sum0, 2);
            sum1 += __shfl_xor_sync(0xffffffffu, sum1, 1);
            sum1 += __shfl_xor_sync(0xffffffffu, sum1, 2);
            lreg[mf][0] = lreg[mf][0] * al0 + sum0;
            lreg[mf][1] = lreg[mf][1] * al1 + sum1;
            mreg[mf][0] = mn0;
            mreg[mf][1] = mn1;
#pragma unroll
            for (int nfd = 0; nfd < 8; nfd++) {
                o[mf][nfd][0] *= al0;
                o[mf][nfd][1] *= al0;
                o[mf][nfd][2] *= al1;
                o[mf][nfd][3] *= al1;
            }
        }
        cp_wait<1>();  // V(c) ready (KE(c+1) may still be in flight)
        __syncthreads();

        // ---- PV: warp's 48-key slice x all 64 d; fp16, 1 pass ----
#pragma unroll
        for (int k = 0; k < 3; k++) {
            int ks = wn * 48 + k * 16;
#pragma unroll
            for (int nfd = 0; nfd < 8; nfd++) {
                int cb = nfd * 8 + g;
                uint32_t vh0 = *(uint32_t*)&Vsh[cb * VS + ks + t2];
                uint32_t vh1 = *(uint32_t*)&Vsh[cb * VS + ks + 8 + t2];
#pragma unroll
                for (int mf = 0; mf < 2; mf++)
                    mma_f16(o[mf][nfd], pf[mf][k][0], pf[mf][k][1],
                            pf[mf][k][2], pf[mf][k][3], vh0, vh1);
            }
        }
        __syncthreads();  // V consumption done before overwrite

        if (c < 7) issue_V(c + 1);
        cp_commit();
    }

    // ---- epilogue: cross-warp (m,l,O) merge + normalize + store ----
    {
        int wbase = (wm * 4 + wn) * 32;
#pragma unroll
        for (int mf = 0; mf < 2; mf++) {
            int lr0 = mf * 16 + g;
            if ((lane & 3) == 0) {
                mls[wn * 64 + wm * 32 + lr0] = mreg[mf][0];
                mls[wn * 64 + wm * 32 + lr0 + 8] = mreg[mf][1];
                lls[wn * 64 + wm * 32 + lr0] = lreg[mf][0];
                lls[wn * 64 + wm * 32 + lr0 + 8] = lreg[mf][1];
            }
#pragma unroll
            for (int nfd = 0; nfd < 8; nfd++) {
                int cc = nfd * 8 + t2;
                *(float2*)&Ored[(wbase + lr0) * OS + cc] =
                    make_float2(o[mf][nfd][0], o[mf][nfd][1]);
                *(float2*)&Ored[(wbase + lr0 + 8) * OS + cc] =
                    make_float2(o[mf][nfd][2], o[mf][nfd][3]);
            }
        }
    }
    __syncthreads();
    {
        const int b = n >> 3, kh = n & 7;
#pragma unroll
        for (int u = 0; u < 4; u++) {
            int id = tid + u * 256;       // 0..1023
            int r = id >> 4;              // 0..63
            int c4 = (id & 15) * 4;       // 0..60
            int wmr = r >> 5, lr = r & 31;
            float mw0 = mls[r], mw1 = mls[64 + r], mw2 = mls[128 + r],
                  mw3 = mls[192 + r];
            float ms = fmaxf(fmaxf(mw0, mw1), fmaxf(mw2, mw3));
            float e0 = exp2f(mw0 - ms), e1 = exp2f(mw1 - ms),
                  e2 = exp2f(mw2 - ms), e3 = exp2f(mw3 - ms);
            float lt = lls[r] * e0 + lls[64 + r] * e1 + lls[128 + r] * e2 +
                       lls[192 + r] * e3;
            float4 s0 = *(float4*)&Ored[((wmr * 4 + 0) * 32 + lr) * OS + c4];
            float4 s1 = *(float4*)&Ored[((wmr * 4 + 1) * 32 + lr) * OS + c4];
            float4 s2 = *(float4*)&Ored[((wmr * 4 + 2) * 32 + lr) * OS + c4];
            float4 s3 = *(float4*)&Ored[((wmr * 4 + 3) * 32 + lr) * OS + c4];
            float inv = 1.0f / lt;
            float x = (s0.x * e0 + s1.x * e1 + s2.x * e2 + s3.x * e3) * inv;
            float y = (s0.y * e0 + s1.y * e1 + s2.y * e2 + s3.y * e3) * inv;
            float z = (s0.z * e0 + s1.z * e1 + s2.z * e2 + s3.z * e3) * inv;
            float w = (s0.w * e0 + s1.w * e1 + s2.w * e2 + s3.w * e3) * inv;
            __nv_bfloat16 h0, l0, h1, l1, h2, l2, h3, l3;
            split_bf(x, h0, l0);
            split_bf(y, h1, l1);
            split_bf(z, h2, l2);
            split_bf(w, h3, l3);
            size_t base = ((size_t)b * 1024 + m0 + r) * 512 + kh * 64 + c4;
            st_bf2(&Ch[base], h0, h1);
            st_bf2(&Ch[base + 2], h2, h3);
            st_bf2(&Cl[base], l0, l1);
            st_bf2(&Cl[base + 2], l2, l3);
        }
    }
}

// ---------------- launcher ----------------------------------------------------
extern "C" void kernel_launch(void* const* d_in, const int* in_sizes, int n_in,
                              void* d_out, int out_size) {
    const float* query = (const float*)d_in[0];
    const float* key = (const float*)d_in[1];
    const float* value = (const float*)d_in[2];
    const float* pos = (const float*)d_in[3];
    const float* Wq = (const float*)d_in[4];
    const float* Wk = (const float*)d_in[5];
    const float* Wv = (const float*)d_in[6];
    const float* Wo = (const float*)d_in[7];
    float* out = (float*)d_out;

    __half *qg, *kg, *vh, *vth, *et;
    __nv_bfloat16 *xqh, *xql, *xkh, *xkl, *xvh, *xvl;
    __nv_bfloat16 *wqth, *wqtl, *wkth, *wktl, *wvth, *wvtl, *woth, *wotl;
    __nv_bfloat16 *ch, *cl;
    cudaGetSymbolAddress((void**)&qg, g_Qh);
    cudaGetSymbolAddress((void**)&kg, g_Kh);
    cudaGetSymbolAddress((void**)&vh, g_Vh);
    cudaGetSymbolAddress((void**)&vth, g_Vth);
    cudaGetSymbolAddress((void**)&et, g_Et);
    cudaGetSymbolAddress((void**)&xqh, g_Xqh);
    cudaGetSymbolAddress((void**)&xql, g_Xql);
    cudaGetSymbolAddress((void**)&xkh, g_Xkh);
    cudaGetSymbolAddress((void**)&xkl, g_Xkl);
    cudaGetSymbolAddress((void**)&xvh, g_Xvh);
    cudaGetSymbolAddress((void**)&xvl, g_Xvl);
    cudaGetSymbolAddress((void**)&wqth, g_WqTh);
    cudaGetSymbolAddress((void**)&wqtl, g_WqTl);
    cudaGetSymbolAddress((void**)&wkth, g_WkTh);
    cudaGetSymbolAddress((void**)&wktl, g_WkTl);
    cudaGetSymbolAddress((void**)&wvth, g_WvTh);
    cudaGetSymbolAddress((void**)&wvtl, g_WvTl);
    cudaGetSymbolAddress((void**)&woth, g_WoTh);
    cudaGetSymbolAddress((void**)&wotl, g_WoTl);
    cudaGetSymbolAddress((void**)&ch, g_Ch);
    cudaGetSymbolAddress((void**)&cl, g_Cl);

    // splits / transposes of inputs
    split_x<<<4096, 256>>>(query, xqh, xql, 1048576);
    split_x<<<8192, 256>>>(key, xkh, xkl, 2097152);
    split_x<<<8192, 256>>>(value, xvh, xvl, 2097152);
    split_wT<<<dim3(16, 16), dim3(256)>>>(Wq, wqth, wqtl);
    split_wT<<<dim3(16, 16), dim3(256)>>>(Wk, wkth, wktl);
    split_wT<<<dim3(16, 16), dim3(256)>>>(Wv, wvth, wvtl);
    split_wT<<<dim3(16, 16), dim3(256)>>>(Wo, woth, wotl);
    conv_eT<<<dim3(32, 2), 256>>>(pos, et);

    // projections
    const int gsm = 2 * 4 * TSZ * 2;  // 81920 bytes
    cudaFuncSetAttribute(gemm_ps<0>, cudaFuncAttributeMaxDynamicSharedMemorySize,
                         gsm);
    cudaFuncSetAttribute(gemm_ps<3>, cudaFuncAttributeMaxDynamicSharedMemorySize,
                         gsm);
    gemm_ps<3><<<dim3(64, 4), 256, gsm>>>(xqh, xql, wqth, wqtl, nullptr, qg,
                                          1024);
    gemm_ps<3><<<dim3(128, 4), 256, gsm>>>(xkh, xkl, wkth, wktl, nullptr, kg,
                                           2048);
    gemm_ps<3><<<dim3(128, 4), 256, gsm>>>(xvh, xvl, wvth, wvtl, nullptr, vh,
                                           2048);

    // V transpose to [n][d][t]
    transpose_v<<<dim3(64, 2, 64), 256>>>((const uint16_t*)vh, (uint16_t*)vth);

    // attention
    const int smem_bytes =
        (64 * 72 + 192 * 72 + 128 * 72 + 64 * 200) * 2 +
        (64 * 132 + 256 + 256) * 4;  // 115200
    cudaFuncSetAttribute(attn_tc11, cudaFuncAttributeMaxDynamicSharedMemorySize,
                         smem_bytes);
    attn_tc11<<<dim3(16, 64), 256, smem_bytes>>>(qg, kg, vth, et, ch, cl);

    // output projection
    gemm_ps<0><<<dim3(64, 4), 256, gsm>>>(ch, cl, woth, wotl, out, nullptr,
                                          1024);
}

// round 14
// speedup vs baseline: 2.9359x; 1.2924x over previous
#include <cuda_runtime.h>
#include <cuda_bf16.h>
#include <cuda_fp16.h>
#include <stdint.h>
#include <math.h>

// B=8, M=1024, H=512, K=8 heads, D=64, SPAN=1024, MK=2048
#define DINLINE __device__ __forceinline__

// ---------------- scratch ----------------------------------------------------
__device__ __align__(16) __half g_Qh[64 * 1024 * 64];          // fp16 Q (single)
__device__ __align__(16) __half g_Kh[64 * 2048 * 64];          // fp16 K (single)
__device__ __align__(16) __half g_Vh[64 * 2048 * 64];          // fp16 V (single)
__device__ __align__(16) __half g_Vth[64 * 64 * 2048];         // V^T [n][d][t]
__device__ __align__(16) __half g_Et[1024 * 64];               // E^T [s][d] fp16
__device__ __align__(16) __half g_Xq16[8 * 1024 * 512];        // fp16 inputs
__device__ __align__(16) __half g_Xk16[8 * 2048 * 512];
__device__ __align__(16) __half g_Xv16[8 * 2048 * 512];
__device__ __align__(16) __half g_WqT16[512 * 512];            // fp16 W^T
__device__ __align__(16) __half g_WkT16[512 * 512];
__device__ __align__(16) __half g_WvT16[512 * 512];
__device__ __align__(16) __nv_bfloat16 g_WoTh[512 * 512], g_WoTl[512 * 512];
__device__ __align__(16) __nv_bfloat16 g_Ch[8 * 1024 * 512], g_Cl[8 * 1024 * 512];

// ---------------- helpers ----------------------------------------------------
DINLINE void mma_bf16(float c[4], uint32_t a0, uint32_t a1, uint32_t a2,
                      uint32_t a3, uint32_t b0, uint32_t b1) {
    asm volatile(
        "mma.sync.aligned.m16n8k16.row.col.f32.bf16.bf16.f32 "
        "{%0,%1,%2,%3}, {%4,%5,%6,%7}, {%8,%9}, {%0,%1,%2,%3};\n"
        : "+f"(c[0]), "+f"(c[1]), "+f"(c[2]), "+f"(c[3])
        : "r"(a0), "r"(a1), "r"(a2), "r"(a3), "r"(b0), "r"(b1));
}

DINLINE void mma_f16(float c[4], uint32_t a0, uint32_t a1, uint32_t a2,
                     uint32_t a3, uint32_t b0, uint32_t b1) {
    asm volatile(
        "mma.sync.aligned.m16n8k16.row.col.f32.f16.f16.f32 "
        "{%0,%1,%2,%3}, {%4,%5,%6,%7}, {%8,%9}, {%0,%1,%2,%3};\n"
        : "+f"(c[0]), "+f"(c[1]), "+f"(c[2]), "+f"(c[3])
        : "r"(a0), "r"(a1), "r"(a2), "r"(a3), "r"(b0), "r"(b1));
}

DINLINE uint32_t smem_u32(const void* p) {
    return (uint32_t)__cvta_generic_to_shared(p);
}

DINLINE void cp16(uint32_t dst, const void* src) {
    asm volatile("cp.async.cg.shared.global [%0], [%1], 16;\n" ::"r"(dst),
                 "l"(src));
}
DINLINE void cp_commit() { asm volatile("cp.async.commit_group;\n" ::); }
template <int N>
DINLINE void cp_wait() {
    asm volatile("cp.async.wait_group %0;\n" ::"n"(N));
}

DINLINE void split_bf(float x, __nv_bfloat16& h, __nv_bfloat16& l) {
    h = __float2bfloat16_rn(x);
    l = __float2bfloat16_rn(x - __bfloat162float(h));
}

DINLINE void st_bf2(__nv_bfloat16* p, __nv_bfloat16 a, __nv_bfloat16 b) {
    __nv_bfloat162 t;
    t.x = a;
    t.y = b;
    *(__nv_bfloat162*)p = t;
}

DINLINE void st_h2(__half* p, __half a, __half b) {
    __half2 t;
    t.x = a;
    t.y = b;
    *(__half2*)p = t;
}

DINLINE uint32_t pack_h2(float a, float b) {
    __half2 t = __floats2half2_rn(a, b);
    return *(uint32_t*)&t;
}

// ---------------- prep kernels --------------------------------------------------
// fp32 -> fp16 single
__global__ void __launch_bounds__(256) conv_x(const float* __restrict__ in,
                                              __half* __restrict__ out, int n4) {
    int i = blockIdx.x * blockDim.x + threadIdx.x;
    if (i >= n4) return;
    float4 v = ((const float4*)in)[i];
    __half2 a = __floats2half2_rn(v.x, v.y);
    __half2 b = __floats2half2_rn(v.z, v.w);
    ((__half2*)out)[i * 2] = a;
    ((__half2*)out)[i * 2 + 1] = b;
}

// W[k][n] fp32 -> T[n][k] fp16 single
__global__ void __launch_bounds__(256) conv_wT_h(const float* __restrict__ W,
                                                 __half* __restrict__ Th) {
    __shared__ float tile[32][33];
    int tx = threadIdx.x & 31, ty = threadIdx.x >> 5;  // 32 x 8
    int n0 = blockIdx.x * 32, k0 = blockIdx.y * 32;
#pragma unroll
    for (int i = 0; i < 4; i++)
        tile[ty + i * 8][tx] = W[(size_t)(k0 + ty + i * 8) * 512 + n0 + tx];
    __syncthreads();
#pragma unroll
    for (int i = 0; i < 4; i++)
        Th[(size_t)(n0 + ty + i * 8) * 512 + k0 + tx] =
            __float2half_rn(tile[tx][ty + i * 8]);
}

// W[k][n] fp32 -> T[n][k] bf16 hi/lo (for Wo)
__global__ void __launch_bounds__(256) split_wT(const float* __restrict__ W,
                                                __nv_bfloat16* __restrict__ Th,
                                                __nv_bfloat16* __restrict__ Tl) {
    __shared__ float tile[32][33];
    int tx = threadIdx.x & 31, ty = threadIdx.x >> 5;
    int n0 = blockIdx.x * 32, k0 = blockIdx.y * 32;
#pragma unroll
    for (int i = 0; i < 4; i++)
        tile[ty + i * 8][tx] = W[(size_t)(k0 + ty + i * 8) * 512 + n0 + tx];
    __syncthreads();
#pragma unroll
    for (int i = 0; i < 4; i++) {
        float v = tile[tx][ty + i * 8];
        __nv_bfloat16 h, l;
        split_bf(v, h, l);
        Th[(size_t)(n0 + ty + i * 8) * 512 + k0 + tx] = h;
        Tl[(size_t)(n0 + ty + i * 8) * 512 + k0 + tx] = l;
    }
}

// 16-bit [n][t][d] -> [n][d][t]
__global__ void __launch_bounds__(256) transpose_v(
    const uint16_t* __restrict__ in, uint16_t* __restrict__ out) {
    __shared__ uint16_t tile[32][33];
    int tx = threadIdx.x & 31, ty = threadIdx.x >> 5;
    int n = blockIdx.z;
    int t0 = blockIdx.x * 32, d0 = blockIdx.y * 32;
    const uint16_t* src = in + ((size_t)n * 2048 + t0) * 64 + d0;
#pragma unroll
    for (int i = 0; i < 4; i++)
        tile[ty + i * 8][tx] = src[(size_t)(ty + i * 8) * 64 + tx];
    __syncthreads();
    uint16_t* dst = out + ((size_t)n * 64 + d0) * 2048 + t0;
#pragma unroll
    for (int i = 0; i < 4; i++)
        dst[(size_t)(ty + i * 8) * 2048 + tx] = tile[tx][ty + i * 8];
}

// E fp32 [d=64][s=1024] -> E^T fp16 [s][d]
__global__ void __launch_bounds__(256) conv_eT(const float* __restrict__ E,
                                               __half* __restrict__ Et) {
    __shared__ float tile[32][33];
    int tx = threadIdx.x & 31, ty = threadIdx.x >> 5;
    int s0 = blockIdx.x * 32, d0 = blockIdx.y * 32;
#pragma unroll
    for (int i = 0; i < 4; i++)
        tile[ty + i * 8][tx] = E[(size_t)(d0 + ty + i * 8) * 1024 + s0 + tx];
    __syncthreads();
#pragma unroll
    for (int i = 0; i < 4; i++)
        Et[(size_t)(s0 + ty + i * 8) * 64 + d0 + tx] =
            __float2half_rn(tile[tx][ty + i * 8]);
}

// ---------------- single-pass fp16 GEMM (Q/K/V projections) -------------------
// C[R,512] = A[R,512] @ W ; A fp16, W^T fp16 [n][k]. Head-scatter fp16 out.
constexpr int AS2 = 40;
constexpr int TSZ = 128 * AS2;

__global__ void __launch_bounds__(256, 1) gemm_h16(
    const __half* __restrict__ A_g, const __half* __restrict__ T_g,
    __half* __restrict__ outH, int T) {
    extern __shared__ __half smh[];

    const int tid = threadIdx.x;
    const int lane = tid & 31, wid = tid >> 5;
    const int wm = wid >> 2, wn = wid & 3;  // 2 x 4 warps
    const int row0 = blockIdx.x * 128, col0 = blockIdx.y * 128;
    const int g = lane >> 2, t2 = (lane & 3) * 2;

    const int lr = tid >> 2;
    const int lc = (tid & 3) * 8;

    float acc[4][4][4] = {};

    {
        __half* As = smh;
        __half* Bs = As + TSZ;
#pragma unroll
        for (int half = 0; half < 2; half++) {
            int r = lr + half * 64;
            cp16(smem_u32(As + r * AS2 + lc), A_g + (size_t)(row0 + r) * 512 + lc);
            cp16(smem_u32(Bs + r * AS2 + lc), T_g + (size_t)(col0 + r) * 512 + lc);
        }
        cp_commit();
    }

    int buf = 0;
    for (int kk = 0; kk < 512; kk += 32) {
        if (kk + 32 < 512) {
            __half* As = smh + (buf ^ 1) * 2 * TSZ;
            __half* Bs = As + TSZ;
            int kn = kk + 32;
#pragma unroll
            for (int half = 0; half < 2; half++) {
                int r = lr + half * 64;
                cp16(smem_u32(As + r * AS2 + lc),
                     A_g + (size_t)(row0 + r) * 512 + kn + lc);
                cp16(smem_u32(Bs + r * AS2 + lc),
                     T_g + (size_t)(col0 + r) * 512 + kn + lc);
            }
            cp_commit();
            cp_wait<1>();
        } else {
            cp_wait<0>();
        }
        __syncthreads();

        const __half* As = smh + buf * 2 * TSZ;
        const __half* Bs = As + TSZ;
#pragma unroll
        for (int ks = 0; ks < 32; ks += 16) {
            uint32_t a[4][4], b[4][2];
#pragma unroll
            for (int mf = 0; mf < 4; mf++) {
                int rb = wm * 64 + mf * 16 + g;
                a[mf][0] = *(uint32_t*)&As[rb * AS2 + ks + t2];
                a[mf][1] = *(uint32_t*)&As[(rb + 8) * AS2 + ks + t2];
                a[mf][2] = *(uint32_t*)&As[rb * AS2 + ks + 8 + t2];
                a[mf][3] = *(uint32_t*)&As[(rb + 8) * AS2 + ks + 8 + t2];
            }
#pragma unroll
            for (int nf = 0; nf < 4; nf++) {
                int cb = wn * 32 + nf * 8 + g;
                b[nf][0] = *(uint32_t*)&Bs[cb * AS2 + ks + t2];
                b[nf][1] = *(uint32_t*)&Bs[cb * AS2 + ks + 8 + t2];
            }
#pragma unroll
            for (int mf = 0; mf < 4; mf++)
#pragma unroll
                for (int nf = 0; nf < 4; nf++)
                    mma_f16(acc[mf][nf], a[mf][0], a[mf][1], a[mf][2],
                            a[mf][3], b[nf][0], b[nf][1]);
        }
        __syncthreads();
        buf ^= 1;
    }

#pragma unroll
    for (int mf = 0; mf < 4; mf++) {
#pragma unroll
        for (int nf = 0; nf < 4; nf++) {
            int rr = row0 + wm * 64 + mf * 16 + g;
            int cc = col0 + wn * 32 + nf * 8 + t2;
            int head = cc >> 6, d = cc & 63;
#pragma unroll
            for (int rh = 0; rh < 2; rh++) {
                int grow = rr + rh * 8;
                int b = grow / T, t = grow - b * T;
                size_t idx = (((size_t)(b * 8 + head) * T + t) << 6) + d;
                st_h2(outH + idx, __float2half_rn(acc[mf][nf][rh * 2 + 0]),
                      __float2half_rn(acc[mf][nf][rh * 2 + 1]));
            }
        }
    }
}

// ---------------- bf16x3 GEMM for output projection ---------------------------
__global__ void __launch_bounds__(256, 1) gemm_out(
    const __nv_bfloat16* __restrict__ Ah_g, const __nv_bfloat16* __restrict__ Al_g,
    const __nv_bfloat16* __restrict__ Th_g, const __nv_bfloat16* __restrict__ Tl_g,
    float* __restrict__ outF) {
    extern __shared__ __nv_bfloat16 smg[];

    const int tid = threadIdx.x;
    const int lane = tid & 31, wid = tid >> 5;
    const int wm = wid >> 2, wn = wid & 3;
    const int row0 = blockIdx.x * 128, col0 = blockIdx.y * 128;
    const int g = lane >> 2, t2 = (lane & 3) * 2;

    const int lr = tid >> 2;
    const int lc = (tid & 3) * 8;

    float acc[4][4][4] = {};

    {
        __nv_bfloat16* Ah = smg;
        __nv_bfloat16* Al = Ah + TSZ;
        __nv_bfloat16* Bh = Al + TSZ;
        __nv_bfloat16* Bl = Bh + TSZ;
#pragma unroll
        for (int half = 0; half < 2; half++) {
            int r = lr + half * 64;
            cp16(smem_u32(Ah + r * AS2 + lc), Ah_g + (size_t)(row0 + r) * 512 + lc);
            cp16(smem_u32(Al + r * AS2 + lc), Al_g + (size_t)(row0 + r) * 512 + lc);
            cp16(smem_u32(Bh + r * AS2 + lc), Th_g + (size_t)(col0 + r) * 512 + lc);
            cp16(smem_u32(Bl + r * AS2 + lc), Tl_g + (size_t)(col0 + r) * 512 + lc);
        }
        cp_commit();
    }

    int buf = 0;
    for (int kk = 0; kk < 512; kk += 32) {
        if (kk + 32 < 512) {
            __nv_bfloat16* Ah = smg + (buf ^ 1) * 4 * TSZ;
            __nv_bfloat16* Al = Ah + TSZ;
            __nv_bfloat16* Bh = Al + TSZ;
            __nv_bfloat16* Bl = Bh + TSZ;
            int kn = kk + 32;
#pragma unroll
            for (int half = 0; half < 2; half++) {
                int r = lr + half * 64;
                cp16(smem_u32(Ah + r * AS2 + lc),
                     Ah_g + (size_t)(row0 + r) * 512 + kn + lc);
                cp16(smem_u32(Al + r * AS2 + lc),
                     Al_g + (size_t)(row0 + r) * 512 + kn + lc);
                cp16(smem_u32(Bh + r * AS2 + lc),
                     Th_g + (size_t)(col0 + r) * 512 + kn + lc);
                cp16(smem_u32(Bl + r * AS2 + lc),
                     Tl_g + (size_t)(col0 + r) * 512 + kn + lc);
            }
            cp_commit();
            cp_wait<1>();
        } else {
            cp_wait<0>();
        }
        __syncthreads();

        const __nv_bfloat16* Ah = smg + buf * 4 * TSZ;
        const __nv_bfloat16* Al = Ah + TSZ;
        const __nv_bfloat16* Bh = Al + TSZ;
        const __nv_bfloat16* Bl = Bh + TSZ;
#pragma unroll
        for (int ks = 0; ks < 32; ks += 16) {
            uint32_t ah[4][4], al[4][4], bh[4][2], bl[4][2];
#pragma unroll
            for (int mf = 0; mf < 4; mf++) {
                int rb = wm * 64 + mf * 16 + g;
                ah[mf][0] = *(uint32_t*)&Ah[rb * AS2 + ks + t2];
                ah[mf][1] = *(uint32_t*)&Ah[(rb + 8) * AS2 + ks + t2];
                ah[mf][2] = *(uint32_t*)&Ah[rb * AS2 + ks + 8 + t2];
                ah[mf][3] = *(uint32_t*)&Ah[(rb + 8) * AS2 + ks + 8 + t2];
                al[mf][0] = *(uint32_t*)&Al[rb * AS2 + ks + t2];
                al[mf][1] = *(uint32_t*)&Al[(rb + 8) * AS2 + ks + t2];
                al[mf][2] = *(uint32_t*)&Al[rb * AS2 + ks + 8 + t2];
                al[mf][3] = *(uint32_t*)&Al[(rb + 8) * AS2 + ks + 8 + t2];
            }
#pragma unroll
            for (int nf = 0; nf < 4; nf++) {
                int cb = wn * 32 + nf * 8 + g;
                bh[nf][0] = *(uint32_t*)&Bh[cb * AS2 + ks + t2];
                bh[nf][1] = *(uint32_t*)&Bh[cb * AS2 + ks + 8 + t2];
                bl[nf][0] = *(uint32_t*)&Bl[cb * AS2 + ks + t2];
                bl[nf][1] = *(uint32_t*)&Bl[cb * AS2 + ks + 8 + t2];
            }
#pragma unroll
            for (int mf = 0; mf < 4; mf++)
#pragma unroll
                for (int nf = 0; nf < 4; nf++) {
                    mma_bf16(acc[mf][nf], ah[mf][0], ah[mf][1], ah[mf][2],
                             ah[mf][3], bh[nf][0], bh[nf][1]);
                    mma_bf16(acc[mf][nf], ah[mf][0], ah[mf][1], ah[mf][2],
                             ah[mf][3], bl[nf][0], bl[nf][1]);
                    mma_bf16(acc[mf][nf], al[mf][0], al[mf][1], al[mf][2],
                             al[mf][3], bh[nf][0], bh[nf][1]);
                }
        }
        __syncthreads();
        buf ^= 1;
    }

#pragma unroll
    for (int mf = 0; mf < 4; mf++) {
#pragma unroll
        for (int nf = 0; nf < 4; nf++) {
            int rr = row0 + wm * 64 + mf * 16 + g;
            int cc = col0 + wn * 32 + nf * 8 + t2;
            *(float2*)&outF[(size_t)rr * 512 + cc] =
                make_float2(acc[mf][nf][0], acc[mf][nf][1]);
            *(float2*)&outF[(size_t)(rr + 8) * 512 + cc] =
                make_float2(acc[mf][nf][2], acc[mf][nf][3]);
        }
    }
}

// ---------------- fused banded attention v11 (unchanged from round 13) ---------
__global__ void __launch_bounds__(256, 1) attn_tc11(
    const __half* __restrict__ Qg, const __half* __restrict__ Kg,
    const __half* __restrict__ Vth, const __half* __restrict__ Et,
    __nv_bfloat16* __restrict__ Ch, __nv_bfloat16* __restrict__ Cl) {
    constexpr int QS = 72, KS = 72, ES = 72, VS = 200, QES = 132, OS = 68;
    extern __shared__ char smraw[];
    __half* Qsh = (__half*)smraw;                // [64][QS]
    __half* Ksh = Qsh + 64 * QS;                 // [192][KS]
    __half* Esh = Ksh + 192 * KS;                // [128][ES]
    __half* Vsh = Esh + 128 * ES;                // [64][VS]
    float* QEs = (float*)(Vsh + 64 * VS);        // [64][QES]
    float* mls = QEs + 64 * QES;                 // [4][64]
    float* lls = mls + 256;                      // [4][64]
    float* Ored = (float*)Ksh;                   // epilogue alias

    const int tid = threadIdx.x, lane = tid & 31, wid = tid >> 5;
    const int wm = wid >> 2, wn = wid & 3;  // 2 x 4 warps
    const int g = lane >> 2, t2 = (lane & 3) * 2;
    const int n = blockIdx.y, m0 = blockIdx.x * 64;
    const float SCl2 = 0.125f * 1.4426950408889634f;

    auto issue_KE = [&](int c) {
        const size_t kbase = ((size_t)n * 2048 + m0 + c * 128) << 6;
        const __half* sh = Kg + kbase;
#pragma unroll
        for (int it = 0; it < 6; it++) {
            int f = tid + it * 256;
            int kr = f >> 3, j = (f & 7) * 8;
            cp16(smem_u32(Ksh + kr * KS + j), sh + f * 8);
        }
        const __half* es = Et + (size_t)(c * 128) * 64;
#pragma unroll
        for (int it = 0; it < 4; it++) {
            int f = tid + it * 256;
            int s = f >> 3, j = (f & 7) * 8;
            cp16(smem_u32(Esh + s * ES + j), es + f * 8);
        }
    };
    auto issue_V = [&](int c) {
        const __half* vh = Vth + (size_t)n * 64 * 2048 + m0 + c * 128;
#pragma unroll
        for (int it = 0; it < 6; it++) {
            int f = tid + it * 256;
            int d = f / 24, j = f - d * 24;
            cp16(smem_u32(Vsh + d * VS + j * 8), vh + (size_t)d * 2048 + j * 8);
        }
    };

    // stage Q tile (fp16 single)
    {
        const uint4* sh = (const uint4*)(Qg + (((size_t)n * 1024 + m0) << 6));
#pragma unroll
        for (int it = 0; it < 2; it++) {
            int f = tid + it * 256;
            int m = f >> 3, j = f & 7;
            ((uint4*)(Qsh + m * QS))[j] = sh[f];
        }
    }

    issue_KE(0);
    cp_commit();
    issue_V(0);
    cp_commit();

    float o[2][8][4] = {};
    float mreg[2][2] = {{-1e30f, -1e30f}, {-1e30f, -1e30f}};
    float lreg[2][2] = {};

    for (int c = 0; c < 8; c++) {
        cp_wait<1>();
        __syncthreads();

        // ---- fused QK (1 pass) + QE (1 pass) ----
        float sAcc[2][6][4] = {};
        float qeAcc[2][4][4] = {};
#pragma unroll
        for (int ks = 0; ks < 64; ks += 16) {
            uint32_t ah[2][4];
#pragma unroll
            for (int mf = 0; mf < 2; mf++) {
                int rb = wm * 32 + mf * 16 + g;
                ah[mf][0] = *(uint32_t*)&Qsh[rb * QS + ks + t2];
                ah[mf][1] = *(uint32_t*)&Qsh[(rb + 8) * QS + ks + t2];
                ah[mf][2] = *(uint32_t*)&Qsh[rb * QS + ks + 8 + t2];
                ah[mf][3] = *(uint32_t*)&Qsh[(rb + 8) * QS + ks + 8 + t2];
            }
#pragma unroll
            for (int nf = 0; nf < 6; nf++) {
                int cb = wn * 48 + nf * 8 + g;
                uint32_t kb0 = *(uint32_t*)&Ksh[cb * KS + ks + t2];
                uint32_t kb1 = *(uint32_t*)&Ksh[cb * KS + ks + 8 + t2];
#pragma unroll
                for (int mf = 0; mf < 2; mf++)
                    mma_f16(sAcc[mf][nf], ah[mf][0], ah[mf][1], ah[mf][2],
                            ah[mf][3], kb0, kb1);
            }
#pragma unroll
            for (int nf = 0; nf < 4; nf++) {
                int cb = wn * 32 + nf * 8 + g;
                uint32_t eb0 = *(uint32_t*)&Esh[cb * ES + ks + t2];
                uint32_t eb1 = *(uint32_t*)&Esh[cb * ES + ks + 8 + t2];
#pragma unroll
                for (int mf = 0; mf < 2; mf++)
                    mma_f16(qeAcc[mf][nf], ah[mf][0], ah[mf][1], ah[mf][2],
                            ah[mf][3], eb0, eb1);
            }
        }
#pragma unroll
        for (int mf = 0; mf < 2; mf++) {
            int R = wm * 32 + mf * 16 + g;
#pragma unroll
            for (int nf = 0; nf < 4; nf++) {
                int cc = wn * 32 + nf * 8 + t2;
                *(float2*)&QEs[R * QES + cc] =
                    make_float2(qeAcc[mf][nf][0], qeAcc[mf][nf][1]);
                *(float2*)&QEs[(R + 8) * QES + cc] =
                    make_float2(qeAcc[mf][nf][2], qeAcc[mf][nf][3]);
            }
        }
        __syncthreads();

        if (c < 7) issue_KE(c + 1);
        cp_commit();

        // ---- warp-local masked softmax ----
        uint32_t pf[2][3][4];
#pragma unroll
        for (int mf = 0; mf < 2; mf++) {
            int R = wm * 32 + mf * 16 + g;
            float mx0 = -3e38f, mx1 = -3e38f;
#pragma unroll
            for (int nf = 0; nf < 6; nf++) {
                int cc = wn * 48 + nf * 8 + t2;
#pragma unroll
                for (int e = 0; e < 4; e++) {
                    int r = R + ((e >> 1) << 3);
                    int col = cc + (e & 1);
                    int diff = col - r;
                    float z = -3e38f;
                    if ((unsigned)diff < 128u)
                        z = sAcc[mf][nf][e] + QEs[r * QES + diff];
                    sAcc[mf][nf][e] = z;
                    if (e < 2) mx0 = fmaxf(mx0, z);
                    else mx1 = fmaxf(mx1, z);
                }
            }
            mx0 = fmaxf(mx0, __shfl_xor_sync(0xffffffffu, mx0, 1));
            mx0 = fmaxf(mx0, __shfl_xor_sync(0xffffffffu, mx0, 2));
            mx1 = fmaxf(mx1, __shfl_xor_sync(0xffffffffu, mx1, 1));
            mx1 = fmaxf(mx1, __shfl_xor_sync(0xffffffffu, mx1, 2));
            float mn0 = fmaxf(mreg[mf][0], mx0 * SCl2);
            float mn1 = fmaxf(mreg[mf][1], mx1 * SCl2);
            float al0 = exp2f(mreg[mf][0] - mn0);
            float al1 = exp2f(mreg[mf][1] - mn1);
            float sum0 = 0.f, sum1 = 0.f;
#pragma unroll
            for (int nf = 0; nf < 6; nf++) {
                float p0 = exp2f(sAcc[mf][nf][0] * SCl2 - mn0);
                float p1 = exp2f(sAcc[mf][nf][1] * SCl2 - mn0);
                float p2 = exp2f(sAcc[mf][nf][2] * SCl2 - mn1);
                float p3 = exp2f(sAcc[mf][nf][3] * SCl2 - mn1);
                sum0 += p0 + p1;
                sum1 += p2 + p3;
                int k = nf >> 1, hf = (nf & 1) * 2;
                pf[mf][k][hf + 0] = pack_h2(p0, p1);
                pf[mf][k][hf + 1] = pack_h2(p2, p3);
            }
            sum0 += __shfl_xor_sync(0xffffffffu, sum0, 1);
            sum0 += __shfl_xor_sync(0xffffffffu, sum0, 2);
            sum1 += __shfl_xor_sync(0xffffffffu, sum1, 1);
            sum1 += __shfl_xor_sync(0xffffffffu, sum1, 2);
            lreg[mf][0] = lreg[mf][0] * al0 + sum0;
            lreg[mf][1] = lreg[mf][1] * al1 + sum1;
            mreg[mf][0] = mn0;
            mreg[mf][1] = mn1;
#pragma unroll
            for (int nfd = 0; nfd < 8; nfd++) {
                o[mf][nfd][0] *= al0;
                o[mf][nfd][1] *= al0;
                o[mf][nfd][2] *= al1;
                o[mf][nfd][3] *= al1;
            }
        }
        cp_wait<1>();
        __syncthreads();

        // ---- PV: 1 pass fp16 ----
#pragma unroll
        for (int k = 0; k < 3; k++) {
            int ks = wn * 48 + k * 16;
#pragma unroll
            for (int nfd = 0; nfd < 8; nfd++) {
                int cb = nfd * 8 + g;
                uint32_t vh0 = *(uint32_t*)&Vsh[cb * VS + ks + t2];
                uint32_t vh1 = *(uint32_t*)&Vsh[cb * VS + ks + 8 + t2];
#pragma unroll
                for (int mf = 0; mf < 2; mf++)
                    mma_f16(o[mf][nfd], pf[mf][k][0], pf[mf][k][1],
                            pf[mf][k][2], pf[mf][k][3], vh0, vh1);
            }
        }
        __syncthreads();

        if (c < 7) issue_V(c + 1);
        cp_commit();
    }

    // ---- epilogue: cross-warp merge + normalize + store ----
    {
        int wbase = (wm * 4 + wn) * 32;
#pragma unroll
        for (int mf = 0; mf < 2; mf++) {
            int lr0 = mf * 16 + g;
            if ((lane & 3) == 0) {
                mls[wn * 64 + wm * 32 + lr0] = mreg[mf][0];
                mls[wn * 64 + wm * 32 + lr0 + 8] = mreg[mf][1];
                lls[wn * 64 + wm * 32 + lr0] = lreg[mf][0];
                lls[wn * 64 + wm * 32 + lr0 + 8] = lreg[mf][1];
            }
#pragma unroll
            for (int nfd = 0; nfd < 8; nfd++) {
                int cc = nfd * 8 + t2;
                *(float2*)&Ored[(wbase + lr0) * OS + cc] =
                    make_float2(o[mf][nfd][0], o[mf][nfd][1]);
                *(float2*)&Ored[(wbase + lr0 + 8) * OS + cc] =
                    make_float2(o[mf][nfd][2], o[mf][nfd][3]);
            }
        }
    }
    __syncthreads();
    {
        const int b = n >> 3, kh = n & 7;
#pragma unroll
        for (int u = 0; u < 4; u++) {
            int id = tid + u * 256;
            int r = id >> 4;
            int c4 = (id & 15) * 4;
            int wmr = r >> 5, lr = r & 31;
            float mw0 = mls[r], mw1 = mls[64 + r], mw2 = mls[128 + r],
                  mw3 = mls[192 + r];
            float ms = fmaxf(fmaxf(mw0, mw1), fmaxf(mw2, mw3));
            float e0 = exp2f(mw0 - ms), e1 = exp2f(mw1 - ms),
                  e2 = exp2f(mw2 - ms), e3 = exp2f(mw3 - ms);
            float lt = lls[r] * e0 + lls[64 + r] * e1 + lls[128 + r] * e2 +
                       lls[192 + r] * e3;
            float4 s0 = *(float4*)&Ored[((wmr * 4 + 0) * 32 + lr) * OS + c4];
            float4 s1 = *(float4*)&Ored[((wmr * 4 + 1) * 32 + lr) * OS + c4];
            float4 s2 = *(float4*)&Ored[((wmr * 4 + 2) * 32 + lr) * OS + c4];
            float4 s3 = *(float4*)&Ored[((wmr * 4 + 3) * 32 + lr) * OS + c4];
            float inv = 1.0f / lt;
            float x = (s0.x * e0 + s1.x * e1 + s2.x * e2 + s3.x * e3) * inv;
            float y = (s0.y * e0 + s1.y * e1 + s2.y * e2 + s3.y * e3) * inv;
            float z = (s0.z * e0 + s1.z * e1 + s2.z * e2 + s3.z * e3) * inv;
            float w = (s0.w * e0 + s1.w * e1 + s2.w * e2 + s3.w * e3) * inv;
            __nv_bfloat16 h0, l0, h1, l1, h2, l2, h3, l3;
            split_bf(x, h0, l0);
            split_bf(y, h1, l1);
            split_bf(z, h2, l2);
            split_bf(w, h3, l3);
            size_t base = ((size_t)b * 1024 + m0 + r) * 512 + kh * 64 + c4;
            st_bf2(&Ch[base], h0, h1);
            st_bf2(&Ch[base + 2], h2, h3);
            st_bf2(&Cl[base], l0, l1);
            st_bf2(&Cl[base + 2], l2, l3);
        }
    }
}

// ---------------- launcher ----------------------------------------------------
extern "C" void kernel_launch(void* const* d_in, const int* in_sizes, int n_in,
                              void* d_out, int out_size) {
    const float* query = (const float*)d_in[0];
    const float* key = (const float*)d_in[1];
    const float* value = (const float*)d_in[2];
    const float* pos = (const float*)d_in[3];
    const float* Wq = (const float*)d_in[4];
    const float* Wk = (const float*)d_in[5];
    const float* Wv = (const float*)d_in[6];
    const float* Wo = (const float*)d_in[7];
    float* out = (float*)d_out;

    __half *qg, *kg, *vh, *vth, *et;
    __half *xq, *xk, *xv, *wqt, *wkt, *wvt;
    __nv_bfloat16 *woth, *wotl, *ch, *cl;
    cudaGetSymbolAddress((void**)&qg, g_Qh);
    cudaGetSymbolAddress((void**)&kg, g_Kh);
    cudaGetSymbolAddress((void**)&vh, g_Vh);
    cudaGetSymbolAddress((void**)&vth, g_Vth);
    cudaGetSymbolAddress((void**)&et, g_Et);
    cudaGetSymbolAddress((void**)&xq, g_Xq16);
    cudaGetSymbolAddress((void**)&xk, g_Xk16);
    cudaGetSymbolAddress((void**)&xv, g_Xv16);
    cudaGetSymbolAddress((void**)&wqt, g_WqT16);
    cudaGetSymbolAddress((void**)&wkt, g_WkT16);
    cudaGetSymbolAddress((void**)&wvt, g_WvT16);
    cudaGetSymbolAddress((void**)&woth, g_WoTh);
    cudaGetSymbolAddress((void**)&wotl, g_WoTl);
    cudaGetSymbolAddress((void**)&ch, g_Ch);
    cudaGetSymbolAddress((void**)&cl, g_Cl);

    // prep
    conv_x<<<4096, 256>>>(query, xq, 1048576);
    conv_x<<<8192, 256>>>(key, xk, 2097152);
    conv_x<<<8192, 256>>>(value, xv, 2097152);
    conv_wT_h<<<dim3(16, 16), 256>>>(Wq, wqt);
    conv_wT_h<<<dim3(16, 16), 256>>>(Wk, wkt);
    conv_wT_h<<<dim3(16, 16), 256>>>(Wv, wvt);
    split_wT<<<dim3(16, 16), 256>>>(Wo, woth, wotl);
    conv_eT<<<dim3(32, 2), 256>>>(pos, et);

    // projections (single-pass fp16)
    const int hsm = 2 * 2 * TSZ * 2;  // 40960 bytes
    cudaFuncSetAttribute(gemm_h16, cudaFuncAttributeMaxDynamicSharedMemorySize,
                         hsm);
    gemm_h16<<<dim3(64, 4), 256, hsm>>>(xq, wqt, qg, 1024);
    gemm_h16<<<dim3(128, 4), 256, hsm>>>(xk, wkt, kg, 2048);
    gemm_h16<<<dim3(128, 4), 256, hsm>>>(xv, wvt, vh, 2048);

    // V transpose to [n][d][t]
    transpose_v<<<dim3(64, 2, 64), 256>>>((const uint16_t*)vh, (uint16_t*)vth);

    // attention
    const int smem_bytes =
        (64 * 72 + 192 * 72 + 128 * 72 + 64 * 200) * 2 +
        (64 * 132 + 256 + 256) * 4;  // 115200
    cudaFuncSetAttribute(attn_tc11, cudaFuncAttributeMaxDynamicSharedMemorySize,
                         smem_bytes);
    attn_tc11<<<dim3(16, 64), 256, smem_bytes>>>(qg, kg, vth, et, ch, cl);

    // output projection (bf16x3 for accuracy)
    const int gsm = 2 * 4 * TSZ * 2;  // 81920 bytes
    cudaFuncSetAttribute(gemm_out, cudaFuncAttributeMaxDynamicSharedMemorySize,
                         gsm);
    gemm_out<<<dim3(64, 4), 256, gsm>>>(ch, cl, woth, wotl, out);
}